// round 2
// baseline (speedup 1.0000x reference)
#include <cuda_runtime.h>
#include <math.h>

// Problem constants (fixed by the dataset)
#define NN     50000
#define NEDGE  800000
#define NP     400000
#define NC     1000
#define RPL    32          // pool scatter privatization replicas

// ---------------- scratch (device globals; no runtime allocation) ----------------
__device__ float g_ea  [NEDGE * 64];     // relu(edge_attr@We+be)
__device__ float g_ht  [NN * 128];       // concat(h1,h2)
__device__ float g_h   [NN * 128];       // after embedding3
__device__ float g_h2  [NN * 128];       // after conv1
__device__ float g_h3  [NN * 128];       // after conv2
__device__ float g_mask[NEDGE * 128];    // edge mask (shared by both convs)
__device__ float g_agg [NN * 128];       // scatter-sum accumulator
__device__ float g_invdeg[NN];
__device__ int   g_deg [NN];
__device__ int   g_cnt [NC];
__device__ float g_invcnt[NC];
__device__ float g_pool[RPL * NC * 256]; // privatized pool accumulators
__device__ float g_s   [NC * 256];       // r1_1 + r1_2

// ---------------- small kernels ----------------
__global__ void k_deg(const int* __restrict__ dst, const int* __restrict__ comm) {
    int i = blockIdx.x * blockDim.x + threadIdx.x;
    if (i < NEDGE) atomicAdd(&g_deg[dst[i]], 1);
    if (i < NP)    atomicAdd(&g_cnt[comm[i]], 1);
}

__global__ void k_inv() {
    int i = blockIdx.x * blockDim.x + threadIdx.x;
    if (i < NN) g_invdeg[i] = 1.0f / (float)max(g_deg[i], 1);
    if (i < NC) g_invcnt[i] = 1.0f / (float)max(g_cnt[i], 1);
}

__global__ void k_ea(const float* __restrict__ eattr,
                     const float* __restrict__ We, const float* __restrict__ be) {
    int gid = blockIdx.x * 256 + threadIdx.x;
    int e = gid >> 6, c = gid & 63;
    if (e >= NEDGE) return;
    const float* a = eattr + e * 8;
    float s = be[c];
#pragma unroll
    for (int k = 0; k < 8; k++) s += a[k] * We[k * 64 + c];
    g_ea[e * 64 + c] = fmaxf(s, 0.0f);
}

__global__ void k_ht(const float* __restrict__ x,
                     const float* __restrict__ W1, const float* __restrict__ b1,
                     const float* __restrict__ W2, const float* __restrict__ b2) {
    int n = blockIdx.x;
    int c = threadIdx.x;            // 128 threads
    const float* xr = x + n * 20;
    float s;
    if (c < 64) {
        s = b1[c];
#pragma unroll
        for (int k = 0; k < 8; k++) s += xr[k] * W1[k * 64 + c];
    } else {
        int cc = c - 64;
        s = b2[cc];
#pragma unroll
        for (int k = 0; k < 12; k++) s += xr[8 + k] * W2[k * 64 + cc];
    }
    g_ht[n * 128 + c] = fmaxf(s, 0.0f);
}

// ---------------- fused gather-GEMM ----------------
// C = epilogue( A_gathered @ W + bias )
// BM=128, BN=128, BK=16, 256 threads, 8x8 per thread (split 4+4 pattern).
enum { M_PLAIN = 0, M_SCALED = 1, M_EL = 2, M_PAIR = 3 };
enum { E_RELU = 0, E_GATE = 1, E_POOL = 2 };

template<int MODE, int EPI, int K>
__global__ void __launch_bounds__(256)
gemm(const float* __restrict__ A, const float* __restrict__ A2,
     const float* __restrict__ W, const float* __restrict__ bias,
     float* __restrict__ Cout,
     const int* __restrict__ idx1, const int* __restrict__ idx2,
     const int* __restrict__ idx3,
     const float* __restrict__ rowscale, const float* __restrict__ hsrc,
     int rows, int ncols)
{
    __shared__ float As[16][128];
    __shared__ float Ws[16][128];

    const int tid = threadIdx.x;
    const int tx = tid & 15, ty = tid >> 4;
    const int rowbase = blockIdx.x * 128;
    const int n0 = blockIdx.y * 128;

    float acc[8][8];
#pragma unroll
    for (int i = 0; i < 8; i++)
#pragma unroll
        for (int j = 0; j < 8; j++) acc[i][j] = 0.0f;

    for (int k0 = 0; k0 < K; k0 += 16) {
        // ---- load A tile (gathered per MODE): 2 float4 per thread ----
#pragma unroll
        for (int l = 0; l < 2; l++) {
            int fid  = tid + l * 256;
            int arow = fid >> 2;
            int apos = (fid & 3) * 4;
            int grow = rowbase + arow;
            float4 v = make_float4(0.f, 0.f, 0.f, 0.f);
            if (grow < rows) {
                int gk = k0 + apos;
                const float* p;
                if (MODE == M_PLAIN || MODE == M_SCALED) {
                    p = A + grow * K + gk;
                    v = *(const float4*)p;
                    if (MODE == M_SCALED) {
                        float sc = rowscale[grow];
                        v.x *= sc; v.y *= sc; v.z *= sc; v.w *= sc;
                    }
                } else if (MODE == M_EL) {
                    if (gk < 128)      p = A  + idx1[grow] * 128 + gk;
                    else if (gk < 256) p = A  + idx2[grow] * 128 + (gk - 128);
                    else               p = A2 + grow * 64 + (gk - 256);
                    v = *(const float4*)p;
                } else { // M_PAIR
                    if (gk < 128) p = A + idx1[grow] * 128 + gk;
                    else          p = A + idx2[grow] * 128 + (gk - 128);
                    v = *(const float4*)p;
                }
            }
            As[apos + 0][arow] = v.x;
            As[apos + 1][arow] = v.y;
            As[apos + 2][arow] = v.z;
            As[apos + 3][arow] = v.w;
        }
        // ---- load W tile: Ws[k][n] ----
#pragma unroll
        for (int l = 0; l < 2; l++) {
            int fid  = tid + l * 256;
            int krow = fid >> 5;
            int c4   = (fid & 31) * 4;
            float4 v = *(const float4*)&W[(k0 + krow) * ncols + n0 + c4];
            *(float4*)&Ws[krow][c4] = v;
        }
        __syncthreads();

#pragma unroll
        for (int k = 0; k < 16; k++) {
            float ar[8], wr[8];
            *(float4*)&ar[0] = *(float4*)&As[k][ty * 4];
            *(float4*)&ar[4] = *(float4*)&As[k][64 + ty * 4];
            *(float4*)&wr[0] = *(float4*)&Ws[k][tx * 4];
            *(float4*)&wr[4] = *(float4*)&Ws[k][64 + tx * 4];
#pragma unroll
            for (int i = 0; i < 8; i++)
#pragma unroll
                for (int j = 0; j < 8; j++)
                    acc[i][j] += ar[i] * wr[j];
        }
        __syncthreads();
    }

    // ---- epilogue ----
    int cloc[8];
#pragma unroll
    for (int j = 0; j < 8; j++) cloc[j] = (j < 4) ? (tx * 4 + j) : (60 + tx * 4 + j);
    float bcol[8];
#pragma unroll
    for (int j = 0; j < 8; j++) bcol[j] = bias[n0 + cloc[j]];

    if (EPI == E_RELU) {
#pragma unroll
        for (int i = 0; i < 8; i++) {
            int r = rowbase + ((i < 4) ? (ty * 4 + i) : (60 + ty * 4 + i));
            if (r >= rows) continue;
            float4 o;
            o.x = fmaxf(acc[i][0] + bcol[0], 0.f);
            o.y = fmaxf(acc[i][1] + bcol[1], 0.f);
            o.z = fmaxf(acc[i][2] + bcol[2], 0.f);
            o.w = fmaxf(acc[i][3] + bcol[3], 0.f);
            *(float4*)&Cout[r * ncols + n0 + tx * 4] = o;
            o.x = fmaxf(acc[i][4] + bcol[4], 0.f);
            o.y = fmaxf(acc[i][5] + bcol[5], 0.f);
            o.z = fmaxf(acc[i][6] + bcol[6], 0.f);
            o.w = fmaxf(acc[i][7] + bcol[7], 0.f);
            *(float4*)&Cout[r * ncols + n0 + 64 + tx * 4] = o;
        }
    } else if (EPI == E_GATE) {
#pragma unroll
        for (int i = 0; i < 8; i++) {
            int r = rowbase + ((i < 4) ? (ty * 4 + i) : (60 + ty * 4 + i));
            if (r >= rows) continue;
            int sI = idx1[r], dI = idx2[r];
            const float* hs = hsrc + sI * 128;
            float* ag = Cout + dI * 128;
#pragma unroll
            for (int j = 0; j < 8; j++) {
                int col = cloc[j];   // n0 == 0, ncols == 128
                float z = acc[i][j] + bcol[j];
                float gate = 1.0f / (1.0f + __expf(-z));
                atomicAdd(&ag[col], gate * hs[col]);
            }
        }
    } else { // E_POOL
        int rep = (blockIdx.x % RPL) * (NC * 256);
#pragma unroll
        for (int i = 0; i < 8; i++) {
            int r = rowbase + ((i < 4) ? (ty * 4 + i) : (60 + ty * 4 + i));
            if (r >= rows) continue;
            int cm = idx3[r];
            float* pb = Cout + rep + cm * 256 + n0;
#pragma unroll
            for (int j = 0; j < 8; j++) {
                float v = fmaxf(acc[i][j] + bcol[j], 0.f);
                atomicAdd(&pb[cloc[j]], v);
            }
        }
    }
}

// ---------------- pool reduce: sum replicas, scale by 1/count ----------------
template<bool ADD>
__global__ void k_poolreduce() {
    int i = blockIdx.x * 256 + threadIdx.x;   // NC*256 elements, 1000 blocks
    int c = i >> 8;
    float s = 0.f;
#pragma unroll
    for (int r = 0; r < RPL; r++) s += g_pool[r * NC * 256 + i];
    s *= g_invcnt[c];
    if (ADD) g_s[i] += s; else g_s[i] = s;
}

// ---------------- final MLP: out = relu(s @ (Wl1_top+Wl1_bot) + bl1) @ Wl2 + bl2 ----------------
__global__ void k_final(const float* __restrict__ Wl1, const float* __restrict__ bl1,
                        const float* __restrict__ Wl2, const float* __restrict__ bl2,
                        float* __restrict__ out) {
    __shared__ float sv[256];
    __shared__ float red[256];
    int c = blockIdx.x, j = threadIdx.x;
    sv[j] = g_s[c * 256 + j];
    __syncthreads();
    float a = bl1[j];
    for (int k = 0; k < 256; k++)
        a += sv[k] * (Wl1[k * 256 + j] + Wl1[(256 + k) * 256 + j]);
    red[j] = fmaxf(a, 0.f) * Wl2[j];
    __syncthreads();
    for (int s = 128; s > 0; s >>= 1) {
        if (j < s) red[j] += red[j + s];
        __syncthreads();
    }
    if (j == 0) out[c] = red[0] + bl2[0];
}

// ---------------- host launch ----------------
extern "C" void kernel_launch(void* const* d_in, const int* in_sizes, int n_in,
                              void* d_out, int out_size) {
    (void)in_sizes; (void)n_in; (void)out_size;
    const float* x     = (const float*)d_in[0];
    const float* eattr = (const float*)d_in[1];
    const int*   ei    = (const int*)d_in[2];
    const int*   comm  = (const int*)d_in[3];
    const int*   pe    = (const int*)d_in[4];
    const float* We  = (const float*)d_in[5],  * be  = (const float*)d_in[6];
    const float* W1  = (const float*)d_in[7],  * b1  = (const float*)d_in[8];
    const float* W2  = (const float*)d_in[9],  * b2  = (const float*)d_in[10];
    const float* W3  = (const float*)d_in[11], * b3  = (const float*)d_in[12];
    const float* Wel = (const float*)d_in[13], * bel = (const float*)d_in[14];
    const float* Wm1 = (const float*)d_in[15], * bm1 = (const float*)d_in[16];
    const float* Wc1 = (const float*)d_in[17], * bc1 = (const float*)d_in[18];
    const float* Wm2 = (const float*)d_in[19], * bm2 = (const float*)d_in[20];
    const float* Wc2 = (const float*)d_in[21], * bc2 = (const float*)d_in[22];
    const float* Wam = (const float*)d_in[23], * bam = (const float*)d_in[24];
    const float* Wl1 = (const float*)d_in[25], * bl1 = (const float*)d_in[26];
    const float* Wl2 = (const float*)d_in[27], * bl2 = (const float*)d_in[28];

    const int* src = ei, * dst = ei + NEDGE;
    const int* pi  = pe, * pj  = pe + NP;

    float *ea_, *ht_, *h_, *h2_, *h3_, *mask_, *agg_, *invdeg_, *pool_;
    int *deg_, *cnt_;
    cudaGetSymbolAddress((void**)&ea_,     g_ea);
    cudaGetSymbolAddress((void**)&ht_,     g_ht);
    cudaGetSymbolAddress((void**)&h_,      g_h);
    cudaGetSymbolAddress((void**)&h2_,     g_h2);
    cudaGetSymbolAddress((void**)&h3_,     g_h3);
    cudaGetSymbolAddress((void**)&mask_,   g_mask);
    cudaGetSymbolAddress((void**)&agg_,    g_agg);
    cudaGetSymbolAddress((void**)&invdeg_, g_invdeg);
    cudaGetSymbolAddress((void**)&pool_,   g_pool);
    cudaGetSymbolAddress((void**)&deg_,    g_deg);
    cudaGetSymbolAddress((void**)&cnt_,    g_cnt);

    cudaMemsetAsync(deg_,  0, NN * sizeof(int));
    cudaMemsetAsync(cnt_,  0, NC * sizeof(int));
    cudaMemsetAsync(agg_,  0, (size_t)NN * 128 * sizeof(float));
    cudaMemsetAsync(pool_, 0, (size_t)RPL * NC * 256 * sizeof(float));

    k_deg<<<(NEDGE + 255) / 256, 256>>>(dst, comm);
    k_inv<<<(NN + 255) / 256, 256>>>();
    k_ea<<<(NEDGE * 64 + 255) / 256, 256>>>(eattr, We, be);
    k_ht<<<NN, 128>>>(x, W1, b1, W2, b2);

    dim3 blk(256);
    const int gN = (NN + 127) / 128;      // 391
    const int gE = NEDGE / 128;           // 6250
    const int gP = NP / 128;              // 3125

    // h = relu(ht @ W3 + b3)
    gemm<M_PLAIN, E_RELU, 128><<<dim3(gN, 1), blk>>>(ht_, nullptr, W3, b3, h_,
        nullptr, nullptr, nullptr, nullptr, nullptr, NN, 128);
    // mask = relu([h[src], h[dst], ea] @ Wel + bel)
    gemm<M_EL, E_RELU, 320><<<dim3(gE, 1), blk>>>(h_, ea_, Wel, bel, mask_,
        src, dst, nullptr, nullptr, nullptr, NEDGE, 128);
    // conv1: gate + gated message + scatter-sum
    gemm<M_PLAIN, E_GATE, 128><<<dim3(gE, 1), blk>>>(mask_, nullptr, Wm1, bm1, agg_,
        src, dst, nullptr, nullptr, h_, NEDGE, 128);
    // h2 = relu((agg * invdeg) @ Wc1 + bc1)
    gemm<M_SCALED, E_RELU, 128><<<dim3(gN, 1), blk>>>(agg_, nullptr, Wc1, bc1, h2_,
        nullptr, nullptr, nullptr, invdeg_, nullptr, NN, 128);
    // pool1
    gemm<M_PAIR, E_POOL, 256><<<dim3(gP, 2), blk>>>(h2_, nullptr, Wam, bam, pool_,
        pi, pj, comm, nullptr, nullptr, NP, 256);
    k_poolreduce<false><<<NC, 256>>>();

    cudaMemsetAsync(agg_,  0, (size_t)NN * 128 * sizeof(float));
    cudaMemsetAsync(pool_, 0, (size_t)RPL * NC * 256 * sizeof(float));

    // conv2
    gemm<M_PLAIN, E_GATE, 128><<<dim3(gE, 1), blk>>>(mask_, nullptr, Wm2, bm2, agg_,
        src, dst, nullptr, nullptr, h2_, NEDGE, 128);
    gemm<M_SCALED, E_RELU, 128><<<dim3(gN, 1), blk>>>(agg_, nullptr, Wc2, bc2, h3_,
        nullptr, nullptr, nullptr, invdeg_, nullptr, NN, 128);
    // pool2
    gemm<M_PAIR, E_POOL, 256><<<dim3(gP, 2), blk>>>(h3_, nullptr, Wam, bam, pool_,
        pi, pj, comm, nullptr, nullptr, NP, 256);
    k_poolreduce<true><<<NC, 256>>>();

    k_final<<<NC, 256>>>(Wl1, bl1, Wl2, bl2, (float*)d_out);
}

// round 3
// speedup vs baseline: 1.9141x; 1.9141x over previous
#include <cuda_runtime.h>
#include <math.h>
#include <stdint.h>

// Problem constants (fixed by the dataset)
#define NN     50000
#define NEDGE  800000
#define NP     400000
#define NC     1000
#define RPL    32          // pool scatter privatization replicas

// ---------------- scratch (device globals; no runtime allocation) ----------------
__device__ float g_ea  [NEDGE * 64];     // relu(edge_attr@We+be)
__device__ float g_ht  [NN * 128];       // concat(h1,h2)
__device__ float g_h   [NN * 128];       // after embedding3
__device__ float g_h2  [NN * 128];       // after conv1
__device__ float g_h3  [NN * 128];       // after conv2
__device__ float g_mask[NEDGE * 128];    // edge mask (shared by both convs)
__device__ float g_agg [NN * 128];       // scatter-sum accumulator
__device__ float g_invdeg[NN];
__device__ int   g_deg [NN];
__device__ int   g_cnt [NC];
__device__ float g_invcnt[NC];
__device__ float g_pool[RPL * NC * 256]; // privatized pool accumulators
__device__ float g_s   [NC * 256];       // r1_1 + r1_2

// ---------------- helpers ----------------
__device__ __forceinline__ float tf32r(float x) {
    uint32_t u;
    asm("cvt.rna.tf32.f32 %0, %1;" : "=r"(u) : "f"(x));
    return __uint_as_float(u);
}

__device__ __forceinline__ void mma_tf32(float* d, const uint32_t* a, const uint32_t* b) {
    asm volatile(
        "mma.sync.aligned.m16n8k8.row.col.f32.tf32.tf32.f32 "
        "{%0,%1,%2,%3}, {%4,%5,%6,%7}, {%8,%9}, {%0,%1,%2,%3};\n"
        : "+f"(d[0]), "+f"(d[1]), "+f"(d[2]), "+f"(d[3])
        : "r"(a[0]), "r"(a[1]), "r"(a[2]), "r"(a[3]), "r"(b[0]), "r"(b[1]));
}

__device__ __forceinline__ void red_v2(float* p, float v0, float v1) {
    asm volatile("red.global.add.v2.f32 [%0], {%1, %2};"
                 :: "l"(p), "f"(v0), "f"(v1) : "memory");
}

// ---------------- small kernels ----------------
__global__ void k_deg(const int* __restrict__ dst, const int* __restrict__ comm) {
    int i = blockIdx.x * blockDim.x + threadIdx.x;
    if (i < NEDGE) atomicAdd(&g_deg[dst[i]], 1);
    if (i < NP)    atomicAdd(&g_cnt[comm[i]], 1);
}

__global__ void k_inv() {
    int i = blockIdx.x * blockDim.x + threadIdx.x;
    if (i < NN) g_invdeg[i] = 1.0f / (float)max(g_deg[i], 1);
    if (i < NC) g_invcnt[i] = 1.0f / (float)max(g_cnt[i], 1);
}

__global__ void k_ea(const float* __restrict__ eattr,
                     const float* __restrict__ We, const float* __restrict__ be) {
    int gid = blockIdx.x * 256 + threadIdx.x;
    int e = gid >> 6, c = gid & 63;
    if (e >= NEDGE) return;
    const float* a = eattr + e * 8;
    float s = be[c];
#pragma unroll
    for (int k = 0; k < 8; k++) s += a[k] * We[k * 64 + c];
    g_ea[e * 64 + c] = fmaxf(s, 0.0f);
}

__global__ void k_ht(const float* __restrict__ x,
                     const float* __restrict__ W1, const float* __restrict__ b1,
                     const float* __restrict__ W2, const float* __restrict__ b2) {
    int n = blockIdx.x;
    int c = threadIdx.x;            // 128 threads
    const float* xr = x + n * 20;
    float s;
    if (c < 64) {
        s = b1[c];
#pragma unroll
        for (int k = 0; k < 8; k++) s += xr[k] * W1[k * 64 + c];
    } else {
        int cc = c - 64;
        s = b2[cc];
#pragma unroll
        for (int k = 0; k < 12; k++) s += xr[8 + k] * W2[k * 64 + cc];
    }
    g_ht[n * 128 + c] = fmaxf(s, 0.0f);
}

// ---------------- fused gather-GEMM on tensor cores (tf32 mma.sync) ----------------
// C = epilogue( A_gathered @ W + bias ),  BM=128, BN=128, BK=16, 256 threads.
// 8 warps: warp_m = wid&1 (64 rows), warp_n = wid>>1 (32 cols).
// Each warp: 4 m-tiles (16) x 4 n-tiles (8), mma.m16n8k8 tf32.
enum { M_PLAIN = 0, M_SCALED = 1, M_EL = 2, M_PAIR = 3 };
enum { E_RELU = 0, E_GATE = 1, E_POOL = 2 };

template<int MODE, int EPI, int K>
__global__ void __launch_bounds__(256)
gemm_tc(const float* __restrict__ A, const float* __restrict__ A2,
        const float* __restrict__ W, const float* __restrict__ bias,
        float* __restrict__ Cout,
        const int* __restrict__ idx1, const int* __restrict__ idx2,
        const int* __restrict__ idx3,
        const float* __restrict__ rowscale, const float* __restrict__ hsrc,
        int rows, int ncols)
{
    __shared__ float As[128][20];    // [row][k], pad 16->20 (frag loads conflict-free)
    __shared__ float Ws[16][136];    // [k][n],   pad 128->136 (frag loads conflict-free)

    const int tid  = threadIdx.x;
    const int wid  = tid >> 5, lane = tid & 31;
    const int wm   = wid & 1,  wn   = wid >> 1;     // warp tile: rows wm*64, cols wn*32
    const int g    = lane >> 2, tig = lane & 3;
    const int rowbase = blockIdx.x * 128;
    const int n0      = blockIdx.y * 128;

    float acc[4][4][4];              // [mt][nt][reg]
#pragma unroll
    for (int a = 0; a < 4; a++)
#pragma unroll
        for (int b = 0; b < 4; b++)
#pragma unroll
            for (int c = 0; c < 4; c++) acc[a][b][c] = 0.0f;

    for (int k0 = 0; k0 < K; k0 += 16) {
        // ---- A tile (gathered per MODE): 2 float4 per thread -> As[row][k] ----
#pragma unroll
        for (int l = 0; l < 2; l++) {
            int fid  = tid + l * 256;
            int arow = fid >> 2;
            int apos = (fid & 3) * 4;
            int grow = rowbase + arow;
            float4 v = make_float4(0.f, 0.f, 0.f, 0.f);
            if (grow < rows) {
                int gk = k0 + apos;
                const float* p;
                if (MODE == M_PLAIN || MODE == M_SCALED) {
                    p = A + (size_t)grow * K + gk;
                    v = *(const float4*)p;
                    if (MODE == M_SCALED) {
                        float sc = rowscale[grow];
                        v.x *= sc; v.y *= sc; v.z *= sc; v.w *= sc;
                    }
                } else if (MODE == M_EL) {
                    if (gk < 128)      p = A  + (size_t)idx1[grow] * 128 + gk;
                    else if (gk < 256) p = A  + (size_t)idx2[grow] * 128 + (gk - 128);
                    else               p = A2 + (size_t)grow * 64 + (gk - 256);
                    v = *(const float4*)p;
                } else { // M_PAIR
                    if (gk < 128) p = A + (size_t)idx1[grow] * 128 + gk;
                    else          p = A + (size_t)idx2[grow] * 128 + (gk - 128);
                    v = *(const float4*)p;
                }
            }
            As[arow][apos + 0] = tf32r(v.x);
            As[arow][apos + 1] = tf32r(v.y);
            As[arow][apos + 2] = tf32r(v.z);
            As[arow][apos + 3] = tf32r(v.w);
        }
        // ---- W tile: Ws[k][n] ----
#pragma unroll
        for (int l = 0; l < 2; l++) {
            int fid  = tid + l * 256;
            int krow = fid >> 5;
            int c4   = (fid & 31) * 4;
            float4 v = *(const float4*)&W[(size_t)(k0 + krow) * ncols + n0 + c4];
            Ws[krow][c4 + 0] = tf32r(v.x);
            Ws[krow][c4 + 1] = tf32r(v.y);
            Ws[krow][c4 + 2] = tf32r(v.z);
            Ws[krow][c4 + 3] = tf32r(v.w);
        }
        __syncthreads();

#pragma unroll
        for (int ks = 0; ks < 2; ks++) {
            const int kb = ks * 8;
            uint32_t af[4][4];
#pragma unroll
            for (int mt = 0; mt < 4; mt++) {
                int r0 = wm * 64 + mt * 16 + g;
                af[mt][0] = __float_as_uint(As[r0    ][kb + tig]);
                af[mt][1] = __float_as_uint(As[r0 + 8][kb + tig]);
                af[mt][2] = __float_as_uint(As[r0    ][kb + tig + 4]);
                af[mt][3] = __float_as_uint(As[r0 + 8][kb + tig + 4]);
            }
            uint32_t bf[4][2];
#pragma unroll
            for (int nt = 0; nt < 4; nt++) {
                int c = wn * 32 + nt * 8 + g;
                bf[nt][0] = __float_as_uint(Ws[kb + tig    ][c]);
                bf[nt][1] = __float_as_uint(Ws[kb + tig + 4][c]);
            }
#pragma unroll
            for (int mt = 0; mt < 4; mt++)
#pragma unroll
                for (int nt = 0; nt < 4; nt++)
                    mma_tf32(acc[mt][nt], af[mt], bf[nt]);
        }
        __syncthreads();
    }

    // ---- epilogue ----
    // D fragment: reg0,1 -> row g,   cols tig*2, tig*2+1
    //             reg2,3 -> row g+8, cols tig*2, tig*2+1
    float bc0[4], bc1[4];
#pragma unroll
    for (int nt = 0; nt < 4; nt++) {
        int c = wn * 32 + nt * 8 + tig * 2;
        bc0[nt] = bias[n0 + c];
        bc1[nt] = bias[n0 + c + 1];
    }

#pragma unroll
    for (int mt = 0; mt < 4; mt++) {
#pragma unroll
        for (int half = 0; half < 2; half++) {
            int rl = wm * 64 + mt * 16 + g + half * 8;
            int r  = rowbase + rl;
            if (r >= rows) continue;

            if (EPI == E_RELU) {
                float* op = Cout + (size_t)r * ncols + n0;
#pragma unroll
                for (int nt = 0; nt < 4; nt++) {
                    int c = wn * 32 + nt * 8 + tig * 2;
                    float2 o;
                    o.x = fmaxf(acc[mt][nt][half * 2    ] + bc0[nt], 0.f);
                    o.y = fmaxf(acc[mt][nt][half * 2 + 1] + bc1[nt], 0.f);
                    *(float2*)&op[c] = o;
                }
            } else if (EPI == E_GATE) {       // n0 == 0, ncols == 128
                int sI = idx1[r], dI = idx2[r];
                const float* hs = hsrc + (size_t)sI * 128;
                float*       ag = Cout + (size_t)dI * 128;
#pragma unroll
                for (int nt = 0; nt < 4; nt++) {
                    int c = wn * 32 + nt * 8 + tig * 2;
                    float z0 = acc[mt][nt][half * 2    ] + bc0[nt];
                    float z1 = acc[mt][nt][half * 2 + 1] + bc1[nt];
                    float g0 = 1.0f / (1.0f + __expf(-z0));
                    float g1 = 1.0f / (1.0f + __expf(-z1));
                    float2 hv = *(const float2*)&hs[c];
                    red_v2(&ag[c], g0 * hv.x, g1 * hv.y);
                }
            } else {                           // E_POOL
                int rep = (blockIdx.x & (RPL - 1)) * (NC * 256);
                int cm  = idx3[r];
                float* pb = Cout + rep + cm * 256 + n0;
#pragma unroll
                for (int nt = 0; nt < 4; nt++) {
                    int c = wn * 32 + nt * 8 + tig * 2;
                    float v0 = fmaxf(acc[mt][nt][half * 2    ] + bc0[nt], 0.f);
                    float v1 = fmaxf(acc[mt][nt][half * 2 + 1] + bc1[nt], 0.f);
                    red_v2(&pb[c], v0, v1);
                }
            }
        }
    }
}

// ---------------- pool reduce: sum replicas, scale by 1/count ----------------
template<bool ADD>
__global__ void k_poolreduce() {
    int i = blockIdx.x * 256 + threadIdx.x;   // NC*256 elements, 1000 blocks
    int c = i >> 8;
    float s = 0.f;
#pragma unroll
    for (int r = 0; r < RPL; r++) s += g_pool[r * NC * 256 + i];
    s *= g_invcnt[c];
    if (ADD) g_s[i] += s; else g_s[i] = s;
}

// ---------------- final MLP ----------------
__global__ void k_final(const float* __restrict__ Wl1, const float* __restrict__ bl1,
                        const float* __restrict__ Wl2, const float* __restrict__ bl2,
                        float* __restrict__ out) {
    __shared__ float sv[256];
    __shared__ float red[256];
    int c = blockIdx.x, j = threadIdx.x;
    sv[j] = g_s[c * 256 + j];
    __syncthreads();
    float a = bl1[j];
    for (int k = 0; k < 256; k++)
        a += sv[k] * (Wl1[k * 256 + j] + Wl1[(256 + k) * 256 + j]);
    red[j] = fmaxf(a, 0.f) * Wl2[j];
    __syncthreads();
    for (int s = 128; s > 0; s >>= 1) {
        if (j < s) red[j] += red[j + s];
        __syncthreads();
    }
    if (j == 0) out[c] = red[0] + bl2[0];
}

// ---------------- host launch ----------------
extern "C" void kernel_launch(void* const* d_in, const int* in_sizes, int n_in,
                              void* d_out, int out_size) {
    (void)in_sizes; (void)n_in; (void)out_size;
    const float* x     = (const float*)d_in[0];
    const float* eattr = (const float*)d_in[1];
    const int*   ei    = (const int*)d_in[2];
    const int*   comm  = (const int*)d_in[3];
    const int*   pe    = (const int*)d_in[4];
    const float* We  = (const float*)d_in[5],  * be  = (const float*)d_in[6];
    const float* W1  = (const float*)d_in[7],  * b1  = (const float*)d_in[8];
    const float* W2  = (const float*)d_in[9],  * b2  = (const float*)d_in[10];
    const float* W3  = (const float*)d_in[11], * b3  = (const float*)d_in[12];
    const float* Wel = (const float*)d_in[13], * bel = (const float*)d_in[14];
    const float* Wm1 = (const float*)d_in[15], * bm1 = (const float*)d_in[16];
    const float* Wc1 = (const float*)d_in[17], * bc1 = (const float*)d_in[18];
    const float* Wm2 = (const float*)d_in[19], * bm2 = (const float*)d_in[20];
    const float* Wc2 = (const float*)d_in[21], * bc2 = (const float*)d_in[22];
    const float* Wam = (const float*)d_in[23], * bam = (const float*)d_in[24];
    const float* Wl1 = (const float*)d_in[25], * bl1 = (const float*)d_in[26];
    const float* Wl2 = (const float*)d_in[27], * bl2 = (const float*)d_in[28];

    const int* src = ei, * dst = ei + NEDGE;
    const int* pi  = pe, * pj  = pe + NP;

    float *ea_, *ht_, *h_, *h2_, *h3_, *mask_, *agg_, *invdeg_, *pool_;
    int *deg_, *cnt_;
    cudaGetSymbolAddress((void**)&ea_,     g_ea);
    cudaGetSymbolAddress((void**)&ht_,     g_ht);
    cudaGetSymbolAddress((void**)&h_,      g_h);
    cudaGetSymbolAddress((void**)&h2_,     g_h2);
    cudaGetSymbolAddress((void**)&h3_,     g_h3);
    cudaGetSymbolAddress((void**)&mask_,   g_mask);
    cudaGetSymbolAddress((void**)&agg_,    g_agg);
    cudaGetSymbolAddress((void**)&invdeg_, g_invdeg);
    cudaGetSymbolAddress((void**)&pool_,   g_pool);
    cudaGetSymbolAddress((void**)&deg_,    g_deg);
    cudaGetSymbolAddress((void**)&cnt_,    g_cnt);

    cudaMemsetAsync(deg_,  0, NN * sizeof(int));
    cudaMemsetAsync(cnt_,  0, NC * sizeof(int));
    cudaMemsetAsync(agg_,  0, (size_t)NN * 128 * sizeof(float));
    cudaMemsetAsync(pool_, 0, (size_t)RPL * NC * 256 * sizeof(float));

    k_deg<<<(NEDGE + 255) / 256, 256>>>(dst, comm);
    k_inv<<<(NN + 255) / 256, 256>>>();
    k_ea<<<(NEDGE * 64 + 255) / 256, 256>>>(eattr, We, be);
    k_ht<<<NN, 128>>>(x, W1, b1, W2, b2);

    dim3 blk(256);
    const int gN = (NN + 127) / 128;      // 391
    const int gE = NEDGE / 128;           // 6250
    const int gP = NP / 128;              // 3125

    // h = relu(ht @ W3 + b3)
    gemm_tc<M_PLAIN, E_RELU, 128><<<dim3(gN, 1), blk>>>(ht_, nullptr, W3, b3, h_,
        nullptr, nullptr, nullptr, nullptr, nullptr, NN, 128);
    // mask = relu([h[src], h[dst], ea] @ Wel + bel)
    gemm_tc<M_EL, E_RELU, 320><<<dim3(gE, 1), blk>>>(h_, ea_, Wel, bel, mask_,
        src, dst, nullptr, nullptr, nullptr, NEDGE, 128);
    // conv1: gate + gated message + scatter-sum
    gemm_tc<M_PLAIN, E_GATE, 128><<<dim3(gE, 1), blk>>>(mask_, nullptr, Wm1, bm1, agg_,
        src, dst, nullptr, nullptr, h_, NEDGE, 128);
    // h2 = relu((agg * invdeg) @ Wc1 + bc1)
    gemm_tc<M_SCALED, E_RELU, 128><<<dim3(gN, 1), blk>>>(agg_, nullptr, Wc1, bc1, h2_,
        nullptr, nullptr, nullptr, invdeg_, nullptr, NN, 128);
    // pool1
    gemm_tc<M_PAIR, E_POOL, 256><<<dim3(gP, 2), blk>>>(h2_, nullptr, Wam, bam, pool_,
        pi, pj, comm, nullptr, nullptr, NP, 256);
    k_poolreduce<false><<<NC, 256>>>();

    cudaMemsetAsync(agg_,  0, (size_t)NN * 128 * sizeof(float));
    cudaMemsetAsync(pool_, 0, (size_t)RPL * NC * 256 * sizeof(float));

    // conv2
    gemm_tc<M_PLAIN, E_GATE, 128><<<dim3(gE, 1), blk>>>(mask_, nullptr, Wm2, bm2, agg_,
        src, dst, nullptr, nullptr, h2_, NEDGE, 128);
    gemm_tc<M_SCALED, E_RELU, 128><<<dim3(gN, 1), blk>>>(agg_, nullptr, Wc2, bc2, h3_,
        nullptr, nullptr, nullptr, invdeg_, nullptr, NN, 128);
    // pool2
    gemm_tc<M_PAIR, E_POOL, 256><<<dim3(gP, 2), blk>>>(h3_, nullptr, Wam, bam, pool_,
        pi, pj, comm, nullptr, nullptr, NP, 256);
    k_poolreduce<true><<<NC, 256>>>();

    k_final<<<NC, 256>>>(Wl1, bl1, Wl2, bl2, (float*)d_out);
}

// round 6
// speedup vs baseline: 2.2772x; 1.1897x over previous
#include <cuda_runtime.h>
#include <math.h>
#include <stdint.h>

// Problem constants (fixed by the dataset)
#define NN     50000
#define NEDGE  800000
#define NP     400000
#define NC     1000
#define RPL    32          // pool scatter privatization replicas

// ---------------- scratch (device globals; no runtime allocation) ----------------
__device__ float g_ea  [NEDGE * 64];     // relu(edge_attr@We+be), tf32-rounded
__device__ float g_ht  [NN * 128];       // concat(h1,h2), tf32-rounded
__device__ float g_h   [NN * 128];       // after embedding3, tf32-rounded
__device__ float g_h2  [NN * 128];       // after conv1, tf32-rounded
__device__ float g_h3  [NN * 128];       // after conv2, tf32-rounded
__device__ float g_mask[NEDGE * 128];    // edge mask, tf32-rounded
__device__ float g_agg [NN * 128];       // scatter-sum accumulator (scaled+rounded in place)
__device__ float g_invdeg[NN];
__device__ int   g_deg [NN];
__device__ int   g_cnt [NC];
__device__ float g_invcnt[NC];
__device__ float g_pool[RPL * NC * 256]; // privatized pool accumulators
__device__ float g_s   [NC * 256];       // r1_1 + r1_2
__device__ float g_wr  [188416];         // tf32-rounded weights, packed

// packed weight offsets (floats)
#define OW3   0
#define OWEL  16384
#define OWM1  57344
#define OWC1  73728
#define OWM2  90112
#define OWC2  106496
#define OWAM  122880

// ---------------- helpers ----------------
__device__ __forceinline__ float tf32r(float x) {
    uint32_t u;
    asm("cvt.rna.tf32.f32 %0, %1;" : "=r"(u) : "f"(x));
    return __uint_as_float(u);
}

__device__ __forceinline__ void mma_tf32(float* d, const uint32_t* a, const uint32_t* b) {
    asm volatile(
        "mma.sync.aligned.m16n8k8.row.col.f32.tf32.tf32.f32 "
        "{%0,%1,%2,%3}, {%4,%5,%6,%7}, {%8,%9}, {%0,%1,%2,%3};\n"
        : "+f"(d[0]), "+f"(d[1]), "+f"(d[2]), "+f"(d[3])
        : "r"(a[0]), "r"(a[1]), "r"(a[2]), "r"(a[3]), "r"(b[0]), "r"(b[1]));
}

__device__ __forceinline__ void red_v2(float* p, float v0, float v1) {
    asm volatile("red.global.add.v2.f32 [%0], {%1, %2};"
                 :: "l"(p), "f"(v0), "f"(v1) : "memory");
}

__device__ __forceinline__ uint32_t s2u(const void* p) {
    return (uint32_t)__cvta_generic_to_shared(p);
}
__device__ __forceinline__ void cp16ca(uint32_t dst, const void* src) {
    asm volatile("cp.async.ca.shared.global [%0], [%1], 16;" :: "r"(dst), "l"(src));
}
__device__ __forceinline__ void cp16cg(uint32_t dst, const void* src) {
    asm volatile("cp.async.cg.shared.global [%0], [%1], 16;" :: "r"(dst), "l"(src));
}
__device__ __forceinline__ void cp_commit() {
    asm volatile("cp.async.commit_group;");
}
template<int N> __device__ __forceinline__ void cp_wait() {
    asm volatile("cp.async.wait_group %0;" :: "n"(N));
}

// ---------------- small kernels ----------------
__global__ void k_deg(const int* __restrict__ dst, const int* __restrict__ comm) {
    int i = blockIdx.x * blockDim.x + threadIdx.x;
    if (i < NEDGE) atomicAdd(&g_deg[dst[i]], 1);
    if (i < NP)    atomicAdd(&g_cnt[comm[i]], 1);
}

__global__ void k_inv() {
    int i = blockIdx.x * blockDim.x + threadIdx.x;
    if (i < NN) g_invdeg[i] = 1.0f / (float)max(g_deg[i], 1);
    if (i < NC) g_invcnt[i] = 1.0f / (float)max(g_cnt[i], 1);
}

__global__ void k_round(float* __restrict__ dstb, const float* __restrict__ src, int n) {
    int i = blockIdx.x * 256 + threadIdx.x;
    if (i < n) dstb[i] = tf32r(src[i]);
}

__global__ void k_scale() {   // agg = tf32r(agg * invdeg[row]) in place
    int i = blockIdx.x * 256 + threadIdx.x;   // NN*128
    if (i < NN * 128) g_agg[i] = tf32r(g_agg[i] * g_invdeg[i >> 7]);
}

__global__ void k_ea(const float* __restrict__ eattr,
                     const float* __restrict__ We, const float* __restrict__ be) {
    int gid = blockIdx.x * 256 + threadIdx.x;
    int e = gid >> 6, c = gid & 63;
    if (e >= NEDGE) return;
    const float* a = eattr + e * 8;
    float s = be[c];
#pragma unroll
    for (int k = 0; k < 8; k++) s += a[k] * We[k * 64 + c];
    g_ea[e * 64 + c] = tf32r(fmaxf(s, 0.0f));
}

__global__ void k_ht(const float* __restrict__ x,
                     const float* __restrict__ W1, const float* __restrict__ b1,
                     const float* __restrict__ W2, const float* __restrict__ b2) {
    int n = blockIdx.x;
    int c = threadIdx.x;            // 128 threads
    const float* xr = x + n * 20;
    float s;
    if (c < 64) {
        s = b1[c];
#pragma unroll
        for (int k = 0; k < 8; k++) s += xr[k] * W1[k * 64 + c];
    } else {
        int cc = c - 64;
        s = b2[cc];
#pragma unroll
        for (int k = 0; k < 12; k++) s += xr[8 + k] * W2[k * 64 + cc];
    }
    g_ht[n * 128 + c] = tf32r(fmaxf(s, 0.0f));
}

// ---------------- fused gather-GEMM, tf32 mma.sync + cp.async pipeline ----------------
// C = epilogue( A_gathered @ W + bias ),  BM=128, BN=128, BK=16, 256 threads, 2-stage.
enum { M_PLAIN = 0, M_EL = 2, M_PAIR = 3 };
enum { E_RELU = 0, E_GATE = 1, E_POOL = 2 };

// stage loader as a plain function (no device lambda)
template<int MODE, int K>
__device__ __forceinline__ void load_stage(
    float (*As)[128][20], float (*Ws)[16][136], int t, int s,
    const float* __restrict__ A, const float* __restrict__ A2,
    const float* __restrict__ W,
    const size_t* offA, const size_t* offB, const size_t* offE,
    int arow, int apos, int tid, int n0, int ncols)
{
    const int k0 = t * 16;
#pragma unroll
    for (int l = 0; l < 2; l++) {
        uint32_t dst = s2u(&As[s][arow + l * 64][apos]);
        int gk = k0 + apos;
        const float* src;
        if (MODE == M_PLAIN) {
            src = A + offA[l] + gk;
            cp16cg(dst, src);
        } else if (MODE == M_EL) {
            if (gk < 128)      src = A  + offA[l] + gk;
            else if (gk < 256) src = A  + offB[l] + (gk - 128);
            else               src = A2 + offE[l] + (gk - 256);
            cp16ca(dst, src);
        } else { // M_PAIR
            if (gk < 128) src = A + offA[l] + gk;
            else          src = A + offB[l] + (gk - 128);
            cp16ca(dst, src);
        }
    }
#pragma unroll
    for (int l = 0; l < 2; l++) {
        int fid  = tid + l * 256;
        int krow = fid >> 5;
        int c4   = (fid & 31) * 4;
        cp16ca(s2u(&Ws[s][krow][c4]),
               W + (size_t)(k0 + krow) * ncols + n0 + c4);
    }
}

template<int MODE, int EPI, int K>
__global__ void __launch_bounds__(256)
gemm_tc(const float* __restrict__ A, const float* __restrict__ A2,
        const float* __restrict__ W, const float* __restrict__ bias,
        float* __restrict__ Cout,
        const int* __restrict__ idx1, const int* __restrict__ idx2,
        const int* __restrict__ idx3,
        const float* __restrict__ hsrc,
        int rows, int ncols)
{
    __shared__ float As[2][128][20];    // [stage][row][k], pad 16->20
    __shared__ float Ws[2][16][136];    // [stage][k][n],   pad 128->136

    const int tid  = threadIdx.x;
    const int wid  = tid >> 5, lane = tid & 31;
    const int wm   = wid & 1,  wn   = wid >> 1;     // warp tile: rows wm*64, cols wn*32
    const int g    = lane >> 2, tig = lane & 3;
    const int rowbase = blockIdx.x * 128;
    const int n0      = blockIdx.y * 128;

    const int arow = tid >> 2;          // l=0 -> arow, l=1 -> arow+64
    const int apos = (tid & 3) * 4;

    size_t offA[2], offB[2], offE[2];
#pragma unroll
    for (int l = 0; l < 2; l++) {
        int grow = rowbase + arow + l * 64;
        int gc = (grow < rows) ? grow : (rows - 1);
        if (MODE == M_PLAIN) {
            offA[l] = (size_t)gc * K;
            offB[l] = 0; offE[l] = 0;
        } else {
            offA[l] = (size_t)idx1[gc] * 128;
            offB[l] = (size_t)idx2[gc] * 128;
            offE[l] = (MODE == M_EL) ? (size_t)gc * 64 : 0;
        }
    }

    float acc[4][4][4];
#pragma unroll
    for (int a = 0; a < 4; a++)
#pragma unroll
        for (int b = 0; b < 4; b++)
#pragma unroll
            for (int c = 0; c < 4; c++) acc[a][b][c] = 0.0f;

    const int NT = K / 16;

    load_stage<MODE, K>(As, Ws, 0, 0, A, A2, W, offA, offB, offE, arow, apos, tid, n0, ncols);
    cp_commit();

    for (int t = 0; t < NT; t++) {
        const int s = t & 1;
        if (t + 1 < NT) {
            load_stage<MODE, K>(As, Ws, t + 1, (t + 1) & 1, A, A2, W,
                                offA, offB, offE, arow, apos, tid, n0, ncols);
            cp_commit();
            cp_wait<1>();
        } else {
            cp_wait<0>();
        }
        __syncthreads();

#pragma unroll
        for (int ks = 0; ks < 2; ks++) {
            const int kb = ks * 8;
            uint32_t af[4][4];
#pragma unroll
            for (int mt = 0; mt < 4; mt++) {
                int r0 = wm * 64 + mt * 16 + g;
                af[mt][0] = __float_as_uint(As[s][r0    ][kb + tig]);
                af[mt][1] = __float_as_uint(As[s][r0 + 8][kb + tig]);
                af[mt][2] = __float_as_uint(As[s][r0    ][kb + tig + 4]);
                af[mt][3] = __float_as_uint(As[s][r0 + 8][kb + tig + 4]);
            }
            uint32_t bf[4][2];
#pragma unroll
            for (int nt = 0; nt < 4; nt++) {
                int c = wn * 32 + nt * 8 + g;
                bf[nt][0] = __float_as_uint(Ws[s][kb + tig    ][c]);
                bf[nt][1] = __float_as_uint(Ws[s][kb + tig + 4][c]);
            }
#pragma unroll
            for (int mt = 0; mt < 4; mt++)
#pragma unroll
                for (int nt = 0; nt < 4; nt++)
                    mma_tf32(acc[mt][nt], af[mt], bf[nt]);
        }
        __syncthreads();
    }

    // ---- epilogue ----
    float bc0[4], bc1[4];
#pragma unroll
    for (int nt = 0; nt < 4; nt++) {
        int c = wn * 32 + nt * 8 + tig * 2;
        bc0[nt] = bias[n0 + c];
        bc1[nt] = bias[n0 + c + 1];
    }

#pragma unroll
    for (int mt = 0; mt < 4; mt++) {
#pragma unroll
        for (int half = 0; half < 2; half++) {
            int rl = wm * 64 + mt * 16 + g + half * 8;
            int r  = rowbase + rl;
            if (r >= rows) continue;

            if (EPI == E_RELU) {
                float* op = Cout + (size_t)r * ncols + n0;
#pragma unroll
                for (int nt = 0; nt < 4; nt++) {
                    int c = wn * 32 + nt * 8 + tig * 2;
                    float2 o;
                    o.x = tf32r(fmaxf(acc[mt][nt][half * 2    ] + bc0[nt], 0.f));
                    o.y = tf32r(fmaxf(acc[mt][nt][half * 2 + 1] + bc1[nt], 0.f));
                    *(float2*)&op[c] = o;
                }
            } else if (EPI == E_GATE) {       // n0 == 0, ncols == 128
                int sI = idx1[r], dI = idx2[r];
                const float* hs = hsrc + (size_t)sI * 128;
                float*       ag = Cout + (size_t)dI * 128;
#pragma unroll
                for (int nt = 0; nt < 4; nt++) {
                    int c = wn * 32 + nt * 8 + tig * 2;
                    float z0 = acc[mt][nt][half * 2    ] + bc0[nt];
                    float z1 = acc[mt][nt][half * 2 + 1] + bc1[nt];
                    float g0 = 1.0f / (1.0f + __expf(-z0));
                    float g1 = 1.0f / (1.0f + __expf(-z1));
                    float2 hv = *(const float2*)&hs[c];
                    red_v2(&ag[c], g0 * hv.x, g1 * hv.y);
                }
            } else {                           // E_POOL
                int rep = (blockIdx.x & (RPL - 1)) * (NC * 256);
                int cm  = idx3[r];
                float* pb = Cout + rep + cm * 256 + n0;
#pragma unroll
                for (int nt = 0; nt < 4; nt++) {
                    int c = wn * 32 + nt * 8 + tig * 2;
                    float v0 = fmaxf(acc[mt][nt][half * 2    ] + bc0[nt], 0.f);
                    float v1 = fmaxf(acc[mt][nt][half * 2 + 1] + bc1[nt], 0.f);
                    red_v2(&pb[c], v0, v1);
                }
            }
        }
    }
}

// ---------------- pool reduce: sum replicas, scale by 1/count ----------------
template<bool ADD>
__global__ void k_poolreduce() {
    int i = blockIdx.x * 256 + threadIdx.x;   // NC*256 elements, 1000 blocks
    int c = i >> 8;
    float s = 0.f;
#pragma unroll
    for (int r = 0; r < RPL; r++) s += g_pool[r * NC * 256 + i];
    s *= g_invcnt[c];
    if (ADD) g_s[i] += s; else g_s[i] = s;
}

// ---------------- final MLP ----------------
__global__ void k_final(const float* __restrict__ Wl1, const float* __restrict__ bl1,
                        const float* __restrict__ Wl2, const float* __restrict__ bl2,
                        float* __restrict__ out) {
    __shared__ float sv[256];
    __shared__ float red[256];
    int c = blockIdx.x, j = threadIdx.x;
    sv[j] = g_s[c * 256 + j];
    __syncthreads();
    float a = bl1[j];
    for (int k = 0; k < 256; k++)
        a += sv[k] * (Wl1[k * 256 + j] + Wl1[(256 + k) * 256 + j]);
    red[j] = fmaxf(a, 0.f) * Wl2[j];
    __syncthreads();
    for (int s = 128; s > 0; s >>= 1) {
        if (j < s) red[j] += red[j + s];
        __syncthreads();
    }
    if (j == 0) out[c] = red[0] + bl2[0];
}

// ---------------- host launch ----------------
extern "C" void kernel_launch(void* const* d_in, const int* in_sizes, int n_in,
                              void* d_out, int out_size) {
    (void)in_sizes; (void)n_in; (void)out_size;
    const float* x     = (const float*)d_in[0];
    const float* eattr = (const float*)d_in[1];
    const int*   ei    = (const int*)d_in[2];
    const int*   comm  = (const int*)d_in[3];
    const int*   pe    = (const int*)d_in[4];
    const float* We  = (const float*)d_in[5],  * be  = (const float*)d_in[6];
    const float* W1  = (const float*)d_in[7],  * b1  = (const float*)d_in[8];
    const float* W2  = (const float*)d_in[9],  * b2  = (const float*)d_in[10];
    const float* W3  = (const float*)d_in[11], * b3  = (const float*)d_in[12];
    const float* Wel = (const float*)d_in[13], * bel = (const float*)d_in[14];
    const float* Wm1 = (const float*)d_in[15], * bm1 = (const float*)d_in[16];
    const float* Wc1 = (const float*)d_in[17], * bc1 = (const float*)d_in[18];
    const float* Wm2 = (const float*)d_in[19], * bm2 = (const float*)d_in[20];
    const float* Wc2 = (const float*)d_in[21], * bc2 = (const float*)d_in[22];
    const float* Wam = (const float*)d_in[23], * bam = (const float*)d_in[24];
    const float* Wl1 = (const float*)d_in[25], * bl1 = (const float*)d_in[26];
    const float* Wl2 = (const float*)d_in[27], * bl2 = (const float*)d_in[28];

    const int* src = ei, * dst = ei + NEDGE;
    const int* pi  = pe, * pj  = pe + NP;

    float *ea_, *ht_, *h_, *h2_, *h3_, *mask_, *agg_, *pool_, *wr_;
    int *deg_, *cnt_;
    cudaGetSymbolAddress((void**)&ea_,   g_ea);
    cudaGetSymbolAddress((void**)&ht_,   g_ht);
    cudaGetSymbolAddress((void**)&h_,    g_h);
    cudaGetSymbolAddress((void**)&h2_,   g_h2);
    cudaGetSymbolAddress((void**)&h3_,   g_h3);
    cudaGetSymbolAddress((void**)&mask_, g_mask);
    cudaGetSymbolAddress((void**)&agg_,  g_agg);
    cudaGetSymbolAddress((void**)&pool_, g_pool);
    cudaGetSymbolAddress((void**)&wr_,   g_wr);
    cudaGetSymbolAddress((void**)&deg_,  g_deg);
    cudaGetSymbolAddress((void**)&cnt_,  g_cnt);

    cudaMemsetAsync(deg_,  0, NN * sizeof(int));
    cudaMemsetAsync(cnt_,  0, NC * sizeof(int));
    cudaMemsetAsync(agg_,  0, (size_t)NN * 128 * sizeof(float));
    cudaMemsetAsync(pool_, 0, (size_t)RPL * NC * 256 * sizeof(float));

    k_deg<<<(NEDGE + 255) / 256, 256>>>(dst, comm);
    k_inv<<<(NN + 255) / 256, 256>>>();

    // pre-round all GEMM weights to the tf32 grid
    k_round<<<(16384 + 255) / 256, 256>>>(wr_ + OW3,  W3,  16384);
    k_round<<<(40960 + 255) / 256, 256>>>(wr_ + OWEL, Wel, 40960);
    k_round<<<(16384 + 255) / 256, 256>>>(wr_ + OWM1, Wm1, 16384);
    k_round<<<(16384 + 255) / 256, 256>>>(wr_ + OWC1, Wc1, 16384);
    k_round<<<(16384 + 255) / 256, 256>>>(wr_ + OWM2, Wm2, 16384);
    k_round<<<(16384 + 255) / 256, 256>>>(wr_ + OWC2, Wc2, 16384);
    k_round<<<(65536 + 255) / 256, 256>>>(wr_ + OWAM, Wam, 65536);

    k_ea<<<(NEDGE * 64 + 255) / 256, 256>>>(eattr, We, be);
    k_ht<<<NN, 128>>>(x, W1, b1, W2, b2);

    dim3 blk(256);
    const int gN = (NN + 127) / 128;      // 391
    const int gE = NEDGE / 128;           // 6250
    const int gP = NP / 128;              // 3125

    // h = relu(ht @ W3 + b3)
    gemm_tc<M_PLAIN, E_RELU, 128><<<dim3(gN, 1), blk>>>(ht_, nullptr, wr_ + OW3, b3, h_,
        nullptr, nullptr, nullptr, nullptr, NN, 128);
    // mask = relu([h[src], h[dst], ea] @ Wel + bel)
    gemm_tc<M_EL, E_RELU, 320><<<dim3(gE, 1), blk>>>(h_, ea_, wr_ + OWEL, bel, mask_,
        src, dst, nullptr, nullptr, NEDGE, 128);
    // conv1: gate + gated message + scatter-sum
    gemm_tc<M_PLAIN, E_GATE, 128><<<dim3(gE, 1), blk>>>(mask_, nullptr, wr_ + OWM1, bm1, agg_,
        src, dst, nullptr, h_, NEDGE, 128);
    k_scale<<<(NN * 128 + 255) / 256, 256>>>();
    // h2 = relu(aggscaled @ Wc1 + bc1)
    gemm_tc<M_PLAIN, E_RELU, 128><<<dim3(gN, 1), blk>>>(agg_, nullptr, wr_ + OWC1, bc1, h2_,
        nullptr, nullptr, nullptr, nullptr, NN, 128);
    // pool1
    gemm_tc<M_PAIR, E_POOL, 256><<<dim3(gP, 2), blk>>>(h2_, nullptr, wr_ + OWAM, bam, pool_,
        pi, pj, comm, nullptr, NP, 256);
    k_poolreduce<false><<<NC, 256>>>();

    cudaMemsetAsync(agg_,  0, (size_t)NN * 128 * sizeof(float));
    cudaMemsetAsync(pool_, 0, (size_t)RPL * NC * 256 * sizeof(float));

    // conv2
    gemm_tc<M_PLAIN, E_GATE, 128><<<dim3(gE, 1), blk>>>(mask_, nullptr, wr_ + OWM2, bm2, agg_,
        src, dst, nullptr, h2_, NEDGE, 128);
    k_scale<<<(NN * 128 + 255) / 256, 256>>>();
    gemm_tc<M_PLAIN, E_RELU, 128><<<dim3(gN, 1), blk>>>(agg_, nullptr, wr_ + OWC2, bc2, h3_,
        nullptr, nullptr, nullptr, nullptr, NN, 128);
    // pool2
    gemm_tc<M_PAIR, E_POOL, 256><<<dim3(gP, 2), blk>>>(h3_, nullptr, wr_ + OWAM, bam, pool_,
        pi, pj, comm, nullptr, NP, 256);
    k_poolreduce<true><<<NC, 256>>>();

    k_final<<<NC, 256>>>(Wl1, bl1, Wl2, bl2, (float*)d_out);
}

// round 8
// speedup vs baseline: 2.4033x; 1.0554x over previous
#include <cuda_runtime.h>
#include <cuda_fp16.h>
#include <math.h>
#include <stdint.h>

// Problem constants (fixed by the dataset)
#define NN     50000
#define NEDGE  800000
#define NP     400000
#define NC     1000
#define RPL    32          // pool scatter privatization replicas

// ---------------- scratch (device globals; no runtime allocation) ----------------
__device__ float   g_ea  [NEDGE * 64];     // relu(edge_attr@We+be), tf32-rounded
__device__ float   g_ht  [NN * 128];       // concat(h1,h2), tf32-rounded
__device__ float   g_h   [NN * 128];       // after embedding3, tf32-rounded
__device__ float   g_h2  [NN * 128];       // after conv1, tf32-rounded
__device__ float   g_h3  [NN * 128];       // after conv2, tf32-rounded
__device__ float   g_agg [NN * 128];       // scatter-sum accumulator
__device__ __half2 g_g2  [NEDGE * 64];     // conv2 gates, fp16 pairs
__device__ float   g_invdeg[NN];
__device__ int     g_deg [NN];
__device__ int     g_cnt [NC];
__device__ float   g_invcnt[NC];
__device__ float   g_pool[RPL * NC * 256]; // privatized pool accumulators
__device__ float   g_s   [NC * 256];       // r1_1 + r1_2
__device__ float   g_wr  [188416];         // tf32-rounded weights, packed

// packed weight offsets (floats)
#define OW3   0
#define OWEL  16384
#define OWM1  57344
#define OWC1  73728
#define OWM2  90112
#define OWC2  106496
#define OWAM  122880

// ---------------- helpers ----------------
__device__ __forceinline__ float tf32r(float x) {
    uint32_t u;
    asm("cvt.rna.tf32.f32 %0, %1;" : "=r"(u) : "f"(x));
    return __uint_as_float(u);
}
__device__ __forceinline__ void mma_tf32(float* d, const uint32_t* a, const uint32_t* b) {
    asm volatile(
        "mma.sync.aligned.m16n8k8.row.col.f32.tf32.tf32.f32 "
        "{%0,%1,%2,%3}, {%4,%5,%6,%7}, {%8,%9}, {%0,%1,%2,%3};\n"
        : "+f"(d[0]), "+f"(d[1]), "+f"(d[2]), "+f"(d[3])
        : "r"(a[0]), "r"(a[1]), "r"(a[2]), "r"(a[3]), "r"(b[0]), "r"(b[1]));
}
__device__ __forceinline__ void red_v2(float* p, float v0, float v1) {
    asm volatile("red.global.add.v2.f32 [%0], {%1, %2};"
                 :: "l"(p), "f"(v0), "f"(v1) : "memory");
}
__device__ __forceinline__ uint32_t s2u(const void* p) {
    return (uint32_t)__cvta_generic_to_shared(p);
}
__device__ __forceinline__ void cp16ca(uint32_t dst, const void* src) {
    asm volatile("cp.async.ca.shared.global [%0], [%1], 16;" :: "r"(dst), "l"(src));
}
__device__ __forceinline__ void cp16cg(uint32_t dst, const void* src) {
    asm volatile("cp.async.cg.shared.global [%0], [%1], 16;" :: "r"(dst), "l"(src));
}
__device__ __forceinline__ void cp_commit() {
    asm volatile("cp.async.commit_group;");
}
template<int N> __device__ __forceinline__ void cp_wait() {
    asm volatile("cp.async.wait_group %0;" :: "n"(N));
}

// ---------------- small kernels ----------------
__global__ void k_deg(const int* __restrict__ dst, const int* __restrict__ comm) {
    int i = blockIdx.x * blockDim.x + threadIdx.x;
    if (i < NEDGE) atomicAdd(&g_deg[dst[i]], 1);
    if (i < NP)    atomicAdd(&g_cnt[comm[i]], 1);
}
__global__ void k_inv() {
    int i = blockIdx.x * blockDim.x + threadIdx.x;
    if (i < NN) g_invdeg[i] = 1.0f / (float)max(g_deg[i], 1);
    if (i < NC) g_invcnt[i] = 1.0f / (float)max(g_cnt[i], 1);
}
__global__ void k_round(float* __restrict__ dstb, const float* __restrict__ src, int n) {
    int i = blockIdx.x * 256 + threadIdx.x;
    if (i < n) dstb[i] = tf32r(src[i]);
}
__global__ void k_scale() {   // agg = tf32r(agg * invdeg[row]) in place
    int i = blockIdx.x * 256 + threadIdx.x;
    if (i < NN * 128) g_agg[i] = tf32r(g_agg[i] * g_invdeg[i >> 7]);
}
__global__ void k_ea(const float* __restrict__ eattr,
                     const float* __restrict__ We, const float* __restrict__ be) {
    int gid = blockIdx.x * 256 + threadIdx.x;
    int e = gid >> 6, c = gid & 63;
    if (e >= NEDGE) return;
    const float* a = eattr + e * 8;
    float s = be[c];
#pragma unroll
    for (int k = 0; k < 8; k++) s += a[k] * We[k * 64 + c];
    g_ea[e * 64 + c] = tf32r(fmaxf(s, 0.0f));
}
__global__ void k_ht(const float* __restrict__ x,
                     const float* __restrict__ W1, const float* __restrict__ b1,
                     const float* __restrict__ W2, const float* __restrict__ b2) {
    int n = blockIdx.x;
    int c = threadIdx.x;
    const float* xr = x + n * 20;
    float s;
    if (c < 64) {
        s = b1[c];
#pragma unroll
        for (int k = 0; k < 8; k++) s += xr[k] * W1[k * 64 + c];
    } else {
        int cc = c - 64;
        s = b2[cc];
#pragma unroll
        for (int k = 0; k < 12; k++) s += xr[8 + k] * W2[k * 64 + cc];
    }
    g_ht[n * 128 + c] = tf32r(fmaxf(s, 0.0f));
}

// ================= generic gather-GEMM (nodes + pool) =================
enum { M_PLAIN = 0, M_PAIR = 3 };
enum { E_RELU = 0, E_POOL = 2 };

template<int MODE, int K>
__device__ __forceinline__ void load_stage(
    float (*As)[128][20], float (*Ws)[16][136], int t, int s,
    const float* __restrict__ A, const float* __restrict__ W,
    const size_t* offA, const size_t* offB,
    int arow, int apos, int tid, int n0, int ncols)
{
    const int k0 = t * 16;
#pragma unroll
    for (int l = 0; l < 2; l++) {
        uint32_t dst = s2u(&As[s][arow + l * 64][apos]);
        int gk = k0 + apos;
        if (MODE == M_PLAIN) {
            cp16cg(dst, A + offA[l] + gk);
        } else { // M_PAIR
            const float* src = (gk < 128) ? (A + offA[l] + gk) : (A + offB[l] + (gk - 128));
            cp16ca(dst, src);
        }
    }
#pragma unroll
    for (int l = 0; l < 2; l++) {
        int fid  = tid + l * 256;
        int krow = fid >> 5;
        int c4   = (fid & 31) * 4;
        cp16ca(s2u(&Ws[s][krow][c4]), W + (size_t)(k0 + krow) * ncols + n0 + c4);
    }
}

template<int MODE, int EPI, int K>
__global__ void __launch_bounds__(256)
gemm_tc(const float* __restrict__ A, const float* __restrict__ W,
        const float* __restrict__ bias, float* __restrict__ Cout,
        const int* __restrict__ idx1, const int* __restrict__ idx2,
        const int* __restrict__ idx3, int rows, int ncols)
{
    __shared__ float As[2][128][20];
    __shared__ float Ws[2][16][136];

    const int tid  = threadIdx.x;
    const int wid  = tid >> 5, lane = tid & 31;
    const int wm   = wid & 1,  wn   = wid >> 1;
    const int g    = lane >> 2, tig = lane & 3;
    const int rowbase = blockIdx.x * 128;
    const int n0      = blockIdx.y * 128;

    const int arow = tid >> 2;
    const int apos = (tid & 3) * 4;

    size_t offA[2], offB[2];
#pragma unroll
    for (int l = 0; l < 2; l++) {
        int grow = rowbase + arow + l * 64;
        int gc = (grow < rows) ? grow : (rows - 1);
        if (MODE == M_PLAIN) { offA[l] = (size_t)gc * K; offB[l] = 0; }
        else { offA[l] = (size_t)idx1[gc] * 128; offB[l] = (size_t)idx2[gc] * 128; }
    }

    float acc[4][4][4];
#pragma unroll
    for (int a = 0; a < 4; a++)
#pragma unroll
        for (int b = 0; b < 4; b++)
#pragma unroll
            for (int c = 0; c < 4; c++) acc[a][b][c] = 0.0f;

    const int NT = K / 16;
    load_stage<MODE, K>(As, Ws, 0, 0, A, W, offA, offB, arow, apos, tid, n0, ncols);
    cp_commit();

    for (int t = 0; t < NT; t++) {
        const int s = t & 1;
        if (t + 1 < NT) {
            load_stage<MODE, K>(As, Ws, t + 1, (t + 1) & 1, A, W, offA, offB, arow, apos, tid, n0, ncols);
            cp_commit();
            cp_wait<1>();
        } else cp_wait<0>();
        __syncthreads();

#pragma unroll
        for (int ks = 0; ks < 2; ks++) {
            const int kb = ks * 8;
            uint32_t af[4][4];
#pragma unroll
            for (int mt = 0; mt < 4; mt++) {
                int r0 = wm * 64 + mt * 16 + g;
                af[mt][0] = __float_as_uint(As[s][r0    ][kb + tig]);
                af[mt][1] = __float_as_uint(As[s][r0 + 8][kb + tig]);
                af[mt][2] = __float_as_uint(As[s][r0    ][kb + tig + 4]);
                af[mt][3] = __float_as_uint(As[s][r0 + 8][kb + tig + 4]);
            }
            uint32_t bf[4][2];
#pragma unroll
            for (int nt = 0; nt < 4; nt++) {
                int c = wn * 32 + nt * 8 + g;
                bf[nt][0] = __float_as_uint(Ws[s][kb + tig    ][c]);
                bf[nt][1] = __float_as_uint(Ws[s][kb + tig + 4][c]);
            }
#pragma unroll
            for (int mt = 0; mt < 4; mt++)
#pragma unroll
                for (int nt = 0; nt < 4; nt++)
                    mma_tf32(acc[mt][nt], af[mt], bf[nt]);
        }
        __syncthreads();
    }

    float bc0[4], bc1[4];
#pragma unroll
    for (int nt = 0; nt < 4; nt++) {
        int c = wn * 32 + nt * 8 + tig * 2;
        bc0[nt] = bias[n0 + c];
        bc1[nt] = bias[n0 + c + 1];
    }

#pragma unroll
    for (int mt = 0; mt < 4; mt++) {
#pragma unroll
        for (int half = 0; half < 2; half++) {
            int rl = wm * 64 + mt * 16 + g + half * 8;
            int r  = rowbase + rl;
            if (r >= rows) continue;
            if (EPI == E_RELU) {
                float* op = Cout + (size_t)r * ncols + n0;
#pragma unroll
                for (int nt = 0; nt < 4; nt++) {
                    int c = wn * 32 + nt * 8 + tig * 2;
                    float2 o;
                    o.x = tf32r(fmaxf(acc[mt][nt][half * 2    ] + bc0[nt], 0.f));
                    o.y = tf32r(fmaxf(acc[mt][nt][half * 2 + 1] + bc1[nt], 0.f));
                    *(float2*)&op[c] = o;
                }
            } else { // E_POOL
                int rep = (blockIdx.x & (RPL - 1)) * (NC * 256);
                int cm  = idx3[r];
                float* pb = Cout + rep + cm * 256 + n0;
#pragma unroll
                for (int nt = 0; nt < 4; nt++) {
                    int c = wn * 32 + nt * 8 + tig * 2;
                    float v0 = fmaxf(acc[mt][nt][half * 2    ] + bc0[nt], 0.f);
                    float v1 = fmaxf(acc[mt][nt][half * 2 + 1] + bc1[nt], 0.f);
                    red_v2(&pb[c], v0, v1);
                }
            }
        }
    }
}

// ================= fused EL + gate1 + gate2 kernel =================
// phase 1: Ms = relu([h[src],h[dst],ea] @ Wel + bel)   (smem-resident, tf32-rounded)
// phase 2: z1 = Ms @ Wm1 + bm1 -> sigmoid -> msg = gate*h[src] -> RED to agg
// phase 3: z2 = Ms @ Wm2 + bm2 -> sigmoid -> fp16 -> g_g2 (smem-staged coalesced store)
#define SM_AS 0
#define SM_WS 20480
#define SM_MS 37888
#define SMEM_EL (SM_MS + 128 * 136 * 4)   // 107,520 bytes
#define GST 68   // gate staging row stride in half2 (272B, 16B-aligned)

__device__ __forceinline__ void el_loadW(float (*Ws)[16][136], int t, int s,
                                         const float* __restrict__ W, int tid) {
    const int k0 = t * 16;
#pragma unroll
    for (int l = 0; l < 2; l++) {
        int fid  = tid + l * 256;
        int krow = fid >> 5;
        int c4   = (fid & 31) * 4;
        cp16ca(s2u(&Ws[s][krow][c4]), W + (size_t)(k0 + krow) * 128 + c4);
    }
}

__global__ void __launch_bounds__(256)
k_elconv(const float* __restrict__ h, const float* __restrict__ ea,
         const float* __restrict__ Wel, const float* __restrict__ bel,
         const float* __restrict__ Wm1, const float* __restrict__ bm1,
         const float* __restrict__ Wm2, const float* __restrict__ bm2,
         const int* __restrict__ src, const int* __restrict__ dst,
         float* __restrict__ agg, __half2* __restrict__ gate2)
{
    extern __shared__ char smem[];
    float (*As)[128][20] = (float (*)[128][20])(smem + SM_AS);
    float (*Ws)[16][136] = (float (*)[16][136])(smem + SM_WS);
    float (*Ms)[136]     = (float (*)[136])(smem + SM_MS);

    const int tid  = threadIdx.x;
    const int wid  = tid >> 5, lane = tid & 31;
    const int wm   = wid & 1,  wn   = wid >> 1;
    const int g    = lane >> 2, tig = lane & 3;
    const int rowbase = blockIdx.x * 128;     // NEDGE % 128 == 0, no tail

    const int arow = tid >> 2;
    const int apos = (tid & 3) * 4;

    size_t offA[2], offB[2], offE[2];
#pragma unroll
    for (int l = 0; l < 2; l++) {
        int grow = rowbase + arow + l * 64;
        offA[l] = (size_t)src[grow] * 128;
        offB[l] = (size_t)dst[grow] * 128;
        offE[l] = (size_t)grow * 64;
    }

    float acc[4][4][4];
#pragma unroll
    for (int a = 0; a < 4; a++)
#pragma unroll
        for (int b = 0; b < 4; b++)
#pragma unroll
            for (int c = 0; c < 4; c++) acc[a][b][c] = 0.0f;

    // ---- phase 1: K=320 pipelined ----
    {
        {
#pragma unroll
            for (int l = 0; l < 2; l++) {
                int gk = apos;   // < 128
                cp16ca(s2u(&As[0][arow + l * 64][apos]), h + offA[l] + gk);
            }
            el_loadW(Ws, 0, 0, Wel, tid);
            cp_commit();
        }
        const int NT = 20;
        for (int t = 0; t < NT; t++) {
            const int s = t & 1;
            if (t + 1 < NT) {
                const int k0 = (t + 1) * 16, sn = (t + 1) & 1;
#pragma unroll
                for (int l = 0; l < 2; l++) {
                    int gk = k0 + apos;
                    const float* srcp;
                    if (gk < 128)      srcp = h  + offA[l] + gk;
                    else if (gk < 256) srcp = h  + offB[l] + (gk - 128);
                    else               srcp = ea + offE[l] + (gk - 256);
                    cp16ca(s2u(&As[sn][arow + l * 64][apos]), srcp);
                }
                el_loadW(Ws, t + 1, sn, Wel, tid);
                cp_commit();
                cp_wait<1>();
            } else cp_wait<0>();
            __syncthreads();

#pragma unroll
            for (int ks = 0; ks < 2; ks++) {
                const int kb = ks * 8;
                uint32_t af[4][4];
#pragma unroll
                for (int mt = 0; mt < 4; mt++) {
                    int r0 = wm * 64 + mt * 16 + g;
                    af[mt][0] = __float_as_uint(As[s][r0    ][kb + tig]);
                    af[mt][1] = __float_as_uint(As[s][r0 + 8][kb + tig]);
                    af[mt][2] = __float_as_uint(As[s][r0    ][kb + tig + 4]);
                    af[mt][3] = __float_as_uint(As[s][r0 + 8][kb + tig + 4]);
                }
                uint32_t bf[4][2];
#pragma unroll
                for (int nt = 0; nt < 4; nt++) {
                    int c = wn * 32 + nt * 8 + g;
                    bf[nt][0] = __float_as_uint(Ws[s][kb + tig    ][c]);
                    bf[nt][1] = __float_as_uint(Ws[s][kb + tig + 4][c]);
                }
#pragma unroll
                for (int mt = 0; mt < 4; mt++)
#pragma unroll
                    for (int nt = 0; nt < 4; nt++)
                        mma_tf32(acc[mt][nt], af[mt], bf[nt]);
            }
            __syncthreads();
        }
        // epilogue -> Ms
#pragma unroll
        for (int mt = 0; mt < 4; mt++)
#pragma unroll
            for (int half = 0; half < 2; half++) {
                int rl = wm * 64 + mt * 16 + g + half * 8;
#pragma unroll
                for (int nt = 0; nt < 4; nt++) {
                    int c = wn * 32 + nt * 8 + tig * 2;
                    Ms[rl][c    ] = tf32r(fmaxf(acc[mt][nt][half * 2    ] + bel[c    ], 0.f));
                    Ms[rl][c + 1] = tf32r(fmaxf(acc[mt][nt][half * 2 + 1] + bel[c + 1], 0.f));
                }
            }
        __syncthreads();
    }

    // ---- phases 2 & 3: Ms @ Wm{1,2}, K=128 ----
#pragma unroll 1
    for (int ph = 0; ph < 2; ph++) {
        const float* Wm = (ph == 0) ? Wm1 : Wm2;
        const float* bm = (ph == 0) ? bm1 : bm2;

#pragma unroll
        for (int a = 0; a < 4; a++)
#pragma unroll
            for (int b = 0; b < 4; b++)
#pragma unroll
                for (int c = 0; c < 4; c++) acc[a][b][c] = 0.0f;

        el_loadW(Ws, 0, 0, Wm, tid);
        cp_commit();
        for (int t = 0; t < 8; t++) {
            const int s = t & 1;
            if (t + 1 < 8) {
                el_loadW(Ws, t + 1, (t + 1) & 1, Wm, tid);
                cp_commit();
                cp_wait<1>();
            } else cp_wait<0>();
            __syncthreads();

#pragma unroll
            for (int ks = 0; ks < 2; ks++) {
                const int kb = t * 16 + ks * 8;
                uint32_t af[4][4];
#pragma unroll
                for (int mt = 0; mt < 4; mt++) {
                    int r0 = wm * 64 + mt * 16 + g;
                    af[mt][0] = __float_as_uint(Ms[r0    ][kb + tig]);
                    af[mt][1] = __float_as_uint(Ms[r0 + 8][kb + tig]);
                    af[mt][2] = __float_as_uint(Ms[r0    ][kb + tig + 4]);
                    af[mt][3] = __float_as_uint(Ms[r0 + 8][kb + tig + 4]);
                }
                uint32_t bf[4][2];
#pragma unroll
                for (int nt = 0; nt < 4; nt++) {
                    int c = wn * 32 + nt * 8 + g;
                    bf[nt][0] = __float_as_uint(Ws[s][(ks * 8) + tig    ][c]);
                    bf[nt][1] = __float_as_uint(Ws[s][(ks * 8) + tig + 4][c]);
                }
#pragma unroll
                for (int mt = 0; mt < 4; mt++)
#pragma unroll
                    for (int nt = 0; nt < 4; nt++)
                        mma_tf32(acc[mt][nt], af[mt], bf[nt]);
            }
            __syncthreads();
        }

        if (ph == 0) {
            // conv1: gate, message from h[src], RED into agg
#pragma unroll
            for (int mt = 0; mt < 4; mt++)
#pragma unroll
                for (int half = 0; half < 2; half++) {
                    int rl = wm * 64 + mt * 16 + g + half * 8;
                    int r  = rowbase + rl;
                    int sI = src[r], dI = dst[r];
                    const float* hs = h + (size_t)sI * 128;
                    float*       ag = agg + (size_t)dI * 128;
#pragma unroll
                    for (int nt = 0; nt < 4; nt++) {
                        int c = wn * 32 + nt * 8 + tig * 2;
                        float z0 = acc[mt][nt][half * 2    ] + bm[c];
                        float z1 = acc[mt][nt][half * 2 + 1] + bm[c + 1];
                        float g0 = 1.0f / (1.0f + __expf(-z0));
                        float g1 = 1.0f / (1.0f + __expf(-z1));
                        float2 hv = *(const float2*)&hs[c];
                        red_v2(&ag[c], g0 * hv.x, g1 * hv.y);
                    }
                }
        } else {
            // conv2 gates -> stage in smem (reuse Ms area) -> coalesced fp16 store
            __half2* stage = (__half2*)Ms;            // [row][GST] half2, 16B-aligned rows
#pragma unroll
            for (int mt = 0; mt < 4; mt++)
#pragma unroll
                for (int half = 0; half < 2; half++) {
                    int rl = wm * 64 + mt * 16 + g + half * 8;
#pragma unroll
                    for (int nt = 0; nt < 4; nt++) {
                        int c = wn * 32 + nt * 8 + tig * 2;
                        float z0 = acc[mt][nt][half * 2    ] + bm[c];
                        float z1 = acc[mt][nt][half * 2 + 1] + bm[c + 1];
                        float g0 = 1.0f / (1.0f + __expf(-z0));
                        float g1 = 1.0f / (1.0f + __expf(-z1));
                        stage[rl * GST + (c >> 1)] = __floats2half2_rn(g0, g1);
                    }
                }
            __syncthreads();
            // copy 128 rows x 64 half2 (256B) to gmem, fully coalesced
            __half2* gout = gate2 + (size_t)rowbase * 64;
            for (int i = tid; i < 2048; i += 256) {        // 2048 float4 = 32KB
                int row = i >> 4, part = i & 15;           // 16 float4 per row
                float4 v = *(float4*)&stage[row * GST + part * 4];
                *(float4*)&gout[row * 64 + part * 4] = v;
            }
        }
    }
}

// ---------------- conv2 scatter: msg = gate2 * h2[src], RED to agg ----------------
__global__ void __launch_bounds__(256) k_conv2(const int* __restrict__ src,
                                               const int* __restrict__ dst) {
    int wid = threadIdx.x >> 5, lane = threadIdx.x & 31;
    int e = blockIdx.x * 8 + wid;          // NEDGE/8 blocks
    int sI = src[e], dI = dst[e];
    const __half2* gp = g_g2 + (size_t)e * 64 + lane * 2;
    float4 hv = *(const float4*)(g_h2 + (size_t)sI * 128 + lane * 4);
    float2 fa = __half22float2(gp[0]);
    float2 fb = __half22float2(gp[1]);
    float* ag = g_agg + (size_t)dI * 128 + lane * 4;
    red_v2(ag,     fa.x * hv.x, fa.y * hv.y);
    red_v2(ag + 2, fb.x * hv.z, fb.y * hv.w);
}

// ---------------- pool reduce ----------------
template<bool ADD>
__global__ void k_poolreduce() {
    int i = blockIdx.x * 256 + threadIdx.x;
    int c = i >> 8;
    float s = 0.f;
#pragma unroll
    for (int r = 0; r < RPL; r++) s += g_pool[r * NC * 256 + i];
    s *= g_invcnt[c];
    if (ADD) g_s[i] += s; else g_s[i] = s;
}

// ---------------- final MLP ----------------
__global__ void k_final(const float* __restrict__ Wl1, const float* __restrict__ bl1,
                        const float* __restrict__ Wl2, const float* __restrict__ bl2,
                        float* __restrict__ out) {
    __shared__ float sv[256];
    __shared__ float red[256];
    int c = blockIdx.x, j = threadIdx.x;
    sv[j] = g_s[c * 256 + j];
    __syncthreads();
    float a = bl1[j];
    for (int k = 0; k < 256; k++)
        a += sv[k] * (Wl1[k * 256 + j] + Wl1[(256 + k) * 256 + j]);
    red[j] = fmaxf(a, 0.f) * Wl2[j];
    __syncthreads();
    for (int s = 128; s > 0; s >>= 1) {
        if (j < s) red[j] += red[j + s];
        __syncthreads();
    }
    if (j == 0) out[c] = red[0] + bl2[0];
}

// ---------------- host launch ----------------
extern "C" void kernel_launch(void* const* d_in, const int* in_sizes, int n_in,
                              void* d_out, int out_size) {
    (void)in_sizes; (void)n_in; (void)out_size;
    const float* x     = (const float*)d_in[0];
    const float* eattr = (const float*)d_in[1];
    const int*   ei    = (const int*)d_in[2];
    const int*   comm  = (const int*)d_in[3];
    const int*   pe    = (const int*)d_in[4];
    const float* We  = (const float*)d_in[5],  * be  = (const float*)d_in[6];
    const float* W1  = (const float*)d_in[7],  * b1  = (const float*)d_in[8];
    const float* W2  = (const float*)d_in[9],  * b2  = (const float*)d_in[10];
    const float* W3  = (const float*)d_in[11], * b3  = (const float*)d_in[12];
    const float* Wel = (const float*)d_in[13], * bel = (const float*)d_in[14];
    const float* Wm1 = (const float*)d_in[15], * bm1 = (const float*)d_in[16];
    const float* Wc1 = (const float*)d_in[17], * bc1 = (const float*)d_in[18];
    const float* Wm2 = (const float*)d_in[19], * bm2 = (const float*)d_in[20];
    const float* Wc2 = (const float*)d_in[21], * bc2 = (const float*)d_in[22];
    const float* Wam = (const float*)d_in[23], * bam = (const float*)d_in[24];
    const float* Wl1 = (const float*)d_in[25], * bl1 = (const float*)d_in[26];
    const float* Wl2 = (const float*)d_in[27], * bl2 = (const float*)d_in[28];

    const int* src = ei, * dst = ei + NEDGE;
    const int* pi  = pe, * pj  = pe + NP;

    float *ea_, *ht_, *h_, *h2_, *h3_, *agg_, *pool_, *wr_;
    __half2* g2_;
    int *deg_, *cnt_;
    cudaGetSymbolAddress((void**)&ea_,   g_ea);
    cudaGetSymbolAddress((void**)&ht_,   g_ht);
    cudaGetSymbolAddress((void**)&h_,    g_h);
    cudaGetSymbolAddress((void**)&h2_,   g_h2);
    cudaGetSymbolAddress((void**)&h3_,   g_h3);
    cudaGetSymbolAddress((void**)&agg_,  g_agg);
    cudaGetSymbolAddress((void**)&pool_, g_pool);
    cudaGetSymbolAddress((void**)&wr_,   g_wr);
    cudaGetSymbolAddress((void**)&g2_,   g_g2);
    cudaGetSymbolAddress((void**)&deg_,  g_deg);
    cudaGetSymbolAddress((void**)&cnt_,  g_cnt);

    static int smem_set = 0;
    if (!smem_set) {
        cudaFuncSetAttribute(k_elconv, cudaFuncAttributeMaxDynamicSharedMemorySize, SMEM_EL);
        smem_set = 1;
    }

    cudaMemsetAsync(deg_,  0, NN * sizeof(int));
    cudaMemsetAsync(cnt_,  0, NC * sizeof(int));
    cudaMemsetAsync(agg_,  0, (size_t)NN * 128 * sizeof(float));
    cudaMemsetAsync(pool_, 0, (size_t)RPL * NC * 256 * sizeof(float));

    k_deg<<<(NEDGE + 255) / 256, 256>>>(dst, comm);
    k_inv<<<(NN + 255) / 256, 256>>>();

    k_round<<<(16384 + 255) / 256, 256>>>(wr_ + OW3,  W3,  16384);
    k_round<<<(40960 + 255) / 256, 256>>>(wr_ + OWEL, Wel, 40960);
    k_round<<<(16384 + 255) / 256, 256>>>(wr_ + OWM1, Wm1, 16384);
    k_round<<<(16384 + 255) / 256, 256>>>(wr_ + OWC1, Wc1, 16384);
    k_round<<<(16384 + 255) / 256, 256>>>(wr_ + OWM2, Wm2, 16384);
    k_round<<<(16384 + 255) / 256, 256>>>(wr_ + OWC2, Wc2, 16384);
    k_round<<<(65536 + 255) / 256, 256>>>(wr_ + OWAM, Wam, 65536);

    k_ea<<<(NEDGE * 64 + 255) / 256, 256>>>(eattr, We, be);
    k_ht<<<NN, 128>>>(x, W1, b1, W2, b2);

    dim3 blk(256);
    const int gN = (NN + 127) / 128;      // 391
    const int gE = NEDGE / 128;           // 6250
    const int gP = NP / 128;              // 3125

    // h = relu(ht @ W3 + b3)
    gemm_tc<M_PLAIN, E_RELU, 128><<<dim3(gN, 1), blk>>>(ht_, wr_ + OW3, b3, h_,
        nullptr, nullptr, nullptr, NN, 128);

    // fused: mask (smem) -> conv1 scatter + conv2 gates
    k_elconv<<<gE, blk, SMEM_EL>>>(h_, ea_, wr_ + OWEL, bel,
                                   wr_ + OWM1, bm1, wr_ + OWM2, bm2,
                                   src, dst, agg_, g2_);
    k_scale<<<(NN * 128 + 255) / 256, 256>>>();
    gemm_tc<M_PLAIN, E_RELU, 128><<<dim3(gN, 1), blk>>>(agg_, wr_ + OWC1, bc1, h2_,
        nullptr, nullptr, nullptr, NN, 128);
    // pool1
    gemm_tc<M_PAIR, E_POOL, 256><<<dim3(gP, 2), blk>>>(h2_, wr_ + OWAM, bam, pool_,
        pi, pj, comm, NP, 256);
    k_poolreduce<false><<<NC, 256>>>();

    cudaMemsetAsync(agg_,  0, (size_t)NN * 128 * sizeof(float));
    cudaMemsetAsync(pool_, 0, (size_t)RPL * NC * 256 * sizeof(float));

    // conv2: pure scatter with precomputed fp16 gates
    k_conv2<<<NEDGE / 8, 256>>>(src, dst);
    k_scale<<<(NN * 128 + 255) / 256, 256>>>();
    gemm_tc<M_PLAIN, E_RELU, 128><<<dim3(gN, 1), blk>>>(agg_, wr_ + OWC2, bc2, h3_,
        nullptr, nullptr, nullptr, NN, 128);
    // pool2
    gemm_tc<M_PAIR, E_POOL, 256><<<dim3(gP, 2), blk>>>(h3_, wr_ + OWAM, bam, pool_,
        pi, pj, comm, NP, 256);
    k_poolreduce<true><<<NC, 256>>>();

    k_final<<<NC, 256>>>(Wl1, bl1, Wl2, bl2, (float*)d_out);
}

// round 9
// speedup vs baseline: 2.8660x; 1.1925x over previous
#include <cuda_runtime.h>
#include <cuda_fp16.h>
#include <math.h>
#include <stdint.h>

// Problem constants (fixed by the dataset)
#define NN     50000
#define NEDGE  800000
#define NP     400000
#define NC     1000
#define RPL    32          // pool scatter privatization replicas

// ---------------- scratch (device globals; no runtime allocation) ----------------
__device__ __half  g_ea  [NEDGE * 64];     // relu(edge_attr@We+be), fp16
__device__ __half  g_ht  [NN * 128];       // concat(h1,h2), fp16
__device__ __half  g_h   [NN * 128];       // after embedding3, fp16
__device__ __half  g_h2  [NN * 128];       // after conv1, fp16
__device__ __half  g_h3  [NN * 128];       // after conv2, fp16
__device__ float   g_agg [NN * 128];       // scatter-sum accumulator (fp32 atomics)
__device__ __half  g_aggh[NN * 128];       // scaled agg, fp16 (GEMM input)
__device__ __half  g_g2  [NEDGE * 128];    // conv2 gates, fp16
__device__ float   g_invdeg[NN];
__device__ int     g_deg [NN];
__device__ int     g_cnt [NC];
__device__ float   g_invcnt[NC];
__device__ float   g_pool[RPL * NC * 256]; // privatized pool accumulators
__device__ float   g_s   [NC * 256];       // r1_1 + r1_2
__device__ __half  g_wh  [188416];         // fp16 weights, TRANSPOSED to [N][K], packed

// packed weight offsets (halves), each W stored as Wt[n*K + k]
#define OW3   0        // 128x128
#define OWEL  16384    // N=128, K=320
#define OWM1  57344
#define OWC1  73728
#define OWM2  90112
#define OWC2  106496
#define OWAM  122880   // N=256, K=256

// tile strides (halves)
#define TS  40    // As/Ws row stride: 80B (16B-mult), 20 words -> conflict-free frags
#define MST 136   // Ms row stride: 272B (16B-mult), 68 words -> conflict-free frags

// ---------------- helpers ----------------
__device__ __forceinline__ void mma_f16(float* d, const uint32_t* a, const uint32_t* b) {
    asm volatile(
        "mma.sync.aligned.m16n8k16.row.col.f32.f16.f16.f32 "
        "{%0,%1,%2,%3}, {%4,%5,%6,%7}, {%8,%9}, {%0,%1,%2,%3};\n"
        : "+f"(d[0]), "+f"(d[1]), "+f"(d[2]), "+f"(d[3])
        : "r"(a[0]), "r"(a[1]), "r"(a[2]), "r"(a[3]), "r"(b[0]), "r"(b[1]));
}
__device__ __forceinline__ uint32_t h2u(const __half* p) {   // load half2 as u32
    return *(const uint32_t*)p;
}
__device__ __forceinline__ void red_v2(float* p, float v0, float v1) {
    asm volatile("red.global.add.v2.f32 [%0], {%1, %2};"
                 :: "l"(p), "f"(v0), "f"(v1) : "memory");
}
__device__ __forceinline__ uint32_t s2u(const void* p) {
    return (uint32_t)__cvta_generic_to_shared(p);
}
__device__ __forceinline__ void cp16(uint32_t dst, const void* src) {
    asm volatile("cp.async.ca.shared.global [%0], [%1], 16;" :: "r"(dst), "l"(src));
}
__device__ __forceinline__ void cp_commit() { asm volatile("cp.async.commit_group;"); }
template<int N> __device__ __forceinline__ void cp_wait() {
    asm volatile("cp.async.wait_group %0;" :: "n"(N));
}

// ---------------- small kernels ----------------
__global__ void k_deg(const int* __restrict__ dst, const int* __restrict__ comm) {
    int i = blockIdx.x * blockDim.x + threadIdx.x;
    if (i < NEDGE) atomicAdd(&g_deg[dst[i]], 1);
    if (i < NP)    atomicAdd(&g_cnt[comm[i]], 1);
}
__global__ void k_inv() {
    int i = blockIdx.x * blockDim.x + threadIdx.x;
    if (i < NN) g_invdeg[i] = 1.0f / (float)max(g_deg[i], 1);
    if (i < NC) g_invcnt[i] = 1.0f / (float)max(g_cnt[i], 1);
}
// transpose + convert: dst[n*K+k] = half(src[k*N+n])
__global__ void k_transW(__half* __restrict__ dstb, const float* __restrict__ src,
                         int K, int N) {
    int i = blockIdx.x * 256 + threadIdx.x;
    if (i >= N * K) return;
    int n = i / K, k = i % K;
    dstb[i] = __float2half(src[k * N + n]);
}
__global__ void k_scale() {   // aggh = half(agg * invdeg[row])
    int i = blockIdx.x * 256 + threadIdx.x;
    if (i < NN * 128) g_aggh[i] = __float2half(g_agg[i] * g_invdeg[i >> 7]);
}
__global__ void k_ea(const float* __restrict__ eattr,
                     const float* __restrict__ We, const float* __restrict__ be) {
    int gid = blockIdx.x * 256 + threadIdx.x;
    int e = gid >> 6, c = gid & 63;
    if (e >= NEDGE) return;
    const float* a = eattr + e * 8;
    float s = be[c];
#pragma unroll
    for (int k = 0; k < 8; k++) s += a[k] * We[k * 64 + c];
    g_ea[e * 64 + c] = __float2half(fmaxf(s, 0.0f));
}
__global__ void k_ht(const float* __restrict__ x,
                     const float* __restrict__ W1, const float* __restrict__ b1,
                     const float* __restrict__ W2, const float* __restrict__ b2) {
    int n = blockIdx.x;
    int c = threadIdx.x;
    const float* xr = x + n * 20;
    float s;
    if (c < 64) {
        s = b1[c];
#pragma unroll
        for (int k = 0; k < 8; k++) s += xr[k] * W1[k * 64 + c];
    } else {
        int cc = c - 64;
        s = b2[cc];
#pragma unroll
        for (int k = 0; k < 12; k++) s += xr[8 + k] * W2[k * 64 + cc];
    }
    g_ht[n * 128 + c] = __float2half(fmaxf(s, 0.0f));
}

// ================= generic fp16 gather-GEMM (nodes + pool) =================
// BM=128, BN=128, BK=32, 256 threads, m16n8k16, 2-stage cp.async.
enum { M_PLAIN = 0, M_PAIR = 3 };
enum { E_RELU = 0, E_POOL = 2 };

template<int MODE, int K>
__device__ __forceinline__ void load_stage(
    __half* As, __half* Ws, int t, int st,
    const __half* __restrict__ A, const __half* __restrict__ Wt,
    const size_t* offA, const size_t* offB,
    int tid, int n0)
{
    const int k0 = t * 32;
    const int chunk = tid & 3;          // 8-half chunk within row
    const int gk = k0 + chunk * 8;
#pragma unroll
    for (int l = 0; l < 2; l++) {
        int row = (tid >> 2) + l * 64;
        uint32_t dst = s2u(&As[st * 5120 + row * TS + chunk * 8]);
        const __half* src;
        if (MODE == M_PLAIN) src = A + offA[l] + gk;
        else src = (gk < 128) ? (A + offA[l] + gk) : (A + offB[l] + (gk - 128));
        cp16(dst, src);
    }
#pragma unroll
    for (int l = 0; l < 2; l++) {
        int nrow = (tid >> 2) + l * 64;
        cp16(s2u(&Ws[st * 5120 + nrow * TS + chunk * 8]),
             Wt + (size_t)(n0 + nrow) * K + gk);
    }
}

template<int MODE, int EPI, int K>
__global__ void __launch_bounds__(256)
gemm_tc(const __half* __restrict__ A, const __half* __restrict__ Wt,
        const float* __restrict__ bias, void* __restrict__ CoutV,
        const int* __restrict__ idx1, const int* __restrict__ idx2,
        const int* __restrict__ idx3, int rows, int ncols)
{
    __shared__ __half As[2 * 5120];
    __shared__ __half Ws[2 * 5120];

    const int tid  = threadIdx.x;
    const int wid  = tid >> 5, lane = tid & 31;
    const int wm   = wid & 1,  wn   = wid >> 1;
    const int g    = lane >> 2, tig = lane & 3;
    const int rowbase = blockIdx.x * 128;
    const int n0      = blockIdx.y * 128;

    size_t offA[2], offB[2];
#pragma unroll
    for (int l = 0; l < 2; l++) {
        int grow = rowbase + (tid >> 2) + l * 64;
        int gc = (grow < rows) ? grow : (rows - 1);
        if (MODE == M_PLAIN) { offA[l] = (size_t)gc * K; offB[l] = 0; }
        else { offA[l] = (size_t)idx1[gc] * 128; offB[l] = (size_t)idx2[gc] * 128; }
    }

    float acc[4][4][4];
#pragma unroll
    for (int a = 0; a < 4; a++)
#pragma unroll
        for (int b = 0; b < 4; b++)
#pragma unroll
            for (int c = 0; c < 4; c++) acc[a][b][c] = 0.0f;

    const int NT = K / 32;
    load_stage<MODE, K>(As, Ws, 0, 0, A, Wt, offA, offB, tid, n0);
    cp_commit();

    for (int t = 0; t < NT; t++) {
        const int s = t & 1;
        if (t + 1 < NT) {
            load_stage<MODE, K>(As, Ws, t + 1, (t + 1) & 1, A, Wt, offA, offB, tid, n0);
            cp_commit();
            cp_wait<1>();
        } else cp_wait<0>();
        __syncthreads();

        const __half* Ab = As + s * 5120;
        const __half* Wb = Ws + s * 5120;
#pragma unroll
        for (int ks = 0; ks < 2; ks++) {
            const int kb = ks * 16;
            uint32_t af[4][4];
#pragma unroll
            for (int mt = 0; mt < 4; mt++) {
                int r0 = wm * 64 + mt * 16 + g;
                af[mt][0] = h2u(&Ab[r0      * TS + kb + 2 * tig]);
                af[mt][1] = h2u(&Ab[(r0 + 8) * TS + kb + 2 * tig]);
                af[mt][2] = h2u(&Ab[r0      * TS + kb + 2 * tig + 8]);
                af[mt][3] = h2u(&Ab[(r0 + 8) * TS + kb + 2 * tig + 8]);
            }
            uint32_t bf[4][2];
#pragma unroll
            for (int nt = 0; nt < 4; nt++) {
                int nr = wn * 32 + nt * 8 + g;
                bf[nt][0] = h2u(&Wb[nr * TS + kb + 2 * tig]);
                bf[nt][1] = h2u(&Wb[nr * TS + kb + 2 * tig + 8]);
            }
#pragma unroll
            for (int mt = 0; mt < 4; mt++)
#pragma unroll
                for (int nt = 0; nt < 4; nt++)
                    mma_f16(acc[mt][nt], af[mt], bf[nt]);
        }
        __syncthreads();
    }

    float bc0[4], bc1[4];
#pragma unroll
    for (int nt = 0; nt < 4; nt++) {
        int c = wn * 32 + nt * 8 + tig * 2;
        bc0[nt] = bias[n0 + c];
        bc1[nt] = bias[n0 + c + 1];
    }

#pragma unroll
    for (int mt = 0; mt < 4; mt++) {
#pragma unroll
        for (int half_ = 0; half_ < 2; half_++) {
            int rl = wm * 64 + mt * 16 + g + half_ * 8;
            int r  = rowbase + rl;
            if (r >= rows) continue;
            if (EPI == E_RELU) {
                __half* op = (__half*)CoutV + (size_t)r * ncols + n0;
#pragma unroll
                for (int nt = 0; nt < 4; nt++) {
                    int c = wn * 32 + nt * 8 + tig * 2;
                    float v0 = fmaxf(acc[mt][nt][half_ * 2    ] + bc0[nt], 0.f);
                    float v1 = fmaxf(acc[mt][nt][half_ * 2 + 1] + bc1[nt], 0.f);
                    *(__half2*)&op[c] = __floats2half2_rn(v0, v1);
                }
            } else { // E_POOL
                int rep = (blockIdx.x & (RPL - 1)) * (NC * 256);
                int cm  = idx3[r];
                float* pb = (float*)CoutV + rep + cm * 256 + n0;
#pragma unroll
                for (int nt = 0; nt < 4; nt++) {
                    int c = wn * 32 + nt * 8 + tig * 2;
                    float v0 = fmaxf(acc[mt][nt][half_ * 2    ] + bc0[nt], 0.f);
                    float v1 = fmaxf(acc[mt][nt][half_ * 2 + 1] + bc1[nt], 0.f);
                    red_v2(&pb[c], v0, v1);
                }
            }
        }
    }
}

// ================= fused EL + gate1 + gate2 kernel (fp16) =================
#define SM_AS 0
#define SM_WS 20480
#define SM_MS 40960
#define SMEM_EL (SM_MS + 128 * MST * 2)   // 40960 + 34816 = 75776 bytes

__device__ __forceinline__ void el_loadW(__half* Ws, int t, int st,
                                         const __half* __restrict__ Wt, int Kw, int tid) {
    const int k0 = t * 32;
    const int chunk = tid & 3;
#pragma unroll
    for (int l = 0; l < 2; l++) {
        int nrow = (tid >> 2) + l * 64;
        cp16(s2u(&Ws[st * 5120 + nrow * TS + chunk * 8]),
             Wt + (size_t)nrow * Kw + k0 + chunk * 8);
    }
}

__global__ void __launch_bounds__(256)
k_elconv(const __half* __restrict__ h, const __half* __restrict__ ea,
         const __half* __restrict__ Welt, const float* __restrict__ bel,
         const __half* __restrict__ Wm1t, const float* __restrict__ bm1,
         const __half* __restrict__ Wm2t, const float* __restrict__ bm2,
         const int* __restrict__ src, const int* __restrict__ dst,
         float* __restrict__ agg, __half* __restrict__ gate2)
{
    extern __shared__ char smem[];
    __half* As = (__half*)(smem + SM_AS);
    __half* Ws = (__half*)(smem + SM_WS);
    __half* Ms = (__half*)(smem + SM_MS);

    const int tid  = threadIdx.x;
    const int wid  = tid >> 5, lane = tid & 31;
    const int wm   = wid & 1,  wn   = wid >> 1;
    const int g    = lane >> 2, tig = lane & 3;
    const int rowbase = blockIdx.x * 128;     // NEDGE % 128 == 0

    size_t offA[2], offB[2], offE[2];
#pragma unroll
    for (int l = 0; l < 2; l++) {
        int grow = rowbase + (tid >> 2) + l * 64;
        offA[l] = (size_t)src[grow] * 128;
        offB[l] = (size_t)dst[grow] * 128;
        offE[l] = (size_t)grow * 64;
    }

    float acc[4][4][4];
#pragma unroll
    for (int a = 0; a < 4; a++)
#pragma unroll
        for (int b = 0; b < 4; b++)
#pragma unroll
            for (int c = 0; c < 4; c++) acc[a][b][c] = 0.0f;

    // ---- phase 1: K=320, 10 k-tiles ----
    {
        const int chunk = tid & 3;
        {   // t=0: gk < 32 -> all from h/offA
#pragma unroll
            for (int l = 0; l < 2; l++) {
                int row = (tid >> 2) + l * 64;
                cp16(s2u(&As[row * TS + chunk * 8]), h + offA[l] + chunk * 8);
            }
            el_loadW(Ws, 0, 0, Welt, 320, tid);
            cp_commit();
        }
        const int NT = 10;
        for (int t = 0; t < NT; t++) {
            const int s = t & 1;
            if (t + 1 < NT) {
                const int sn = (t + 1) & 1;
                const int gk = (t + 1) * 32 + chunk * 8;
#pragma unroll
                for (int l = 0; l < 2; l++) {
                    int row = (tid >> 2) + l * 64;
                    const __half* srcp;
                    if (gk < 128)      srcp = h  + offA[l] + gk;
                    else if (gk < 256) srcp = h  + offB[l] + (gk - 128);
                    else               srcp = ea + offE[l] + (gk - 256);
                    cp16(s2u(&As[sn * 5120 + row * TS + chunk * 8]), srcp);
                }
                el_loadW(Ws, t + 1, sn, Welt, 320, tid);
                cp_commit();
                cp_wait<1>();
            } else cp_wait<0>();
            __syncthreads();

            const __half* Ab = As + s * 5120;
            const __half* Wb = Ws + s * 5120;
#pragma unroll
            for (int ks = 0; ks < 2; ks++) {
                const int kb = ks * 16;
                uint32_t af[4][4];
#pragma unroll
                for (int mt = 0; mt < 4; mt++) {
                    int r0 = wm * 64 + mt * 16 + g;
                    af[mt][0] = h2u(&Ab[r0      * TS + kb + 2 * tig]);
                    af[mt][1] = h2u(&Ab[(r0 + 8) * TS + kb + 2 * tig]);
                    af[mt][2] = h2u(&Ab[r0      * TS + kb + 2 * tig + 8]);
                    af[mt][3] = h2u(&Ab[(r0 + 8) * TS + kb + 2 * tig + 8]);
                }
                uint32_t bf[4][2];
#pragma unroll
                for (int nt = 0; nt < 4; nt++) {
                    int nr = wn * 32 + nt * 8 + g;
                    bf[nt][0] = h2u(&Wb[nr * TS + kb + 2 * tig]);
                    bf[nt][1] = h2u(&Wb[nr * TS + kb + 2 * tig + 8]);
                }
#pragma unroll
                for (int mt = 0; mt < 4; mt++)
#pragma unroll
                    for (int nt = 0; nt < 4; nt++)
                        mma_f16(acc[mt][nt], af[mt], bf[nt]);
            }
            __syncthreads();
        }
        // epilogue -> Ms (fp16 mask)
#pragma unroll
        for (int mt = 0; mt < 4; mt++)
#pragma unroll
            for (int half_ = 0; half_ < 2; half_++) {
                int rl = wm * 64 + mt * 16 + g + half_ * 8;
#pragma unroll
                for (int nt = 0; nt < 4; nt++) {
                    int c = wn * 32 + nt * 8 + tig * 2;
                    float v0 = fmaxf(acc[mt][nt][half_ * 2    ] + bel[c    ], 0.f);
                    float v1 = fmaxf(acc[mt][nt][half_ * 2 + 1] + bel[c + 1], 0.f);
                    *(__half2*)&Ms[rl * MST + c] = __floats2half2_rn(v0, v1);
                }
            }
        __syncthreads();
    }

    // ---- phases 2 & 3: Ms @ Wm{1,2}, K=128, 4 k-tiles ----
#pragma unroll 1
    for (int ph = 0; ph < 2; ph++) {
        const __half* Wm = (ph == 0) ? Wm1t : Wm2t;
        const float*  bm = (ph == 0) ? bm1 : bm2;

#pragma unroll
        for (int a = 0; a < 4; a++)
#pragma unroll
            for (int b = 0; b < 4; b++)
#pragma unroll
                for (int c = 0; c < 4; c++) acc[a][b][c] = 0.0f;

        el_loadW(Ws, 0, 0, Wm, 128, tid);
        cp_commit();
        for (int t = 0; t < 4; t++) {
            const int s = t & 1;
            if (t + 1 < 4) {
                el_loadW(Ws, t + 1, (t + 1) & 1, Wm, 128, tid);
                cp_commit();
                cp_wait<1>();
            } else cp_wait<0>();
            __syncthreads();

            const __half* Wb = Ws + s * 5120;
#pragma unroll
            for (int ks = 0; ks < 2; ks++) {
                const int kbM = t * 32 + ks * 16;   // into Ms
                const int kbW = ks * 16;            // into Ws stage
                uint32_t af[4][4];
#pragma unroll
                for (int mt = 0; mt < 4; mt++) {
                    int r0 = wm * 64 + mt * 16 + g;
                    af[mt][0] = h2u(&Ms[r0      * MST + kbM + 2 * tig]);
                    af[mt][1] = h2u(&Ms[(r0 + 8) * MST + kbM + 2 * tig]);
                    af[mt][2] = h2u(&Ms[r0      * MST + kbM + 2 * tig + 8]);
                    af[mt][3] = h2u(&Ms[(r0 + 8) * MST + kbM + 2 * tig + 8]);
                }
                uint32_t bf[4][2];
#pragma unroll
                for (int nt = 0; nt < 4; nt++) {
                    int nr = wn * 32 + nt * 8 + g;
                    bf[nt][0] = h2u(&Wb[nr * TS + kbW + 2 * tig]);
                    bf[nt][1] = h2u(&Wb[nr * TS + kbW + 2 * tig + 8]);
                }
#pragma unroll
                for (int mt = 0; mt < 4; mt++)
#pragma unroll
                    for (int nt = 0; nt < 4; nt++)
                        mma_f16(acc[mt][nt], af[mt], bf[nt]);
            }
            __syncthreads();
        }

        if (ph == 0) {
            // conv1: gate, message from h[src], RED into agg
#pragma unroll
            for (int mt = 0; mt < 4; mt++)
#pragma unroll
                for (int half_ = 0; half_ < 2; half_++) {
                    int rl = wm * 64 + mt * 16 + g + half_ * 8;
                    int r  = rowbase + rl;
                    int sI = src[r], dI = dst[r];
                    const __half* hs = h + (size_t)sI * 128;
                    float*        ag = agg + (size_t)dI * 128;
#pragma unroll
                    for (int nt = 0; nt < 4; nt++) {
                        int c = wn * 32 + nt * 8 + tig * 2;
                        float z0 = acc[mt][nt][half_ * 2    ] + bm[c];
                        float z1 = acc[mt][nt][half_ * 2 + 1] + bm[c + 1];
                        float g0 = 1.0f / (1.0f + __expf(-z0));
                        float g1 = 1.0f / (1.0f + __expf(-z1));
                        float2 hv = __half22float2(*(const __half2*)&hs[c]);
                        red_v2(&ag[c], g0 * hv.x, g1 * hv.y);
                    }
                }
        } else {
            // conv2 gates -> write into Ms (all MMA reads done), then coalesced copy
#pragma unroll
            for (int mt = 0; mt < 4; mt++)
#pragma unroll
                for (int half_ = 0; half_ < 2; half_++) {
                    int rl = wm * 64 + mt * 16 + g + half_ * 8;
#pragma unroll
                    for (int nt = 0; nt < 4; nt++) {
                        int c = wn * 32 + nt * 8 + tig * 2;
                        float z0 = acc[mt][nt][half_ * 2    ] + bm[c];
                        float z1 = acc[mt][nt][half_ * 2 + 1] + bm[c + 1];
                        float g0 = 1.0f / (1.0f + __expf(-z0));
                        float g1 = 1.0f / (1.0f + __expf(-z1));
                        *(__half2*)&Ms[rl * MST + c] = __floats2half2_rn(g0, g1);
                    }
                }
            __syncthreads();
            __half* gout = gate2 + (size_t)rowbase * 128;
            for (int i = tid; i < 2048; i += 256) {   // 128 rows x 16 x 16B
                int row = i >> 4, part = i & 15;
                float4 v = *(float4*)&Ms[row * MST + part * 8];
                *(float4*)&gout[row * 128 + part * 8] = v;
            }
        }
    }
}

// ---------------- conv2 scatter: msg = gate2 * h2[src], RED to agg ----------------
__global__ void __launch_bounds__(256) k_conv2(const int* __restrict__ src,
                                               const int* __restrict__ dst) {
    int wid = threadIdx.x >> 5, lane = threadIdx.x & 31;
    int e = blockIdx.x * 8 + wid;          // NEDGE/8 blocks
    int sI = src[e], dI = dst[e];
    const __half* gp = g_g2 + (size_t)e * 128 + lane * 4;
    const __half* hp = g_h2 + (size_t)sI * 128 + lane * 4;
    float2 ga = __half22float2(*(const __half2*)&gp[0]);
    float2 gb = __half22float2(*(const __half2*)&gp[2]);
    float2 ha = __half22float2(*(const __half2*)&hp[0]);
    float2 hb = __half22float2(*(const __half2*)&hp[2]);
    float* ag = g_agg + (size_t)dI * 128 + lane * 4;
    red_v2(ag,     ga.x * ha.x, ga.y * ha.y);
    red_v2(ag + 2, gb.x * hb.x, gb.y * hb.y);
}

// ---------------- pool reduce ----------------
template<bool ADD>
__global__ void k_poolreduce() {
    int i = blockIdx.x * 256 + threadIdx.x;
    int c = i >> 8;
    float s = 0.f;
#pragma unroll
    for (int r = 0; r < RPL; r++) s += g_pool[r * NC * 256 + i];
    s *= g_invcnt[c];
    if (ADD) g_s[i] += s; else g_s[i] = s;
}

// ---------------- final MLP ----------------
__global__ void k_final(const float* __restrict__ Wl1, const float* __restrict__ bl1,
                        const float* __restrict__ Wl2, const float* __restrict__ bl2,
                        float* __restrict__ out) {
    __shared__ float sv[256];
    __shared__ float red[256];
    int c = blockIdx.x, j = threadIdx.x;
    sv[j] = g_s[c * 256 + j];
    __syncthreads();
    float a = bl1[j];
    for (int k = 0; k < 256; k++)
        a += sv[k] * (Wl1[k * 256 + j] + Wl1[(256 + k) * 256 + j]);
    red[j] = fmaxf(a, 0.f) * Wl2[j];
    __syncthreads();
    for (int s = 128; s > 0; s >>= 1) {
        if (j < s) red[j] += red[j + s];
        __syncthreads();
    }
    if (j == 0) out[c] = red[0] + bl2[0];
}

// ---------------- host launch ----------------
extern "C" void kernel_launch(void* const* d_in, const int* in_sizes, int n_in,
                              void* d_out, int out_size) {
    (void)in_sizes; (void)n_in; (void)out_size;
    const float* x     = (const float*)d_in[0];
    const float* eattr = (const float*)d_in[1];
    const int*   ei    = (const int*)d_in[2];
    const int*   comm  = (const int*)d_in[3];
    const int*   pe    = (const int*)d_in[4];
    const float* We  = (const float*)d_in[5],  * be  = (const float*)d_in[6];
    const float* W1  = (const float*)d_in[7],  * b1  = (const float*)d_in[8];
    const float* W2  = (const float*)d_in[9],  * b2  = (const float*)d_in[10];
    const float* W3  = (const float*)d_in[11], * b3  = (const float*)d_in[12];
    const float* Wel = (const float*)d_in[13], * bel = (const float*)d_in[14];
    const float* Wm1 = (const float*)d_in[15], * bm1 = (const float*)d_in[16];
    const float* Wc1 = (const float*)d_in[17], * bc1 = (const float*)d_in[18];
    const float* Wm2 = (const float*)d_in[19], * bm2 = (const float*)d_in[20];
    const float* Wc2 = (const float*)d_in[21], * bc2 = (const float*)d_in[22];
    const float* Wam = (const float*)d_in[23], * bam = (const float*)d_in[24];
    const float* Wl1 = (const float*)d_in[25], * bl1 = (const float*)d_in[26];
    const float* Wl2 = (const float*)d_in[27], * bl2 = (const float*)d_in[28];

    const int* src = ei, * dst = ei + NEDGE;
    const int* pi  = pe, * pj  = pe + NP;

    __half *ea_, *ht_, *h_, *h2_, *h3_, *aggh_, *g2_, *wh_;
    float *agg_, *pool_;
    int *deg_, *cnt_;
    cudaGetSymbolAddress((void**)&ea_,   g_ea);
    cudaGetSymbolAddress((void**)&ht_,   g_ht);
    cudaGetSymbolAddress((void**)&h_,    g_h);
    cudaGetSymbolAddress((void**)&h2_,   g_h2);
    cudaGetSymbolAddress((void**)&h3_,   g_h3);
    cudaGetSymbolAddress((void**)&aggh_, g_aggh);
    cudaGetSymbolAddress((void**)&agg_,  g_agg);
    cudaGetSymbolAddress((void**)&pool_, g_pool);
    cudaGetSymbolAddress((void**)&wh_,   g_wh);
    cudaGetSymbolAddress((void**)&g2_,   g_g2);
    cudaGetSymbolAddress((void**)&deg_,  g_deg);
    cudaGetSymbolAddress((void**)&cnt_,  g_cnt);

    static int smem_set = 0;
    if (!smem_set) {
        cudaFuncSetAttribute(k_elconv, cudaFuncAttributeMaxDynamicSharedMemorySize, SMEM_EL);
        smem_set = 1;
    }

    cudaMemsetAsync(deg_,  0, NN * sizeof(int));
    cudaMemsetAsync(cnt_,  0, NC * sizeof(int));
    cudaMemsetAsync(agg_,  0, (size_t)NN * 128 * sizeof(float));
    cudaMemsetAsync(pool_, 0, (size_t)RPL * NC * 256 * sizeof(float));

    k_deg<<<(NEDGE + 255) / 256, 256>>>(dst, comm);
    k_inv<<<(NN + 255) / 256, 256>>>();

    // fp16 weights, transposed to [N][K]
    k_transW<<<(16384 + 255) / 256, 256>>>(wh_ + OW3,  W3,  128, 128);
    k_transW<<<(40960 + 255) / 256, 256>>>(wh_ + OWEL, Wel, 320, 128);
    k_transW<<<(16384 + 255) / 256, 256>>>(wh_ + OWM1, Wm1, 128, 128);
    k_transW<<<(16384 + 255) / 256, 256>>>(wh_ + OWC1, Wc1, 128, 128);
    k_transW<<<(16384 + 255) / 256, 256>>>(wh_ + OWM2, Wm2, 128, 128);
    k_transW<<<(16384 + 255) / 256, 256>>>(wh_ + OWC2, Wc2, 128, 128);
    k_transW<<<(65536 + 255) / 256, 256>>>(wh_ + OWAM, Wam, 256, 256);

    k_ea<<<(NEDGE * 64 + 255) / 256, 256>>>(eattr, We, be);
    k_ht<<<NN, 128>>>(x, W1, b1, W2, b2);

    dim3 blk(256);
    const int gN = (NN + 127) / 128;      // 391
    const int gE = NEDGE / 128;           // 6250
    const int gP = NP / 128;              // 3125

    // h = relu(ht @ W3 + b3)
    gemm_tc<M_PLAIN, E_RELU, 128><<<dim3(gN, 1), blk>>>(ht_, wh_ + OW3, b3, h_,
        nullptr, nullptr, nullptr, NN, 128);

    // fused: mask (smem) -> conv1 scatter + conv2 gates
    k_elconv<<<gE, blk, SMEM_EL>>>(h_, ea_, wh_ + OWEL, bel,
                                   wh_ + OWM1, bm1, wh_ + OWM2, bm2,
                                   src, dst, agg_, g2_);
    k_scale<<<(NN * 128 + 255) / 256, 256>>>();
    gemm_tc<M_PLAIN, E_RELU, 128><<<dim3(gN, 1), blk>>>(aggh_, wh_ + OWC1, bc1, h2_,
        nullptr, nullptr, nullptr, NN, 128);
    // pool1
    gemm_tc<M_PAIR, E_POOL, 256><<<dim3(gP, 2), blk>>>(h2_, wh_ + OWAM, bam, pool_,
        pi, pj, comm, NP, 256);
    k_poolreduce<false><<<NC, 256>>>();

    cudaMemsetAsync(agg_,  0, (size_t)NN * 128 * sizeof(float));
    cudaMemsetAsync(pool_, 0, (size_t)RPL * NC * 256 * sizeof(float));

    // conv2: pure scatter with precomputed fp16 gates
    k_conv2<<<NEDGE / 8, 256>>>(src, dst);
    k_scale<<<(NN * 128 + 255) / 256, 256>>>();
    gemm_tc<M_PLAIN, E_RELU, 128><<<dim3(gN, 1), blk>>>(aggh_, wh_ + OWC2, bc2, h3_,
        nullptr, nullptr, nullptr, NN, 128);
    // pool2
    gemm_tc<M_PAIR, E_POOL, 256><<<dim3(gP, 2), blk>>>(h3_, wh_ + OWAM, bam, pool_,
        pi, pj, comm, NP, 256);
    k_poolreduce<true><<<NC, 256>>>();

    k_final<<<NC, 256>>>(Wl1, bl1, Wl2, bl2, (float*)d_out);
}

// round 10
// speedup vs baseline: 3.0939x; 1.0795x over previous
#include <cuda_runtime.h>
#include <cuda_fp16.h>
#include <math.h>
#include <stdint.h>

#define NN     50000
#define NEDGE  800000
#define NP     400000
#define NC     1000
#define RPL    32

// ---------------- scratch ----------------
__device__ __half  g_ht  [NN * 128];
__device__ __half  g_h   [NN * 128];
__device__ __half  g_h2  [NN * 128];
__device__ __half  g_h3  [NN * 128];
__device__ float   g_agg [NN * 128];
__device__ float   g_agg2[NN * 128];
__device__ __half  g_aggh [NN * 128];
__device__ __half  g_aggh2[NN * 128];
__device__ __half  g_g2  [NEDGE * 128];
__device__ float   g_invdeg[NN];
__device__ int     g_deg [NN];
__device__ int     g_cnt [NC];
__device__ float   g_invcnt[NC];
__device__ float   g_pool1[RPL * NC * 256];
__device__ float   g_pool2[RPL * NC * 256];
__device__ float   g_s1  [NC * 256];
__device__ float   g_s2  [NC * 256];
__device__ __half  g_wh  [188416];   // fp16 weights, [N][K] transposed, packed

#define OW3   0
#define OWEL  16384
#define OWM1  57344
#define OWC1  73728
#define OWM2  90112
#define OWC2  106496
#define OWAM  122880

#define TS  40
#define MST 136

// ---------------- helpers ----------------
__device__ __forceinline__ void mma_f16(float* d, const uint32_t* a, const uint32_t* b) {
    asm volatile(
        "mma.sync.aligned.m16n8k16.row.col.f32.f16.f16.f32 "
        "{%0,%1,%2,%3}, {%4,%5,%6,%7}, {%8,%9}, {%0,%1,%2,%3};\n"
        : "+f"(d[0]), "+f"(d[1]), "+f"(d[2]), "+f"(d[3])
        : "r"(a[0]), "r"(a[1]), "r"(a[2]), "r"(a[3]), "r"(b[0]), "r"(b[1]));
}
__device__ __forceinline__ uint32_t h2u(const __half* p) { return *(const uint32_t*)p; }
__device__ __forceinline__ void red_v2(float* p, float v0, float v1) {
    asm volatile("red.global.add.v2.f32 [%0], {%1, %2};"
                 :: "l"(p), "f"(v0), "f"(v1) : "memory");
}
__device__ __forceinline__ uint32_t s2u(const void* p) {
    return (uint32_t)__cvta_generic_to_shared(p);
}
__device__ __forceinline__ void cp16(uint32_t dst, const void* src) {
    asm volatile("cp.async.ca.shared.global [%0], [%1], 16;" :: "r"(dst), "l"(src));
}
__device__ __forceinline__ void cp_commit() { asm volatile("cp.async.commit_group;"); }
template<int N> __device__ __forceinline__ void cp_wait() {
    asm volatile("cp.async.wait_group %0;" :: "n"(N));
}

// ---------------- small kernels ----------------
__global__ void k_deg(const int* __restrict__ dst, const int* __restrict__ comm) {
    int i = blockIdx.x * blockDim.x + threadIdx.x;
    if (i < NEDGE) atomicAdd(&g_deg[dst[i]], 1);
    if (i < NP)    atomicAdd(&g_cnt[comm[i]], 1);
}
__global__ void k_inv() {
    int i = blockIdx.x * blockDim.x + threadIdx.x;
    if (i < NN) g_invdeg[i] = 1.0f / (float)max(g_deg[i], 1);
    if (i < NC) g_invcnt[i] = 1.0f / (float)max(g_cnt[i], 1);
}
// all 7 weight transposes in one launch (736 blocks x 256)
__global__ void k_transAll(const float* __restrict__ W3,  const float* __restrict__ Wel,
                           const float* __restrict__ Wm1, const float* __restrict__ Wc1,
                           const float* __restrict__ Wm2, const float* __restrict__ Wc2,
                           const float* __restrict__ Wam) {
    int b = blockIdx.x;
    const float* src; __half* dst; int K, N, base;
    if      (b < 64)  { src = W3;  dst = g_wh + OW3;  K = 128; N = 128; base = b; }
    else if (b < 224) { src = Wel; dst = g_wh + OWEL; K = 320; N = 128; base = b - 64; }
    else if (b < 288) { src = Wm1; dst = g_wh + OWM1; K = 128; N = 128; base = b - 224; }
    else if (b < 352) { src = Wc1; dst = g_wh + OWC1; K = 128; N = 128; base = b - 288; }
    else if (b < 416) { src = Wm2; dst = g_wh + OWM2; K = 128; N = 128; base = b - 352; }
    else if (b < 480) { src = Wc2; dst = g_wh + OWC2; K = 128; N = 128; base = b - 416; }
    else              { src = Wam; dst = g_wh + OWAM; K = 256; N = 256; base = b - 480; }
    int i = base * 256 + threadIdx.x;
    int n = i / K, k = i % K;
    dst[i] = __float2half(src[k * N + n]);
}
__global__ void k_scale(const float* __restrict__ in, __half* __restrict__ out) {
    int i = blockIdx.x * 256 + threadIdx.x;
    if (i < NN * 128) out[i] = __float2half(in[i] * g_invdeg[i >> 7]);
}
__global__ void k_ht(const float* __restrict__ x,
                     const float* __restrict__ W1, const float* __restrict__ b1,
                     const float* __restrict__ W2, const float* __restrict__ b2) {
    int n = blockIdx.x;
    int c = threadIdx.x;
    const float* xr = x + n * 20;
    float s;
    if (c < 64) {
        s = b1[c];
#pragma unroll
        for (int k = 0; k < 8; k++) s += xr[k] * W1[k * 64 + c];
    } else {
        int cc = c - 64;
        s = b2[cc];
#pragma unroll
        for (int k = 0; k < 12; k++) s += xr[8 + k] * W2[k * 64 + cc];
    }
    g_ht[n * 128 + c] = __float2half(fmaxf(s, 0.0f));
}

// ================= generic fp16 gather-GEMM =================
enum { M_PLAIN = 0, M_PAIR = 3 };
enum { E_RELU = 0, E_POOL = 2 };

template<int MODE, int K>
__device__ __forceinline__ void load_stage(
    __half* As, __half* Ws, int t, int st,
    const __half* __restrict__ A, const __half* __restrict__ Wt,
    const size_t* offA, const size_t* offB, int tid, int n0)
{
    const int k0 = t * 32;
    const int chunk = tid & 3;
    const int gk = k0 + chunk * 8;
#pragma unroll
    for (int l = 0; l < 2; l++) {
        int row = (tid >> 2) + l * 64;
        uint32_t dst = s2u(&As[st * 5120 + row * TS + chunk * 8]);
        const __half* src;
        if (MODE == M_PLAIN) src = A + offA[l] + gk;
        else src = (gk < 128) ? (A + offA[l] + gk) : (A + offB[l] + (gk - 128));
        cp16(dst, src);
    }
#pragma unroll
    for (int l = 0; l < 2; l++) {
        int nrow = (tid >> 2) + l * 64;
        cp16(s2u(&Ws[st * 5120 + nrow * TS + chunk * 8]),
             Wt + (size_t)(n0 + nrow) * K + gk);
    }
}

template<int MODE, int EPI, int K>
__global__ void __launch_bounds__(256)
gemm_tc(const __half* __restrict__ A, const __half* __restrict__ Wt,
        const float* __restrict__ bias, void* __restrict__ CoutV,
        const int* __restrict__ idx1, const int* __restrict__ idx2,
        const int* __restrict__ idx3, int rows, int ncols)
{
    __shared__ __half As[2 * 5120];
    __shared__ __half Ws[2 * 5120];

    const int tid  = threadIdx.x;
    const int wid  = tid >> 5, lane = tid & 31;
    const int wm   = wid & 1,  wn   = wid >> 1;
    const int g    = lane >> 2, tig = lane & 3;
    const int rowbase = blockIdx.x * 128;
    const int n0      = blockIdx.y * 128;

    size_t offA[2], offB[2];
#pragma unroll
    for (int l = 0; l < 2; l++) {
        int grow = rowbase + (tid >> 2) + l * 64;
        int gc = (grow < rows) ? grow : (rows - 1);
        if (MODE == M_PLAIN) { offA[l] = (size_t)gc * K; offB[l] = 0; }
        else { offA[l] = (size_t)idx1[gc] * 128; offB[l] = (size_t)idx2[gc] * 128; }
    }

    float acc[4][4][4];
#pragma unroll
    for (int a = 0; a < 4; a++)
#pragma unroll
        for (int b = 0; b < 4; b++)
#pragma unroll
            for (int c = 0; c < 4; c++) acc[a][b][c] = 0.0f;

    const int NT = K / 32;
    load_stage<MODE, K>(As, Ws, 0, 0, A, Wt, offA, offB, tid, n0);
    cp_commit();

    for (int t = 0; t < NT; t++) {
        const int s = t & 1;
        if (t + 1 < NT) {
            load_stage<MODE, K>(As, Ws, t + 1, (t + 1) & 1, A, Wt, offA, offB, tid, n0);
            cp_commit();
            cp_wait<1>();
        } else cp_wait<0>();
        __syncthreads();

        const __half* Ab = As + s * 5120;
        const __half* Wb = Ws + s * 5120;
#pragma unroll
        for (int ks = 0; ks < 2; ks++) {
            const int kb = ks * 16;
            uint32_t af[4][4];
#pragma unroll
            for (int mt = 0; mt < 4; mt++) {
                int r0 = wm * 64 + mt * 16 + g;
                af[mt][0] = h2u(&Ab[r0      * TS + kb + 2 * tig]);
                af[mt][1] = h2u(&Ab[(r0 + 8) * TS + kb + 2 * tig]);
                af[mt][2] = h2u(&Ab[r0      * TS + kb + 2 * tig + 8]);
                af[mt][3] = h2u(&Ab[(r0 + 8) * TS + kb + 2 * tig + 8]);
            }
            uint32_t bf[4][2];
#pragma unroll
            for (int nt = 0; nt < 4; nt++) {
                int nr = wn * 32 + nt * 8 + g;
                bf[nt][0] = h2u(&Wb[nr * TS + kb + 2 * tig]);
                bf[nt][1] = h2u(&Wb[nr * TS + kb + 2 * tig + 8]);
            }
#pragma unroll
            for (int mt = 0; mt < 4; mt++)
#pragma unroll
                for (int nt = 0; nt < 4; nt++)
                    mma_f16(acc[mt][nt], af[mt], bf[nt]);
        }
        __syncthreads();
    }

    float bc0[4], bc1[4];
#pragma unroll
    for (int nt = 0; nt < 4; nt++) {
        int c = wn * 32 + nt * 8 + tig * 2;
        bc0[nt] = bias[n0 + c];
        bc1[nt] = bias[n0 + c + 1];
    }

#pragma unroll
    for (int mt = 0; mt < 4; mt++) {
#pragma unroll
        for (int half_ = 0; half_ < 2; half_++) {
            int rl = wm * 64 + mt * 16 + g + half_ * 8;
            int r  = rowbase + rl;
            if (r >= rows) continue;
            if (EPI == E_RELU) {
                __half* op = (__half*)CoutV + (size_t)r * ncols + n0;
#pragma unroll
                for (int nt = 0; nt < 4; nt++) {
                    int c = wn * 32 + nt * 8 + tig * 2;
                    float v0 = fmaxf(acc[mt][nt][half_ * 2    ] + bc0[nt], 0.f);
                    float v1 = fmaxf(acc[mt][nt][half_ * 2 + 1] + bc1[nt], 0.f);
                    *(__half2*)&op[c] = __floats2half2_rn(v0, v1);
                }
            } else { // E_POOL
                int rep = (blockIdx.x & (RPL - 1)) * (NC * 256);
                int cm  = idx3[r];
                float* pb = (float*)CoutV + rep + cm * 256 + n0;
#pragma unroll
                for (int nt = 0; nt < 4; nt++) {
                    int c = wn * 32 + nt * 8 + tig * 2;
                    float v0 = fmaxf(acc[mt][nt][half_ * 2    ] + bc0[nt], 0.f);
                    float v1 = fmaxf(acc[mt][nt][half_ * 2 + 1] + bc1[nt], 0.f);
                    red_v2(&pb[c], v0, v1);
                }
            }
        }
    }
}

// ================= fused EL + gate1 + gate2 kernel =================
#define SM_AS 0
#define SM_WS 20480
#define SM_MS 40960
#define SM_WE (SM_MS + 128 * MST * 2)      // 75776: We (8x64 f32)
#define SM_BE (SM_WE + 2048)               // 77824: be (64 f32)
#define SMEM_EL (SM_BE + 256)              // 78080 bytes

__device__ __forceinline__ void el_loadW(__half* Ws, int t, int st,
                                         const __half* __restrict__ Wt, int Kw, int tid) {
    const int k0 = t * 32;
    const int chunk = tid & 3;
#pragma unroll
    for (int l = 0; l < 2; l++) {
        int nrow = (tid >> 2) + l * 64;
        cp16(s2u(&Ws[st * 5120 + nrow * TS + chunk * 8]),
             Wt + (size_t)nrow * Kw + k0 + chunk * 8);
    }
}

__global__ void __launch_bounds__(256)
k_elconv(const __half* __restrict__ h,
         const float* __restrict__ eattr, const float* __restrict__ We,
         const float* __restrict__ be,
         const __half* __restrict__ Welt, const float* __restrict__ bel,
         const __half* __restrict__ Wm1t, const float* __restrict__ bm1,
         const __half* __restrict__ Wm2t, const float* __restrict__ bm2,
         const int* __restrict__ src, const int* __restrict__ dst,
         float* __restrict__ agg, __half* __restrict__ gate2)
{
    extern __shared__ char smem[];
    __half* As = (__half*)(smem + SM_AS);
    __half* Ws = (__half*)(smem + SM_WS);
    __half* Ms = (__half*)(smem + SM_MS);
    float* Wes = (float*)(smem + SM_WE);
    float* bes = (float*)(smem + SM_BE);

    const int tid  = threadIdx.x;
    const int wid  = tid >> 5, lane = tid & 31;
    const int wm   = wid & 1,  wn   = wid >> 1;
    const int g    = lane >> 2, tig = lane & 3;
    const int rowbase = blockIdx.x * 128;     // NEDGE % 128 == 0

    size_t offA[2], offB[2];
    float eat[2][8];
#pragma unroll
    for (int l = 0; l < 2; l++) {
        int grow = rowbase + (tid >> 2) + l * 64;
        offA[l] = (size_t)src[grow] * 128;
        offB[l] = (size_t)dst[grow] * 128;
        const float4* ap = (const float4*)(eattr + (size_t)grow * 8);
        float4 a0 = ap[0], a1 = ap[1];
        eat[l][0] = a0.x; eat[l][1] = a0.y; eat[l][2] = a0.z; eat[l][3] = a0.w;
        eat[l][4] = a1.x; eat[l][5] = a1.y; eat[l][6] = a1.z; eat[l][7] = a1.w;
    }
    // preload We/be
    if (tid < 256) { Wes[tid] = We[tid]; Wes[256 + tid] = We[256 + tid]; }
    if (tid < 64)  bes[tid] = be[tid];
    __syncthreads();

    float acc[4][4][4];
#pragma unroll
    for (int a = 0; a < 4; a++)
#pragma unroll
        for (int b = 0; b < 4; b++)
#pragma unroll
            for (int c = 0; c < 4; c++) acc[a][b][c] = 0.0f;

    const int chunk = tid & 3;

    // ---- phase 1: K=320, 10 k-tiles; tiles 8,9 computed from edge_attr ----
    {
        {
#pragma unroll
            for (int l = 0; l < 2; l++) {
                int row = (tid >> 2) + l * 64;
                cp16(s2u(&As[row * TS + chunk * 8]), h + offA[l] + chunk * 8);
            }
            el_loadW(Ws, 0, 0, Welt, 320, tid);
            cp_commit();
        }
        const int NT = 10;
        for (int t = 0; t < NT; t++) {
            const int s = t & 1;
            if (t + 1 < NT) {
                const int sn = (t + 1) & 1;
                if (t + 1 < 8) {
                    const int gk = (t + 1) * 32 + chunk * 8;
#pragma unroll
                    for (int l = 0; l < 2; l++) {
                        int row = (tid >> 2) + l * 64;
                        const __half* srcp = (gk < 128) ? (h + offA[l] + gk)
                                                        : (h + offB[l] + (gk - 128));
                        cp16(s2u(&As[sn * 5120 + row * TS + chunk * 8]), srcp);
                    }
                } else {
                    // compute ea columns cb..cb+7 for this thread's two rows
                    const int cb = (t + 1 - 8) * 32 + chunk * 8;
#pragma unroll
                    for (int l = 0; l < 2; l++) {
                        int row = (tid >> 2) + l * 64;
                        __half* dstp = &As[sn * 5120 + row * TS + chunk * 8];
#pragma unroll
                        for (int j = 0; j < 8; j += 2) {
                            float s0 = bes[cb + j], s1 = bes[cb + j + 1];
#pragma unroll
                            for (int k = 0; k < 8; k++) {
                                s0 += eat[l][k] * Wes[k * 64 + cb + j];
                                s1 += eat[l][k] * Wes[k * 64 + cb + j + 1];
                            }
                            *(__half2*)&dstp[j] =
                                __floats2half2_rn(fmaxf(s0, 0.f), fmaxf(s1, 0.f));
                        }
                    }
                }
                el_loadW(Ws, t + 1, sn, Welt, 320, tid);
                cp_commit();
                cp_wait<1>();
            } else cp_wait<0>();
            __syncthreads();

            const __half* Ab = As + s * 5120;
            const __half* Wb = Ws + s * 5120;
#pragma unroll
            for (int ks = 0; ks < 2; ks++) {
                const int kb = ks * 16;
                uint32_t af[4][4];
#pragma unroll
                for (int mt = 0; mt < 4; mt++) {
                    int r0 = wm * 64 + mt * 16 + g;
                    af[mt][0] = h2u(&Ab[r0      * TS + kb + 2 * tig]);
                    af[mt][1] = h2u(&Ab[(r0 + 8) * TS + kb + 2 * tig]);
                    af[mt][2] = h2u(&Ab[r0      * TS + kb + 2 * tig + 8]);
                    af[mt][3] = h2u(&Ab[(r0 + 8) * TS + kb + 2 * tig + 8]);
                }
                uint32_t bf[4][2];
#pragma unroll
                for (int nt = 0; nt < 4; nt++) {
                    int nr = wn * 32 + nt * 8 + g;
                    bf[nt][0] = h2u(&Wb[nr * TS + kb + 2 * tig]);
                    bf[nt][1] = h2u(&Wb[nr * TS + kb + 2 * tig + 8]);
                }
#pragma unroll
                for (int mt = 0; mt < 4; mt++)
#pragma unroll
                    for (int nt = 0; nt < 4; nt++)
                        mma_f16(acc[mt][nt], af[mt], bf[nt]);
            }
            __syncthreads();
        }
        // epilogue -> Ms (fp16 mask)
#pragma unroll
        for (int mt = 0; mt < 4; mt++)
#pragma unroll
            for (int half_ = 0; half_ < 2; half_++) {
                int rl = wm * 64 + mt * 16 + g + half_ * 8;
#pragma unroll
                for (int nt = 0; nt < 4; nt++) {
                    int c = wn * 32 + nt * 8 + tig * 2;
                    float v0 = fmaxf(acc[mt][nt][half_ * 2    ] + bel[c    ], 0.f);
                    float v1 = fmaxf(acc[mt][nt][half_ * 2 + 1] + bel[c + 1], 0.f);
                    *(__half2*)&Ms[rl * MST + c] = __floats2half2_rn(v0, v1);
                }
            }
        __syncthreads();
    }

    // ---- phases 2 & 3: Ms @ Wm{1,2}, K=128 ----
#pragma unroll 1
    for (int ph = 0; ph < 2; ph++) {
        const __half* Wm = (ph == 0) ? Wm1t : Wm2t;
        const float*  bm = (ph == 0) ? bm1 : bm2;

#pragma unroll
        for (int a = 0; a < 4; a++)
#pragma unroll
            for (int b = 0; b < 4; b++)
#pragma unroll
                for (int c = 0; c < 4; c++) acc[a][b][c] = 0.0f;

        el_loadW(Ws, 0, 0, Wm, 128, tid);
        cp_commit();
        for (int t = 0; t < 4; t++) {
            const int s = t & 1;
            if (t + 1 < 4) {
                el_loadW(Ws, t + 1, (t + 1) & 1, Wm, 128, tid);
                cp_commit();
                cp_wait<1>();
            } else cp_wait<0>();
            __syncthreads();

            const __half* Wb = Ws + s * 5120;
#pragma unroll
            for (int ks = 0; ks < 2; ks++) {
                const int kbM = t * 32 + ks * 16;
                const int kbW = ks * 16;
                uint32_t af[4][4];
#pragma unroll
                for (int mt = 0; mt < 4; mt++) {
                    int r0 = wm * 64 + mt * 16 + g;
                    af[mt][0] = h2u(&Ms[r0      * MST + kbM + 2 * tig]);
                    af[mt][1] = h2u(&Ms[(r0 + 8) * MST + kbM + 2 * tig]);
                    af[mt][2] = h2u(&Ms[r0      * MST + kbM + 2 * tig + 8]);
                    af[mt][3] = h2u(&Ms[(r0 + 8) * MST + kbM + 2 * tig + 8]);
                }
                uint32_t bf[4][2];
#pragma unroll
                for (int nt = 0; nt < 4; nt++) {
                    int nr = wn * 32 + nt * 8 + g;
                    bf[nt][0] = h2u(&Wb[nr * TS + kbW + 2 * tig]);
                    bf[nt][1] = h2u(&Wb[nr * TS + kbW + 2 * tig + 8]);
                }
#pragma unroll
                for (int mt = 0; mt < 4; mt++)
#pragma unroll
                    for (int nt = 0; nt < 4; nt++)
                        mma_f16(acc[mt][nt], af[mt], bf[nt]);
            }
            __syncthreads();
        }

        if (ph == 0) {
#pragma unroll
            for (int mt = 0; mt < 4; mt++)
#pragma unroll
                for (int half_ = 0; half_ < 2; half_++) {
                    int rl = wm * 64 + mt * 16 + g + half_ * 8;
                    int r  = rowbase + rl;
                    int sI = src[r], dI = dst[r];
                    const __half* hs = h + (size_t)sI * 128;
                    float*        ag = agg + (size_t)dI * 128;
#pragma unroll
                    for (int nt = 0; nt < 4; nt++) {
                        int c = wn * 32 + nt * 8 + tig * 2;
                        float z0 = acc[mt][nt][half_ * 2    ] + bm[c];
                        float z1 = acc[mt][nt][half_ * 2 + 1] + bm[c + 1];
                        float g0 = 1.0f / (1.0f + __expf(-z0));
                        float g1 = 1.0f / (1.0f + __expf(-z1));
                        float2 hv = __half22float2(*(const __half2*)&hs[c]);
                        red_v2(&ag[c], g0 * hv.x, g1 * hv.y);
                    }
                }
        } else {
#pragma unroll
            for (int mt = 0; mt < 4; mt++)
#pragma unroll
                for (int half_ = 0; half_ < 2; half_++) {
                    int rl = wm * 64 + mt * 16 + g + half_ * 8;
#pragma unroll
                    for (int nt = 0; nt < 4; nt++) {
                        int c = wn * 32 + nt * 8 + tig * 2;
                        float z0 = acc[mt][nt][half_ * 2    ] + bm[c];
                        float z1 = acc[mt][nt][half_ * 2 + 1] + bm[c + 1];
                        float g0 = 1.0f / (1.0f + __expf(-z0));
                        float g1 = 1.0f / (1.0f + __expf(-z1));
                        *(__half2*)&Ms[rl * MST + c] = __floats2half2_rn(g0, g1);
                    }
                }
            __syncthreads();
            __half* gout = gate2 + (size_t)rowbase * 128;
            for (int i = tid; i < 2048; i += 256) {
                int row = i >> 4, part = i & 15;
                float4 v = *(float4*)&Ms[row * MST + part * 8];
                *(float4*)&gout[row * 128 + part * 8] = v;
            }
        }
    }
}

// ---------------- conv2 scatter ----------------
__global__ void __launch_bounds__(256) k_conv2(const int* __restrict__ src,
                                               const int* __restrict__ dst) {
    int wid = threadIdx.x >> 5, lane = threadIdx.x & 31;
    int e = blockIdx.x * 8 + wid;
    int sI = src[e], dI = dst[e];
    const __half* gp = g_g2 + (size_t)e * 128 + lane * 4;
    const __half* hp = g_h2 + (size_t)sI * 128 + lane * 4;
    float2 ga = __half22float2(*(const __half2*)&gp[0]);
    float2 gb = __half22float2(*(const __half2*)&gp[2]);
    float2 ha = __half22float2(*(const __half2*)&hp[0]);
    float2 hb = __half22float2(*(const __half2*)&hp[2]);
    float* ag = g_agg2 + (size_t)dI * 128 + lane * 4;
    red_v2(ag,     ga.x * ha.x, ga.y * ha.y);
    red_v2(ag + 2, gb.x * hb.x, gb.y * hb.y);
}

// ---------------- pool reduce ----------------
__global__ void k_poolreduce(const float* __restrict__ pool, float* __restrict__ sOut) {
    int i = blockIdx.x * 256 + threadIdx.x;
    int c = i >> 8;
    float s = 0.f;
#pragma unroll
    for (int r = 0; r < RPL; r++) s += pool[r * NC * 256 + i];
    sOut[i] = s * g_invcnt[c];
}

// ---------------- final MLP ----------------
__global__ void k_final(const float* __restrict__ Wl1, const float* __restrict__ bl1,
                        const float* __restrict__ Wl2, const float* __restrict__ bl2,
                        float* __restrict__ out) {
    __shared__ float sv[256];
    __shared__ float red[256];
    int c = blockIdx.x, j = threadIdx.x;
    sv[j] = g_s1[c * 256 + j] + g_s2[c * 256 + j];
    __syncthreads();
    float a = bl1[j];
    for (int k = 0; k < 256; k++)
        a += sv[k] * (Wl1[k * 256 + j] + Wl1[(256 + k) * 256 + j]);
    red[j] = fmaxf(a, 0.f) * Wl2[j];
    __syncthreads();
    for (int s = 128; s > 0; s >>= 1) {
        if (j < s) red[j] += red[j + s];
        __syncthreads();
    }
    if (j == 0) out[c] = red[0] + bl2[0];
}

// ---------------- host launch ----------------
extern "C" void kernel_launch(void* const* d_in, const int* in_sizes, int n_in,
                              void* d_out, int out_size) {
    (void)in_sizes; (void)n_in; (void)out_size;
    const float* x     = (const float*)d_in[0];
    const float* eattr = (const float*)d_in[1];
    const int*   ei    = (const int*)d_in[2];
    const int*   comm  = (const int*)d_in[3];
    const int*   pe    = (const int*)d_in[4];
    const float* We  = (const float*)d_in[5],  * be  = (const float*)d_in[6];
    const float* W1  = (const float*)d_in[7],  * b1  = (const float*)d_in[8];
    const float* W2  = (const float*)d_in[9],  * b2  = (const float*)d_in[10];
    const float* W3  = (const float*)d_in[11], * b3  = (const float*)d_in[12];
    const float* Wel = (const float*)d_in[13], * bel = (const float*)d_in[14];
    const float* Wm1 = (const float*)d_in[15], * bm1 = (const float*)d_in[16];
    const float* Wc1 = (const float*)d_in[17], * bc1 = (const float*)d_in[18];
    const float* Wm2 = (const float*)d_in[19], * bm2 = (const float*)d_in[20];
    const float* Wc2 = (const float*)d_in[21], * bc2 = (const float*)d_in[22];
    const float* Wam = (const float*)d_in[23], * bam = (const float*)d_in[24];
    const float* Wl1 = (const float*)d_in[25], * bl1 = (const float*)d_in[26];
    const float* Wl2 = (const float*)d_in[27], * bl2 = (const float*)d_in[28];

    const int* src = ei, * dst = ei + NEDGE;
    const int* pi  = pe, * pj  = pe + NP;

    __half *ht_, *h_, *h2_, *h3_, *aggh_, *aggh2_, *g2_, *wh_;
    float *agg_, *agg2_, *pool1_, *pool2_, *s1_, *s2_;
    int *deg_, *cnt_;
    cudaGetSymbolAddress((void**)&ht_,    g_ht);
    cudaGetSymbolAddress((void**)&h_,     g_h);
    cudaGetSymbolAddress((void**)&h2_,    g_h2);
    cudaGetSymbolAddress((void**)&h3_,    g_h3);
    cudaGetSymbolAddress((void**)&aggh_,  g_aggh);
    cudaGetSymbolAddress((void**)&aggh2_, g_aggh2);
    cudaGetSymbolAddress((void**)&agg_,   g_agg);
    cudaGetSymbolAddress((void**)&agg2_,  g_agg2);
    cudaGetSymbolAddress((void**)&pool1_, g_pool1);
    cudaGetSymbolAddress((void**)&pool2_, g_pool2);
    cudaGetSymbolAddress((void**)&s1_,    g_s1);
    cudaGetSymbolAddress((void**)&s2_,    g_s2);
    cudaGetSymbolAddress((void**)&wh_,    g_wh);
    cudaGetSymbolAddress((void**)&g2_,    g_g2);
    cudaGetSymbolAddress((void**)&deg_,   g_deg);
    cudaGetSymbolAddress((void**)&cnt_,   g_cnt);

    cudaFuncSetAttribute(k_elconv, cudaFuncAttributeMaxDynamicSharedMemorySize, SMEM_EL);

    // side stream + events (created on each host execution of kernel_launch;
    // only the correctness run and the capture run execute host code)
    cudaStream_t sB;
    cudaStreamCreateWithFlags(&sB, cudaStreamNonBlocking);
    cudaEvent_t evF, evJ;
    cudaEventCreateWithFlags(&evF, cudaEventDisableTiming);
    cudaEventCreateWithFlags(&evJ, cudaEventDisableTiming);

    cudaMemsetAsync(deg_,   0, NN * sizeof(int));
    cudaMemsetAsync(cnt_,   0, NC * sizeof(int));
    cudaMemsetAsync(agg_,   0, (size_t)NN * 128 * sizeof(float));
    cudaMemsetAsync(agg2_,  0, (size_t)NN * 128 * sizeof(float));
    cudaMemsetAsync(pool1_, 0, (size_t)RPL * NC * 256 * sizeof(float));
    cudaMemsetAsync(pool2_, 0, (size_t)RPL * NC * 256 * sizeof(float));

    dim3 blk(256);
    const int gN = (NN + 127) / 128;
    const int gE = NEDGE / 128;
    const int gP = NP / 128;

    // kernel order on default stream: transAll(0) ht(1) deg(2) inv(3) h-gemm(4) elconv(5)
    k_transAll<<<736, 256>>>(W3, Wel, Wm1, Wc1, Wm2, Wc2, Wam);
    k_ht<<<NN, 128>>>(x, W1, b1, W2, b2);
    k_deg<<<(NEDGE + 255) / 256, 256>>>(dst, comm);
    k_inv<<<(NN + 255) / 256, 256>>>();

    gemm_tc<M_PLAIN, E_RELU, 128><<<dim3(gN, 1), blk>>>(ht_, wh_ + OW3, b3, h_,
        nullptr, nullptr, nullptr, NN, 128);

    k_elconv<<<gE, blk, SMEM_EL>>>(h_, eattr, We, be,
                                   wh_ + OWEL, bel, wh_ + OWM1, bm1, wh_ + OWM2, bm2,
                                   src, dst, agg_, g2_);
    k_scale<<<(NN * 128 + 255) / 256, 256>>>(agg_, aggh_);
    gemm_tc<M_PLAIN, E_RELU, 128><<<dim3(gN, 1), blk>>>(aggh_, wh_ + OWC1, bc1, h2_,
        nullptr, nullptr, nullptr, NN, 128);

    // ---- fork: pool1 chain on side stream, conv2 chain on default ----
    cudaEventRecord(evF, 0);
    cudaStreamWaitEvent(sB, evF, 0);
    gemm_tc<M_PAIR, E_POOL, 256><<<dim3(gP, 2), blk, 0, sB>>>(h2_, wh_ + OWAM, bam, pool1_,
        pi, pj, comm, NP, 256);
    k_poolreduce<<<NC, 256, 0, sB>>>(pool1_, s1_);
    cudaEventRecord(evJ, sB);

    k_conv2<<<NEDGE / 8, 256>>>(src, dst);
    k_scale<<<(NN * 128 + 255) / 256, 256>>>(agg2_, aggh2_);
    gemm_tc<M_PLAIN, E_RELU, 128><<<dim3(gN, 1), blk>>>(aggh2_, wh_ + OWC2, bc2, h3_,
        nullptr, nullptr, nullptr, NN, 128);
    gemm_tc<M_PAIR, E_POOL, 256><<<dim3(gP, 2), blk>>>(h3_, wh_ + OWAM, bam, pool2_,
        pi, pj, comm, NP, 256);
    k_poolreduce<<<NC, 256>>>(pool2_, s2_);

    cudaStreamWaitEvent(0, evJ, 0);
    k_final<<<NC, 256>>>(Wl1, bl1, Wl2, bl2, (float*)d_out);
}

// round 12
// speedup vs baseline: 4.1738x; 1.3490x over previous
#include <cuda_runtime.h>
#include <cuda_fp16.h>
#include <math.h>
#include <stdint.h>

#define NN     50000
#define NEDGE  800000
#define NP     400000
#define NC     1000
#define RPL    32

// ---------------- scratch ----------------
__device__ __half  g_ht  [NN * 128];
__device__ __half  g_h   [NN * 128];
__device__ __half  g_h2  [NN * 128];
__device__ __half  g_h3  [NN * 128];
__device__ float   g_agg [NN * 128];
__device__ float   g_agg2[NN * 128];
__device__ __half  g_aggh [NN * 128];
__device__ __half  g_aggh2[NN * 128];
__device__ __half  g_g2  [NEDGE * 128];
__device__ float   g_invdeg[NN];
__device__ int     g_deg [NN];
__device__ int     g_cnt [NC];
__device__ float   g_invcnt[NC];
__device__ float   g_pool1[RPL * NC * 256];
__device__ float   g_pool2[RPL * NC * 256];
__device__ float   g_s1  [NC * 256];
__device__ float   g_s2  [NC * 256];
__device__ __half  g_wh  [188416];

#define OW3   0
#define OWEL  16384
#define OWM1  57344
#define OWC1  73728
#define OWM2  90112
#define OWC2  106496
#define OWAM  122880

#define TS  40
#define MST 136

// ---------------- helpers ----------------
__device__ __forceinline__ void mma_f16(float* d, const uint32_t* a, const uint32_t* b) {
    asm volatile(
        "mma.sync.aligned.m16n8k16.row.col.f32.f16.f16.f32 "
        "{%0,%1,%2,%3}, {%4,%5,%6,%7}, {%8,%9}, {%0,%1,%2,%3};\n"
        : "+f"(d[0]), "+f"(d[1]), "+f"(d[2]), "+f"(d[3])
        : "r"(a[0]), "r"(a[1]), "r"(a[2]), "r"(a[3]), "r"(b[0]), "r"(b[1]));
}
__device__ __forceinline__ void ldsm_x4(uint32_t& r0, uint32_t& r1, uint32_t& r2,
                                        uint32_t& r3, uint32_t addr) {
    asm volatile("ldmatrix.sync.aligned.m8n8.x4.shared.b16 {%0,%1,%2,%3}, [%4];"
                 : "=r"(r0), "=r"(r1), "=r"(r2), "=r"(r3) : "r"(addr));
}
__device__ __forceinline__ void red_v2(float* p, float v0, float v1) {
    asm volatile("red.global.add.v2.f32 [%0], {%1, %2};"
                 :: "l"(p), "f"(v0), "f"(v1) : "memory");
}
__device__ __forceinline__ uint32_t s2u(const void* p) {
    return (uint32_t)__cvta_generic_to_shared(p);
}
__device__ __forceinline__ void cp16(uint32_t dst, const void* src) {
    asm volatile("cp.async.ca.shared.global [%0], [%1], 16;" :: "r"(dst), "l"(src));
}
__device__ __forceinline__ void cp_commit() { asm volatile("cp.async.commit_group;"); }
template<int N> __device__ __forceinline__ void cp_wait() {
    asm volatile("cp.async.wait_group %0;" :: "n"(N));
}

// ---------------- small kernels ----------------
__global__ void k_deg(const int* __restrict__ dst, const int* __restrict__ comm) {
    int i = blockIdx.x * blockDim.x + threadIdx.x;
    if (i < NEDGE) atomicAdd(&g_deg[dst[i]], 1);
    if (i < NP)    atomicAdd(&g_cnt[comm[i]], 1);
}
__global__ void k_inv() {
    int i = blockIdx.x * blockDim.x + threadIdx.x;
    if (i < NN) g_invdeg[i] = 1.0f / (float)max(g_deg[i], 1);
    if (i < NC) g_invcnt[i] = 1.0f / (float)max(g_cnt[i], 1);
}
__global__ void k_transAll(const float* __restrict__ W3,  const float* __restrict__ Wel,
                           const float* __restrict__ Wm1, const float* __restrict__ Wc1,
                           const float* __restrict__ Wm2, const float* __restrict__ Wc2,
                           const float* __restrict__ Wam) {
    int b = blockIdx.x;
    const float* src; __half* dst; int K, N, base;
    if      (b < 64)  { src = W3;  dst = g_wh + OW3;  K = 128; N = 128; base = b; }
    else if (b < 224) { src = Wel; dst = g_wh + OWEL; K = 320; N = 128; base = b - 64; }
    else if (b < 288) { src = Wm1; dst = g_wh + OWM1; K = 128; N = 128; base = b - 224; }
    else if (b < 352) { src = Wc1; dst = g_wh + OWC1; K = 128; N = 128; base = b - 288; }
    else if (b < 416) { src = Wm2; dst = g_wh + OWM2; K = 128; N = 128; base = b - 352; }
    else if (b < 480) { src = Wc2; dst = g_wh + OWC2; K = 128; N = 128; base = b - 416; }
    else              { src = Wam; dst = g_wh + OWAM; K = 256; N = 256; base = b - 480; }
    int i = base * 256 + threadIdx.x;
    int n = i / K, k = i % K;
    dst[i] = __float2half(src[k * N + n]);
}
__global__ void k_scale(const float* __restrict__ in, __half* __restrict__ out) {
    int i = blockIdx.x * 256 + threadIdx.x;     // NN*32 threads, 4 elems each
    if (i >= NN * 32) return;
    float4 v = *(const float4*)(in + i * 4);
    float sc = g_invdeg[i >> 5];
    __half2 a = __floats2half2_rn(v.x * sc, v.y * sc);
    __half2 b = __floats2half2_rn(v.z * sc, v.w * sc);
    *(__half2*)(out + i * 4)     = a;
    *(__half2*)(out + i * 4 + 2) = b;
}
__global__ void k_ht(const float* __restrict__ x,
                     const float* __restrict__ W1, const float* __restrict__ b1,
                     const float* __restrict__ W2, const float* __restrict__ b2) {
    int n = blockIdx.x;
    int c = threadIdx.x;
    const float* xr = x + n * 20;
    float s;
    if (c < 64) {
        s = b1[c];
#pragma unroll
        for (int k = 0; k < 8; k++) s += xr[k] * W1[k * 64 + c];
    } else {
        int cc = c - 64;
        s = b2[cc];
#pragma unroll
        for (int k = 0; k < 12; k++) s += xr[8 + k] * W2[k * 64 + cc];
    }
    g_ht[n * 128 + c] = __float2half(fmaxf(s, 0.0f));
}

// ================= generic fp16 gather-GEMM (ldmatrix mainloop) =================
enum { M_PLAIN = 0, M_PAIR = 3 };
enum { E_RELU = 0, E_POOL = 2 };

template<int MODE, int K>
__device__ __forceinline__ void load_stage(
    __half* As, __half* Ws, int t, int st,
    const __half* __restrict__ A, const __half* __restrict__ Wt,
    const size_t* offA, const size_t* offB, int tid, int n0)
{
    const int k0 = t * 32;
    const int chunk = tid & 3;
    const int gk = k0 + chunk * 8;
#pragma unroll
    for (int l = 0; l < 2; l++) {
        int row = (tid >> 2) + l * 64;
        uint32_t dst = s2u(&As[st * 5120 + row * TS + chunk * 8]);
        const __half* src;
        if (MODE == M_PLAIN) src = A + offA[l] + gk;
        else src = (gk < 128) ? (A + offA[l] + gk) : (A + offB[l] + (gk - 128));
        cp16(dst, src);
    }
#pragma unroll
    for (int l = 0; l < 2; l++) {
        int nrow = (tid >> 2) + l * 64;
        cp16(s2u(&Ws[st * 5120 + nrow * TS + chunk * 8]),
             Wt + (size_t)(n0 + nrow) * K + gk);
    }
}

template<int MODE, int EPI, int K>
__global__ void __launch_bounds__(256)
gemm_tc(const __half* __restrict__ A, const __half* __restrict__ Wt,
        const float* __restrict__ bias, void* __restrict__ CoutV,
        const int* __restrict__ idx1, const int* __restrict__ idx2,
        const int* __restrict__ idx3, int rows, int ncols)
{
    __shared__ __half As[2 * 5120];
    __shared__ __half Ws[2 * 5120];

    const int tid  = threadIdx.x;
    const int wid  = tid >> 5, lane = tid & 31;
    const int wm   = wid & 1,  wn   = wid >> 1;
    const int g    = lane >> 2, tig = lane & 3;
    const int rowbase = blockIdx.x * 128;
    const int n0      = blockIdx.y * 128;

    const int laneA_row = (lane & 7) + ((lane >> 3) & 1) * 8;
    const int laneA_col = (lane >> 4) * 8;
    const int laneB_row = lane & 7;
    const int laneB_nt  = (lane >> 4);
    const int laneB_kh  = ((lane >> 3) & 1) * 8;

    size_t offA[2], offB[2];
#pragma unroll
    for (int l = 0; l < 2; l++) {
        int grow = rowbase + (tid >> 2) + l * 64;
        int gc = (grow < rows) ? grow : (rows - 1);
        if (MODE == M_PLAIN) { offA[l] = (size_t)gc * K; offB[l] = 0; }
        else { offA[l] = (size_t)idx1[gc] * 128; offB[l] = (size_t)idx2[gc] * 128; }
    }

    float acc[4][4][4];
#pragma unroll
    for (int a = 0; a < 4; a++)
#pragma unroll
        for (int b = 0; b < 4; b++)
#pragma unroll
            for (int c = 0; c < 4; c++) acc[a][b][c] = 0.0f;

    const int NT = K / 32;
    load_stage<MODE, K>(As, Ws, 0, 0, A, Wt, offA, offB, tid, n0);
    cp_commit();

    for (int t = 0; t < NT; t++) {
        const int s = t & 1;
        if (t + 1 < NT) {
            load_stage<MODE, K>(As, Ws, t + 1, (t + 1) & 1, A, Wt, offA, offB, tid, n0);
            cp_commit();
            cp_wait<1>();
        } else cp_wait<0>();
        __syncthreads();

        const __half* Ab = As + s * 5120;
        const __half* Wb = Ws + s * 5120;
#pragma unroll
        for (int ks = 0; ks < 2; ks++) {
            const int kb = ks * 16;
            uint32_t af[4][4];
#pragma unroll
            for (int mt = 0; mt < 4; mt++)
                ldsm_x4(af[mt][0], af[mt][1], af[mt][2], af[mt][3],
                        s2u(&Ab[(wm * 64 + mt * 16 + laneA_row) * TS + kb + laneA_col]));
            uint32_t bf[4][2];
#pragma unroll
            for (int p = 0; p < 2; p++) {
                int nr = wn * 32 + (p * 2 + laneB_nt) * 8 + laneB_row;
                ldsm_x4(bf[p * 2][0], bf[p * 2][1], bf[p * 2 + 1][0], bf[p * 2 + 1][1],
                        s2u(&Wb[nr * TS + kb + laneB_kh]));
            }
#pragma unroll
            for (int mt = 0; mt < 4; mt++)
#pragma unroll
                for (int nt = 0; nt < 4; nt++)
                    mma_f16(acc[mt][nt], af[mt], bf[nt]);
        }
        __syncthreads();
    }

    float bc0[4], bc1[4];
#pragma unroll
    for (int nt = 0; nt < 4; nt++) {
        int c = wn * 32 + nt * 8 + tig * 2;
        bc0[nt] = bias[n0 + c];
        bc1[nt] = bias[n0 + c + 1];
    }

#pragma unroll
    for (int mt = 0; mt < 4; mt++) {
#pragma unroll
        for (int half_ = 0; half_ < 2; half_++) {
            int rl = wm * 64 + mt * 16 + g + half_ * 8;
            int r  = rowbase + rl;
            if (r >= rows) continue;
            if (EPI == E_RELU) {
                __half* op = (__half*)CoutV + (size_t)r * ncols + n0;
#pragma unroll
                for (int nt = 0; nt < 4; nt++) {
                    int c = wn * 32 + nt * 8 + tig * 2;
                    float v0 = fmaxf(acc[mt][nt][half_ * 2    ] + bc0[nt], 0.f);
                    float v1 = fmaxf(acc[mt][nt][half_ * 2 + 1] + bc1[nt], 0.f);
                    *(__half2*)&op[c] = __floats2half2_rn(v0, v1);
                }
            } else { // E_POOL
                int rep = (blockIdx.x & (RPL - 1)) * (NC * 256);
                int cm  = idx3[r];
                float* pb = (float*)CoutV + rep + cm * 256 + n0;
#pragma unroll
                for (int nt = 0; nt < 4; nt++) {
                    int c = wn * 32 + nt * 8 + tig * 2;
                    float v0 = fmaxf(acc[mt][nt][half_ * 2    ] + bc0[nt], 0.f);
                    float v1 = fmaxf(acc[mt][nt][half_ * 2 + 1] + bc1[nt], 0.f);
                    red_v2(&pb[c], v0, v1);
                }
            }
        }
    }
}

// ================= fused EL + gate1 + gate2 kernel =================
#define SM_AS 0
#define SM_WS 20480
#define SM_MS 40960
#define SM_WE (SM_MS + 128 * MST * 2)
#define SM_BE (SM_WE + 2048)
#define SMEM_EL (SM_BE + 256)

__device__ __forceinline__ void el_loadW(__half* Ws, int t, int st,
                                         const __half* __restrict__ Wt, int Kw, int tid) {
    const int k0 = t * 32;
    const int chunk = tid & 3;
#pragma unroll
    for (int l = 0; l < 2; l++) {
        int nrow = (tid >> 2) + l * 64;
        cp16(s2u(&Ws[st * 5120 + nrow * TS + chunk * 8]),
             Wt + (size_t)nrow * Kw + k0 + chunk * 8);
    }
}

__global__ void __launch_bounds__(256)
k_elconv(const __half* __restrict__ h,
         const float* __restrict__ eattr, const float* __restrict__ We,
         const float* __restrict__ be,
         const __half* __restrict__ Welt, const float* __restrict__ bel,
         const __half* __restrict__ Wm1t, const float* __restrict__ bm1,
         const __half* __restrict__ Wm2t, const float* __restrict__ bm2,
         const int* __restrict__ src, const int* __restrict__ dst,
         float* __restrict__ agg, __half* __restrict__ gate2)
{
    extern __shared__ char smem[];
    __half* As = (__half*)(smem + SM_AS);
    __half* Ws = (__half*)(smem + SM_WS);
    __half* Ms = (__half*)(smem + SM_MS);
    float* Wes = (float*)(smem + SM_WE);
    float* bes = (float*)(smem + SM_BE);

    const int tid  = threadIdx.x;
    const int wid  = tid >> 5, lane = tid & 31;
    const int wm   = wid & 1,  wn   = wid >> 1;
    const int g    = lane >> 2, tig = lane & 3;
    const int rowbase = blockIdx.x * 128;

    const int laneA_row = (lane & 7) + ((lane >> 3) & 1) * 8;
    const int laneA_col = (lane >> 4) * 8;
    const int laneB_row = lane & 7;
    const int laneB_nt  = (lane >> 4);
    const int laneB_kh  = ((lane >> 3) & 1) * 8;

    size_t offA[2], offB[2];
    float eat[2][8];
#pragma unroll
    for (int l = 0; l < 2; l++) {
        int grow = rowbase + (tid >> 2) + l * 64;
        offA[l] = (size_t)src[grow] * 128;
        offB[l] = (size_t)dst[grow] * 128;
        const float4* ap = (const float4*)(eattr + (size_t)grow * 8);
        float4 a0 = ap[0], a1 = ap[1];
        eat[l][0] = a0.x; eat[l][1] = a0.y; eat[l][2] = a0.z; eat[l][3] = a0.w;
        eat[l][4] = a1.x; eat[l][5] = a1.y; eat[l][6] = a1.z; eat[l][7] = a1.w;
    }
    if (tid < 256) { Wes[tid] = We[tid]; Wes[256 + tid] = We[256 + tid]; }
    if (tid < 64)  bes[tid] = be[tid];
    __syncthreads();

    float acc[4][4][4];
#pragma unroll
    for (int a = 0; a < 4; a++)
#pragma unroll
        for (int b = 0; b < 4; b++)
#pragma unroll
            for (int c = 0; c < 4; c++) acc[a][b][c] = 0.0f;

    const int chunk = tid & 3;

    // ---- phase 1: K=320, 10 k-tiles; tiles 8,9 computed from edge_attr ----
    {
        {
#pragma unroll
            for (int l = 0; l < 2; l++) {
                int row = (tid >> 2) + l * 64;
                cp16(s2u(&As[row * TS + chunk * 8]), h + offA[l] + chunk * 8);
            }
            el_loadW(Ws, 0, 0, Welt, 320, tid);
            cp_commit();
        }
        const int NT = 10;
        for (int t = 0; t < NT; t++) {
            const int s = t & 1;
            if (t + 1 < NT) {
                const int sn = (t + 1) & 1;
                if (t + 1 < 8) {
                    const int gk = (t + 1) * 32 + chunk * 8;
#pragma unroll
                    for (int l = 0; l < 2; l++) {
                        int row = (tid >> 2) + l * 64;
                        const __half* srcp = (gk < 128) ? (h + offA[l] + gk)
                                                        : (h + offB[l] + (gk - 128));
                        cp16(s2u(&As[sn * 5120 + row * TS + chunk * 8]), srcp);
                    }
                } else {
                    const int cb = (t + 1 - 8) * 32 + chunk * 8;
#pragma unroll
                    for (int l = 0; l < 2; l++) {
                        int row = (tid >> 2) + l * 64;
                        __half* dstp = &As[sn * 5120 + row * TS + chunk * 8];
#pragma unroll
                        for (int j = 0; j < 8; j += 2) {
                            float s0 = bes[cb + j], s1 = bes[cb + j + 1];
#pragma unroll
                            for (int k = 0; k < 8; k++) {
                                s0 += eat[l][k] * Wes[k * 64 + cb + j];
                                s1 += eat[l][k] * Wes[k * 64 + cb + j + 1];
                            }
                            *(__half2*)&dstp[j] =
                                __floats2half2_rn(fmaxf(s0, 0.f), fmaxf(s1, 0.f));
                        }
                    }
                }
                el_loadW(Ws, t + 1, sn, Welt, 320, tid);
                cp_commit();
                cp_wait<1>();
            } else cp_wait<0>();
            __syncthreads();

            const __half* Ab = As + s * 5120;
            const __half* Wb = Ws + s * 5120;
#pragma unroll
            for (int ks = 0; ks < 2; ks++) {
                const int kb = ks * 16;
                uint32_t af[4][4];
#pragma unroll
                for (int mt = 0; mt < 4; mt++)
                    ldsm_x4(af[mt][0], af[mt][1], af[mt][2], af[mt][3],
                            s2u(&Ab[(wm * 64 + mt * 16 + laneA_row) * TS + kb + laneA_col]));
                uint32_t bf[4][2];
#pragma unroll
                for (int p = 0; p < 2; p++) {
                    int nr = wn * 32 + (p * 2 + laneB_nt) * 8 + laneB_row;
                    ldsm_x4(bf[p * 2][0], bf[p * 2][1], bf[p * 2 + 1][0], bf[p * 2 + 1][1],
                            s2u(&Wb[nr * TS + kb + laneB_kh]));
                }
#pragma unroll
                for (int mt = 0; mt < 4; mt++)
#pragma unroll
                    for (int nt = 0; nt < 4; nt++)
                        mma_f16(acc[mt][nt], af[mt], bf[nt]);
            }
            __syncthreads();
        }
#pragma unroll
        for (int mt = 0; mt < 4; mt++)
#pragma unroll
            for (int half_ = 0; half_ < 2; half_++) {
                int rl = wm * 64 + mt * 16 + g + half_ * 8;
#pragma unroll
                for (int nt = 0; nt < 4; nt++) {
                    int c = wn * 32 + nt * 8 + tig * 2;
                    float v0 = fmaxf(acc[mt][nt][half_ * 2    ] + bel[c    ], 0.f);
                    float v1 = fmaxf(acc[mt][nt][half_ * 2 + 1] + bel[c + 1], 0.f);
                    *(__half2*)&Ms[rl * MST + c] = __floats2half2_rn(v0, v1);
                }
            }
        __syncthreads();
    }

    // ---- phases 2 & 3 ----
#pragma unroll 1
    for (int ph = 0; ph < 2; ph++) {
        const __half* Wm = (ph == 0) ? Wm1t : Wm2t;
        const float*  bm = (ph == 0) ? bm1 : bm2;

#pragma unroll
        for (int a = 0; a < 4; a++)
#pragma unroll
            for (int b = 0; b < 4; b++)
#pragma unroll
                for (int c = 0; c < 4; c++) acc[a][b][c] = 0.0f;

        el_loadW(Ws, 0, 0, Wm, 128, tid);
        cp_commit();
        for (int t = 0; t < 4; t++) {
            const int s = t & 1;
            if (t + 1 < 4) {
                el_loadW(Ws, t + 1, (t + 1) & 1, Wm, 128, tid);
                cp_commit();
                cp_wait<1>();
            } else cp_wait<0>();
            __syncthreads();

            const __half* Wb = Ws + s * 5120;
#pragma unroll
            for (int ks = 0; ks < 2; ks++) {
                const int kbM = t * 32 + ks * 16;
                const int kbW = ks * 16;
                uint32_t af[4][4];
#pragma unroll
                for (int mt = 0; mt < 4; mt++)
                    ldsm_x4(af[mt][0], af[mt][1], af[mt][2], af[mt][3],
                            s2u(&Ms[(wm * 64 + mt * 16 + laneA_row) * MST + kbM + laneA_col]));
                uint32_t bf[4][2];
#pragma unroll
                for (int p = 0; p < 2; p++) {
                    int nr = wn * 32 + (p * 2 + laneB_nt) * 8 + laneB_row;
                    ldsm_x4(bf[p * 2][0], bf[p * 2][1], bf[p * 2 + 1][0], bf[p * 2 + 1][1],
                            s2u(&Wb[nr * TS + kbW + laneB_kh]));
                }
#pragma unroll
                for (int mt = 0; mt < 4; mt++)
#pragma unroll
                    for (int nt = 0; nt < 4; nt++)
                        mma_f16(acc[mt][nt], af[mt], bf[nt]);
            }
            __syncthreads();
        }

        if (ph == 0) {
#pragma unroll
            for (int mt = 0; mt < 4; mt++)
#pragma unroll
                for (int half_ = 0; half_ < 2; half_++) {
                    int rl = wm * 64 + mt * 16 + g + half_ * 8;
                    int r  = rowbase + rl;
                    int sI = src[r], dI = dst[r];
                    const __half* hs = h + (size_t)sI * 128;
                    float*        ag = agg + (size_t)dI * 128;
#pragma unroll
                    for (int nt = 0; nt < 4; nt++) {
                        int c = wn * 32 + nt * 8 + tig * 2;
                        float z0 = acc[mt][nt][half_ * 2    ] + bm[c];
                        float z1 = acc[mt][nt][half_ * 2 + 1] + bm[c + 1];
                        float g0 = 1.0f / (1.0f + __expf(-z0));
                        float g1 = 1.0f / (1.0f + __expf(-z1));
                        float2 hv = __half22float2(*(const __half2*)&hs[c]);
                        red_v2(&ag[c], g0 * hv.x, g1 * hv.y);
                    }
                }
        } else {
#pragma unroll
            for (int mt = 0; mt < 4; mt++)
#pragma unroll
                for (int half_ = 0; half_ < 2; half_++) {
                    int rl = wm * 64 + mt * 16 + g + half_ * 8;
#pragma unroll
                    for (int nt = 0; nt < 4; nt++) {
                        int c = wn * 32 + nt * 8 + tig * 2;
                        float z0 = acc[mt][nt][half_ * 2    ] + bm[c];
                        float z1 = acc[mt][nt][half_ * 2 + 1] + bm[c + 1];
                        float g0 = 1.0f / (1.0f + __expf(-z0));
                        float g1 = 1.0f / (1.0f + __expf(-z1));
                        *(__half2*)&Ms[rl * MST + c] = __floats2half2_rn(g0, g1);
                    }
                }
            __syncthreads();
            __half* gout = gate2 + (size_t)rowbase * 128;
            for (int i = tid; i < 2048; i += 256) {
                int row = i >> 4, part = i & 15;
                float4 v = *(float4*)&Ms[row * MST + part * 8];
                *(float4*)&gout[row * 128 + part * 8] = v;
            }
        }
    }
}

// ---------------- conv2 scatter ----------------
__global__ void __launch_bounds__(256) k_conv2(const int* __restrict__ src,
                                               const int* __restrict__ dst) {
    int wid = threadIdx.x >> 5, lane = threadIdx.x & 31;
    int e = blockIdx.x * 8 + wid;
    int sI = src[e], dI = dst[e];
    const __half* gp = g_g2 + (size_t)e * 128 + lane * 4;
    const __half* hp = g_h2 + (size_t)sI * 128 + lane * 4;
    float2 ga = __half22float2(*(const __half2*)&gp[0]);
    float2 gb = __half22float2(*(const __half2*)&gp[2]);
    float2 ha = __half22float2(*(const __half2*)&hp[0]);
    float2 hb = __half22float2(*(const __half2*)&hp[2]);
    float* ag = g_agg2 + (size_t)dI * 128 + lane * 4;
    red_v2(ag,     ga.x * ha.x, ga.y * ha.y);
    red_v2(ag + 2, gb.x * hb.x, gb.y * hb.y);
}

// ---------------- pool reduce ----------------
__global__ void k_poolreduce(const float* __restrict__ pool, float* __restrict__ sOut) {
    int i = blockIdx.x * 256 + threadIdx.x;
    int c = i >> 8;
    float s = 0.f;
#pragma unroll
    for (int r = 0; r < RPL; r++) s += pool[r * NC * 256 + i];
    sOut[i] = s * g_invcnt[c];
}

// ---------------- final MLP ----------------
__global__ void k_final(const float* __restrict__ Wl1, const float* __restrict__ bl1,
                        const float* __restrict__ Wl2, const float* __restrict__ bl2,
                        float* __restrict__ out) {
    __shared__ float sv[256];
    __shared__ float red[256];
    int c = blockIdx.x, j = threadIdx.x;
    sv[j] = g_s1[c * 256 + j] + g_s2[c * 256 + j];
    __syncthreads();
    float a = bl1[j];
    for (int k = 0; k < 256; k++)
        a += sv[k] * (Wl1[k * 256 + j] + Wl1[(256 + k) * 256 + j]);
    red[j] = fmaxf(a, 0.f) * Wl2[j];
    __syncthreads();
    for (int s = 128; s > 0; s >>= 1) {
        if (j < s) red[j] += red[j + s];
        __syncthreads();
    }
    if (j == 0) out[c] = red[0] + bl2[0];
}

// ---------------- host launch ----------------
extern "C" void kernel_launch(void* const* d_in, const int* in_sizes, int n_in,
                              void* d_out, int out_size) {
    (void)in_sizes; (void)n_in; (void)out_size;
    const float* x     = (const float*)d_in[0];
    const float* eattr = (const float*)d_in[1];
    const int*   ei    = (const int*)d_in[2];
    const int*   comm  = (const int*)d_in[3];
    const int*   pe    = (const int*)d_in[4];
    const float* We  = (const float*)d_in[5],  * be  = (const float*)d_in[6];
    const float* W1  = (const float*)d_in[7],  * b1  = (const float*)d_in[8];
    const float* W2  = (const float*)d_in[9],  * b2  = (const float*)d_in[10];
    const float* W3  = (const float*)d_in[11], * b3  = (const float*)d_in[12];
    const float* Wel = (const float*)d_in[13], * bel = (const float*)d_in[14];
    const float* Wm1 = (const float*)d_in[15], * bm1 = (const float*)d_in[16];
    const float* Wc1 = (const float*)d_in[17], * bc1 = (const float*)d_in[18];
    const float* Wm2 = (const float*)d_in[19], * bm2 = (const float*)d_in[20];
    const float* Wc2 = (const float*)d_in[21], * bc2 = (const float*)d_in[22];
    const float* Wam = (const float*)d_in[23], * bam = (const float*)d_in[24];
    const float* Wl1 = (const float*)d_in[25], * bl1 = (const float*)d_in[26];
    const float* Wl2 = (const float*)d_in[27], * bl2 = (const float*)d_in[28];

    const int* src = ei, * dst = ei + NEDGE;
    const int* pi  = pe, * pj  = pe + NP;

    __half *ht_, *h_, *h2_, *h3_, *aggh_, *aggh2_, *g2_, *wh_;
    float *agg_, *agg2_, *pool1_, *pool2_, *s1_, *s2_;
    int *deg_, *cnt_;
    cudaGetSymbolAddress((void**)&ht_,    g_ht);
    cudaGetSymbolAddress((void**)&h_,     g_h);
    cudaGetSymbolAddress((void**)&h2_,    g_h2);
    cudaGetSymbolAddress((void**)&h3_,    g_h3);
    cudaGetSymbolAddress((void**)&aggh_,  g_aggh);
    cudaGetSymbolAddress((void**)&aggh2_, g_aggh2);
    cudaGetSymbolAddress((void**)&agg_,   g_agg);
    cudaGetSymbolAddress((void**)&agg2_,  g_agg2);
    cudaGetSymbolAddress((void**)&pool1_, g_pool1);
    cudaGetSymbolAddress((void**)&pool2_, g_pool2);
    cudaGetSymbolAddress((void**)&s1_,    g_s1);
    cudaGetSymbolAddress((void**)&s2_,    g_s2);
    cudaGetSymbolAddress((void**)&wh_,    g_wh);
    cudaGetSymbolAddress((void**)&g2_,    g_g2);
    cudaGetSymbolAddress((void**)&deg_,   g_deg);
    cudaGetSymbolAddress((void**)&cnt_,   g_cnt);

    cudaFuncSetAttribute(k_elconv, cudaFuncAttributeMaxDynamicSharedMemorySize, SMEM_EL);

    cudaStream_t sB;
    cudaStreamCreateWithFlags(&sB, cudaStreamNonBlocking);
    cudaEvent_t evS, evP, evF, evJ;
    cudaEventCreateWithFlags(&evS, cudaEventDisableTiming);
    cudaEventCreateWithFlags(&evP, cudaEventDisableTiming);
    cudaEventCreateWithFlags(&evF, cudaEventDisableTiming);
    cudaEventCreateWithFlags(&evJ, cudaEventDisableTiming);

    dim3 blk(256);
    const int gN = (NN + 127) / 128;
    const int gE = NEDGE / 128;
    const int gP = NP / 128;

    // ---- fork side stream FROM the capture origin stream (required for capture) ----
    cudaEventRecord(evS, 0);
    cudaStreamWaitEvent(sB, evS, 0);

    // ---- side stream: deg/inv + late-needed memsets ----
    cudaMemsetAsync(deg_,   0, NN * sizeof(int), sB);
    cudaMemsetAsync(cnt_,   0, NC * sizeof(int), sB);
    k_deg<<<(NEDGE + 255) / 256, 256, 0, sB>>>(dst, comm);
    k_inv<<<(NN + 255) / 256, 256, 0, sB>>>();
    cudaMemsetAsync(agg2_,  0, (size_t)NN * 128 * sizeof(float), sB);
    cudaMemsetAsync(pool1_, 0, (size_t)RPL * NC * 256 * sizeof(float), sB);
    cudaMemsetAsync(pool2_, 0, (size_t)RPL * NC * 256 * sizeof(float), sB);
    cudaEventRecord(evP, sB);

    // ---- default stream: main chain ----
    cudaMemsetAsync(agg_, 0, (size_t)NN * 128 * sizeof(float));
    k_transAll<<<736, 256>>>(W3, Wel, Wm1, Wc1, Wm2, Wc2, Wam);
    k_ht<<<NN, 128>>>(x, W1, b1, W2, b2);
    gemm_tc<M_PLAIN, E_RELU, 128><<<dim3(gN, 1), blk>>>(ht_, wh_ + OW3, b3, h_,
        nullptr, nullptr, nullptr, NN, 128);
    k_elconv<<<gE, blk, SMEM_EL>>>(h_, eattr, We, be,
                                   wh_ + OWEL, bel, wh_ + OWM1, bm1, wh_ + OWM2, bm2,
                                   src, dst, agg_, g2_);
    cudaStreamWaitEvent(0, evP, 0);   // invdeg + agg2/pool memsets ready
    k_scale<<<(NN * 32 + 255) / 256, 256>>>(agg_, aggh_);
    gemm_tc<M_PLAIN, E_RELU, 128><<<dim3(gN, 1), blk>>>(aggh_, wh_ + OWC1, bc1, h2_,
        nullptr, nullptr, nullptr, NN, 128);

    // ---- fork: pool1 chain on side stream ----
    cudaEventRecord(evF, 0);
    cudaStreamWaitEvent(sB, evF, 0);
    gemm_tc<M_PAIR, E_POOL, 256><<<dim3(gP, 2), blk, 0, sB>>>(h2_, wh_ + OWAM, bam, pool1_,
        pi, pj, comm, NP, 256);
    k_poolreduce<<<NC, 256, 0, sB>>>(pool1_, s1_);
    cudaEventRecord(evJ, sB);

    k_conv2<<<NEDGE / 8, 256>>>(src, dst);
    k_scale<<<(NN * 32 + 255) / 256, 256>>>(agg2_, aggh2_);
    gemm_tc<M_PLAIN, E_RELU, 128><<<dim3(gN, 1), blk>>>(aggh2_, wh_ + OWC2, bc2, h3_,
        nullptr, nullptr, nullptr, NN, 128);
    gemm_tc<M_PAIR, E_POOL, 256><<<dim3(gP, 2), blk>>>(h3_, wh_ + OWAM, bam, pool2_,
        pi, pj, comm, NP, 256);
    k_poolreduce<<<NC, 256>>>(pool2_, s2_);

    cudaStreamWaitEvent(0, evJ, 0);
    k_final<<<NC, 256>>>(Wl1, bl1, Wl2, bl2, (float*)d_out);
}

// round 13
// speedup vs baseline: 4.6492x; 1.1139x over previous
#include <cuda_runtime.h>
#include <cuda_fp16.h>
#include <math.h>
#include <stdint.h>

#define NN     50000
#define NEDGE  800000
#define NP     400000
#define NC     1000
#define RPL    32

// ---------------- scratch ----------------
__device__ __half  g_ht  [NN * 128];
__device__ __half  g_h   [NN * 128];
__device__ __half  g_hab [NN * 256];    // [HA | HB] = h @ [Wa|Wb]
__device__ __half  g_h2  [NN * 128];
__device__ __half  g_h3  [NN * 128];
__device__ __half  g_p1  [NN * 512];    // [PU | PV] = h2 @ [Wu|Wv]
__device__ __half  g_p2  [NN * 512];    // from h3
__device__ float   g_agg [NN * 128];
__device__ float   g_agg2[NN * 128];
__device__ __half  g_aggh [NN * 128];
__device__ __half  g_aggh2[NN * 128];
__device__ __half  g_g2  [NEDGE * 128];
__device__ float   g_invdeg[NN];
__device__ int     g_deg [NN];
__device__ int     g_cnt [NC];
__device__ float   g_invcnt[NC];
__device__ float   g_pool1[RPL * NC * 256];
__device__ float   g_pool2[RPL * NC * 256];
__device__ float   g_s1  [NC * 256];
__device__ float   g_s2  [NC * 256];
__device__ __half  g_wh  [188416];

#define OW3   0        // 128x128
#define OWAB  16384    // 256 n x 128 k
#define OWC   49152    // 128 n x 64 k
#define OWM1  57344
#define OWC1  73728
#define OWM2  90112
#define OWC2  106496
#define OWUV  122880   // 512 n x 128 k

#define TS  40
#define MST 136

// ---------------- helpers ----------------
__device__ __forceinline__ void mma_f16(float* d, const uint32_t* a, const uint32_t* b) {
    asm volatile(
        "mma.sync.aligned.m16n8k16.row.col.f32.f16.f16.f32 "
        "{%0,%1,%2,%3}, {%4,%5,%6,%7}, {%8,%9}, {%0,%1,%2,%3};\n"
        : "+f"(d[0]), "+f"(d[1]), "+f"(d[2]), "+f"(d[3])
        : "r"(a[0]), "r"(a[1]), "r"(a[2]), "r"(a[3]), "r"(b[0]), "r"(b[1]));
}
__device__ __forceinline__ void ldsm_x4(uint32_t& r0, uint32_t& r1, uint32_t& r2,
                                        uint32_t& r3, uint32_t addr) {
    asm volatile("ldmatrix.sync.aligned.m8n8.x4.shared.b16 {%0,%1,%2,%3}, [%4];"
                 : "=r"(r0), "=r"(r1), "=r"(r2), "=r"(r3) : "r"(addr));
}
__device__ __forceinline__ void red_v2(float* p, float v0, float v1) {
    asm volatile("red.global.add.v2.f32 [%0], {%1, %2};"
                 :: "l"(p), "f"(v0), "f"(v1) : "memory");
}
__device__ __forceinline__ void red_v4(float* p, float a, float b, float c, float d) {
    asm volatile("red.global.add.v4.f32 [%0], {%1, %2, %3, %4};"
                 :: "l"(p), "f"(a), "f"(b), "f"(c), "f"(d) : "memory");
}
__device__ __forceinline__ uint32_t s2u(const void* p) {
    return (uint32_t)__cvta_generic_to_shared(p);
}
__device__ __forceinline__ void cp16(uint32_t dst, const void* src) {
    asm volatile("cp.async.ca.shared.global [%0], [%1], 16;" :: "r"(dst), "l"(src));
}
__device__ __forceinline__ void cp_commit() { asm volatile("cp.async.commit_group;"); }
template<int N> __device__ __forceinline__ void cp_wait() {
    asm volatile("cp.async.wait_group %0;" :: "n"(N));
}

// ---------------- small kernels ----------------
__global__ void k_deg(const int* __restrict__ dst, const int* __restrict__ comm) {
    int i = blockIdx.x * blockDim.x + threadIdx.x;
    if (i < NEDGE) atomicAdd(&g_deg[dst[i]], 1);
    if (i < NP)    atomicAdd(&g_cnt[comm[i]], 1);
}
__global__ void k_inv() {
    int i = blockIdx.x * blockDim.x + threadIdx.x;
    if (i < NN) g_invdeg[i] = 1.0f / (float)max(g_deg[i], 1);
    if (i < NC) g_invcnt[i] = 1.0f / (float)max(g_cnt[i], 1);
}
__global__ void k_transAll(const float* __restrict__ W3,  const float* __restrict__ Wel,
                           const float* __restrict__ Wm1, const float* __restrict__ Wc1,
                           const float* __restrict__ Wm2, const float* __restrict__ Wc2,
                           const float* __restrict__ Wam) {
    int b = blockIdx.x, tid = threadIdx.x;
    if (b < 64) {                              // W3
        int i = b * 256 + tid; int n = i >> 7, k = i & 127;
        g_wh[OW3 + i] = __float2half(W3[k * 128 + n]);
    } else if (b < 192) {                      // WAB: [Wa|Wb] of Wel
        int i = (b - 64) * 256 + tid; int n = i >> 7, k = i & 127;
        int kk = k + ((n & 128) ? 128 : 0);
        g_wh[OWAB + i] = __float2half(Wel[kk * 128 + (n & 127)]);
    } else if (b < 224) {                      // WC: Wel rows 256..319
        int i = (b - 192) * 256 + tid; int n = i >> 6, k = i & 63;
        g_wh[OWC + i] = __float2half(Wel[(k + 256) * 128 + n]);
    } else if (b < 288) {
        int i = (b - 224) * 256 + tid; int n = i >> 7, k = i & 127;
        g_wh[OWM1 + i] = __float2half(Wm1[k * 128 + n]);
    } else if (b < 352) {
        int i = (b - 288) * 256 + tid; int n = i >> 7, k = i & 127;
        g_wh[OWC1 + i] = __float2half(Wc1[k * 128 + n]);
    } else if (b < 416) {
        int i = (b - 352) * 256 + tid; int n = i >> 7, k = i & 127;
        g_wh[OWM2 + i] = __float2half(Wm2[k * 128 + n]);
    } else if (b < 480) {
        int i = (b - 416) * 256 + tid; int n = i >> 7, k = i & 127;
        g_wh[OWC2 + i] = __float2half(Wc2[k * 128 + n]);
    } else {                                   // WUV: [Wu|Wv] of Wam
        int i = (b - 480) * 256 + tid; int n = i >> 7, k = i & 127;
        int kk = k + ((n & 256) ? 128 : 0);
        g_wh[OWUV + i] = __float2half(Wam[kk * 256 + (n & 255)]);
    }
}
__global__ void k_scale(const float* __restrict__ in, __half* __restrict__ out) {
    int i = blockIdx.x * 256 + threadIdx.x;
    if (i >= NN * 32) return;
    float4 v = *(const float4*)(in + i * 4);
    float sc = g_invdeg[i >> 5];
    *(__half2*)(out + i * 4)     = __floats2half2_rn(v.x * sc, v.y * sc);
    *(__half2*)(out + i * 4 + 2) = __floats2half2_rn(v.z * sc, v.w * sc);
}
__global__ void k_ht(const float* __restrict__ x,
                     const float* __restrict__ W1, const float* __restrict__ b1,
                     const float* __restrict__ W2, const float* __restrict__ b2) {
    int n = blockIdx.x;
    int c = threadIdx.x;
    const float* xr = x + n * 20;
    float s;
    if (c < 64) {
        s = b1[c];
#pragma unroll
        for (int k = 0; k < 8; k++) s += xr[k] * W1[k * 64 + c];
    } else {
        int cc = c - 64;
        s = b2[cc];
#pragma unroll
        for (int k = 0; k < 12; k++) s += xr[8 + k] * W2[k * 64 + cc];
    }
    g_ht[n * 128 + c] = __float2half(fmaxf(s, 0.0f));
}

// ================= plain fp16 GEMM (node-level), ldmatrix mainloop =================
enum { E_RELU = 0, E_LIN = 1 };

template<int K>
__device__ __forceinline__ void load_stage(
    __half* As, __half* Ws, int t, int st,
    const __half* __restrict__ A, const __half* __restrict__ Wt,
    const size_t* offA, int tid, int n0)
{
    const int k0 = t * 32;
    const int chunk = tid & 3;
    const int gk = k0 + chunk * 8;
#pragma unroll
    for (int l = 0; l < 2; l++) {
        int row = (tid >> 2) + l * 64;
        cp16(s2u(&As[st * 5120 + row * TS + chunk * 8]), A + offA[l] + gk);
    }
#pragma unroll
    for (int l = 0; l < 2; l++) {
        int nrow = (tid >> 2) + l * 64;
        cp16(s2u(&Ws[st * 5120 + nrow * TS + chunk * 8]),
             Wt + (size_t)(n0 + nrow) * K + gk);
    }
}

template<int EPI, int K>
__global__ void __launch_bounds__(256)
gemm_tc(const __half* __restrict__ A, const __half* __restrict__ Wt,
        const float* __restrict__ bias, __half* __restrict__ Cout,
        int rows, int ncols)
{
    __shared__ __half As[2 * 5120];
    __shared__ __half Ws[2 * 5120];

    const int tid  = threadIdx.x;
    const int wid  = tid >> 5, lane = tid & 31;
    const int wm   = wid & 1,  wn   = wid >> 1;
    const int g    = lane >> 2, tig = lane & 3;
    const int rowbase = blockIdx.x * 128;
    const int n0      = blockIdx.y * 128;

    const int laneA_row = (lane & 7) + ((lane >> 3) & 1) * 8;
    const int laneA_col = (lane >> 4) * 8;
    const int laneB_row = lane & 7;
    const int laneB_nt  = (lane >> 4);
    const int laneB_kh  = ((lane >> 3) & 1) * 8;

    size_t offA[2];
#pragma unroll
    for (int l = 0; l < 2; l++) {
        int grow = rowbase + (tid >> 2) + l * 64;
        int gc = (grow < rows) ? grow : (rows - 1);
        offA[l] = (size_t)gc * K;
    }

    float acc[4][4][4];
#pragma unroll
    for (int a = 0; a < 4; a++)
#pragma unroll
        for (int b = 0; b < 4; b++)
#pragma unroll
            for (int c = 0; c < 4; c++) acc[a][b][c] = 0.0f;

    const int NT = K / 32;
    load_stage<K>(As, Ws, 0, 0, A, Wt, offA, tid, n0);
    cp_commit();

    for (int t = 0; t < NT; t++) {
        const int s = t & 1;
        if (t + 1 < NT) {
            load_stage<K>(As, Ws, t + 1, (t + 1) & 1, A, Wt, offA, tid, n0);
            cp_commit();
            cp_wait<1>();
        } else cp_wait<0>();
        __syncthreads();

        const __half* Ab = As + s * 5120;
        const __half* Wb = Ws + s * 5120;
#pragma unroll
        for (int ks = 0; ks < 2; ks++) {
            const int kb = ks * 16;
            uint32_t af[4][4];
#pragma unroll
            for (int mt = 0; mt < 4; mt++)
                ldsm_x4(af[mt][0], af[mt][1], af[mt][2], af[mt][3],
                        s2u(&Ab[(wm * 64 + mt * 16 + laneA_row) * TS + kb + laneA_col]));
            uint32_t bf[4][2];
#pragma unroll
            for (int p = 0; p < 2; p++) {
                int nr = wn * 32 + (p * 2 + laneB_nt) * 8 + laneB_row;
                ldsm_x4(bf[p * 2][0], bf[p * 2][1], bf[p * 2 + 1][0], bf[p * 2 + 1][1],
                        s2u(&Wb[nr * TS + kb + laneB_kh]));
            }
#pragma unroll
            for (int mt = 0; mt < 4; mt++)
#pragma unroll
                for (int nt = 0; nt < 4; nt++)
                    mma_f16(acc[mt][nt], af[mt], bf[nt]);
        }
        __syncthreads();
    }

    float bc0[4], bc1[4];
    if (EPI == E_RELU) {
#pragma unroll
        for (int nt = 0; nt < 4; nt++) {
            int c = wn * 32 + nt * 8 + tig * 2;
            bc0[nt] = bias[n0 + c];
            bc1[nt] = bias[n0 + c + 1];
        }
    }

#pragma unroll
    for (int mt = 0; mt < 4; mt++) {
#pragma unroll
        for (int half_ = 0; half_ < 2; half_++) {
            int rl = wm * 64 + mt * 16 + g + half_ * 8;
            int r  = rowbase + rl;
            if (r >= rows) continue;
            __half* op = Cout + (size_t)r * ncols + n0;
#pragma unroll
            for (int nt = 0; nt < 4; nt++) {
                int c = wn * 32 + nt * 8 + tig * 2;
                float v0 = acc[mt][nt][half_ * 2    ];
                float v1 = acc[mt][nt][half_ * 2 + 1];
                if (EPI == E_RELU) {
                    v0 = fmaxf(v0 + bc0[nt], 0.f);
                    v1 = fmaxf(v1 + bc1[nt], 0.f);
                }
                *(__half2*)&op[c] = __floats2half2_rn(v0, v1);
            }
        }
    }
}

// ================= fused EL + gate1 + gate2 kernel =================
// phase 1: mask = relu( ea@Wc + HA[src] + HB[dst] + bel )
#define SM_AS 0
#define SM_WS 20480
#define SM_MS 40960                       // X = HA[src] staging, then mask
#define SM_Y  (SM_MS + 128 * MST * 2)     // 75776: Y = HB[dst]
#define SM_WE (SM_Y + 128 * MST * 2)      // 110592
#define SM_BE (SM_WE + 2048)              // 112640
#define SMEM_EL (SM_BE + 256)             // 112896

__device__ __forceinline__ void el_loadW(__half* Ws, int t, int st,
                                         const __half* __restrict__ Wt, int Kw, int tid) {
    const int k0 = t * 32;
    const int chunk = tid & 3;
#pragma unroll
    for (int l = 0; l < 2; l++) {
        int nrow = (tid >> 2) + l * 64;
        cp16(s2u(&Ws[st * 5120 + nrow * TS + chunk * 8]),
             Wt + (size_t)nrow * Kw + k0 + chunk * 8);
    }
}

__global__ void __launch_bounds__(256)
k_elconv(const __half* __restrict__ h, const __half* __restrict__ hab,
         const float* __restrict__ eattr, const float* __restrict__ We,
         const float* __restrict__ be,   const float* __restrict__ bel,
         const __half* __restrict__ Wct,
         const __half* __restrict__ Wm1t, const float* __restrict__ bm1,
         const __half* __restrict__ Wm2t, const float* __restrict__ bm2,
         const int* __restrict__ src, const int* __restrict__ dst,
         float* __restrict__ agg, __half* __restrict__ gate2)
{
    extern __shared__ char smem[];
    __half* As = (__half*)(smem + SM_AS);
    __half* Ws = (__half*)(smem + SM_WS);
    __half* Ms = (__half*)(smem + SM_MS);
    __half* Ys = (__half*)(smem + SM_Y);
    float* Wes = (float*)(smem + SM_WE);
    float* bes = (float*)(smem + SM_BE);

    const int tid  = threadIdx.x;
    const int wid  = tid >> 5, lane = tid & 31;
    const int wm   = wid & 1,  wn   = wid >> 1;
    const int g    = lane >> 2, tig = lane & 3;
    const int rowbase = blockIdx.x * 128;

    const int laneA_row = (lane & 7) + ((lane >> 3) & 1) * 8;
    const int laneA_col = (lane >> 4) * 8;
    const int laneB_row = lane & 7;
    const int laneB_nt  = (lane >> 4);
    const int laneB_kh  = ((lane >> 3) & 1) * 8;

    const int chunk = tid & 3;
    int sIdx[2], dIdx[2];
    float eat[2][8];
#pragma unroll
    for (int l = 0; l < 2; l++) {
        int grow = rowbase + (tid >> 2) + l * 64;
        sIdx[l] = src[grow];
        dIdx[l] = dst[grow];
        const float4* ap = (const float4*)(eattr + (size_t)grow * 8);
        float4 a0 = ap[0], a1 = ap[1];
        eat[l][0] = a0.x; eat[l][1] = a0.y; eat[l][2] = a0.z; eat[l][3] = a0.w;
        eat[l][4] = a1.x; eat[l][5] = a1.y; eat[l][6] = a1.z; eat[l][7] = a1.w;
    }
    if (tid < 256) { Wes[tid] = We[tid]; Wes[256 + tid] = We[256 + tid]; }
    if (tid < 64)  bes[tid] = be[tid];

    // ---- async gathers: X = HA[src] (cols 0..127), Y = HB[dst] (cols 128..255) ----
#pragma unroll
    for (int l = 0; l < 2; l++) {
        int row = (tid >> 2) + l * 64;
        const __half* xa = hab + (size_t)sIdx[l] * 256;
        const __half* yb = hab + (size_t)dIdx[l] * 256 + 128;
#pragma unroll
        for (int q = 0; q < 4; q++) {
            int cc = (chunk + q * 4) * 8;     // 8-half chunk
            cp16(s2u(&Ms[row * MST + cc]), xa + cc);
            cp16(s2u(&Ys[row * MST + cc]), yb + cc);
        }
    }
    // ---- Wc weights: both k-tiles (K=64) ----
    el_loadW(Ws, 0, 0, Wct, 64, tid);
    el_loadW(Ws, 1, 1, Wct, 64, tid);
    cp_commit();

    __syncthreads();   // Wes/bes visible

    // ---- compute ea tiles into As stage 0 (k 0..31) and 1 (k 32..63) ----
#pragma unroll
    for (int t = 0; t < 2; t++) {
        const int cb = t * 32 + chunk * 8;
#pragma unroll
        for (int l = 0; l < 2; l++) {
            int row = (tid >> 2) + l * 64;
            __half* dstp = &As[t * 5120 + row * TS + chunk * 8];
#pragma unroll
            for (int j = 0; j < 8; j += 2) {
                float s0 = bes[cb + j], s1 = bes[cb + j + 1];
#pragma unroll
                for (int k = 0; k < 8; k++) {
                    s0 += eat[l][k] * Wes[k * 64 + cb + j];
                    s1 += eat[l][k] * Wes[k * 64 + cb + j + 1];
                }
                *(__half2*)&dstp[j] = __floats2half2_rn(fmaxf(s0, 0.f), fmaxf(s1, 0.f));
            }
        }
    }
    cp_wait<0>();
    __syncthreads();

    float acc[4][4][4];
#pragma unroll
    for (int a = 0; a < 4; a++)
#pragma unroll
        for (int b = 0; b < 4; b++)
#pragma unroll
            for (int c = 0; c < 4; c++) acc[a][b][c] = 0.0f;

    // ---- phase 1 MMA: 2 k-tiles of ea@Wc ----
#pragma unroll
    for (int t = 0; t < 2; t++) {
        const __half* Ab = As + t * 5120;
        const __half* Wb = Ws + t * 5120;
#pragma unroll
        for (int ks = 0; ks < 2; ks++) {
            const int kb = ks * 16;
            uint32_t af[4][4];
#pragma unroll
            for (int mt = 0; mt < 4; mt++)
                ldsm_x4(af[mt][0], af[mt][1], af[mt][2], af[mt][3],
                        s2u(&Ab[(wm * 64 + mt * 16 + laneA_row) * TS + kb + laneA_col]));
            uint32_t bf[4][2];
#pragma unroll
            for (int p = 0; p < 2; p++) {
                int nr = wn * 32 + (p * 2 + laneB_nt) * 8 + laneB_row;
                ldsm_x4(bf[p * 2][0], bf[p * 2][1], bf[p * 2 + 1][0], bf[p * 2 + 1][1],
                        s2u(&Wb[nr * TS + kb + laneB_kh]));
            }
#pragma unroll
            for (int mt = 0; mt < 4; mt++)
#pragma unroll
                for (int nt = 0; nt < 4; nt++)
                    mma_f16(acc[mt][nt], af[mt], bf[nt]);
        }
    }

    // ---- phase-1 epilogue: mask = relu(acc + X + Y + bel) -> Ms (aliases X) ----
#pragma unroll
    for (int mt = 0; mt < 4; mt++)
#pragma unroll
        for (int half_ = 0; half_ < 2; half_++) {
            int rl = wm * 64 + mt * 16 + g + half_ * 8;
#pragma unroll
            for (int nt = 0; nt < 4; nt++) {
                int c = wn * 32 + nt * 8 + tig * 2;
                float2 xv = __half22float2(*(__half2*)&Ms[rl * MST + c]);
                float2 yv = __half22float2(*(__half2*)&Ys[rl * MST + c]);
                float v0 = fmaxf(acc[mt][nt][half_ * 2    ] + xv.x + yv.x + bel[c    ], 0.f);
                float v1 = fmaxf(acc[mt][nt][half_ * 2 + 1] + xv.y + yv.y + bel[c + 1], 0.f);
                *(__half2*)&Ms[rl * MST + c] = __floats2half2_rn(v0, v1);
            }
        }
    __syncthreads();

    // ---- phases 2 & 3: Ms @ Wm{1,2}, K=128 ----
#pragma unroll 1
    for (int ph = 0; ph < 2; ph++) {
        const __half* Wm = (ph == 0) ? Wm1t : Wm2t;
        const float*  bm = (ph == 0) ? bm1 : bm2;

#pragma unroll
        for (int a = 0; a < 4; a++)
#pragma unroll
            for (int b = 0; b < 4; b++)
#pragma unroll
                for (int c = 0; c < 4; c++) acc[a][b][c] = 0.0f;

        el_loadW(Ws, 0, 0, Wm, 128, tid);
        cp_commit();
        for (int t = 0; t < 4; t++) {
            const int s = t & 1;
            if (t + 1 < 4) {
                el_loadW(Ws, t + 1, (t + 1) & 1, Wm, 128, tid);
                cp_commit();
                cp_wait<1>();
            } else cp_wait<0>();
            __syncthreads();

            const __half* Wb = Ws + s * 5120;
#pragma unroll
            for (int ks = 0; ks < 2; ks++) {
                const int kbM = t * 32 + ks * 16;
                const int kbW = ks * 16;
                uint32_t af[4][4];
#pragma unroll
                for (int mt = 0; mt < 4; mt++)
                    ldsm_x4(af[mt][0], af[mt][1], af[mt][2], af[mt][3],
                            s2u(&Ms[(wm * 64 + mt * 16 + laneA_row) * MST + kbM + laneA_col]));
                uint32_t bf[4][2];
#pragma unroll
                for (int p = 0; p < 2; p++) {
                    int nr = wn * 32 + (p * 2 + laneB_nt) * 8 + laneB_row;
                    ldsm_x4(bf[p * 2][0], bf[p * 2][1], bf[p * 2 + 1][0], bf[p * 2 + 1][1],
                            s2u(&Wb[nr * TS + kbW + laneB_kh]));
                }
#pragma unroll
                for (int mt = 0; mt < 4; mt++)
#pragma unroll
                    for (int nt = 0; nt < 4; nt++)
                        mma_f16(acc[mt][nt], af[mt], bf[nt]);
            }
            __syncthreads();
        }

        if (ph == 0) {
#pragma unroll
            for (int mt = 0; mt < 4; mt++)
#pragma unroll
                for (int half_ = 0; half_ < 2; half_++) {
                    int rl = wm * 64 + mt * 16 + g + half_ * 8;
                    int r  = rowbase + rl;
                    int sI = src[r], dI = dst[r];
                    const __half* hs = h + (size_t)sI * 128;
                    float*        ag = agg + (size_t)dI * 128;
#pragma unroll
                    for (int nt = 0; nt < 4; nt++) {
                        int c = wn * 32 + nt * 8 + tig * 2;
                        float z0 = acc[mt][nt][half_ * 2    ] + bm[c];
                        float z1 = acc[mt][nt][half_ * 2 + 1] + bm[c + 1];
                        float g0 = 1.0f / (1.0f + __expf(-z0));
                        float g1 = 1.0f / (1.0f + __expf(-z1));
                        float2 hv = __half22float2(*(const __half2*)&hs[c]);
                        red_v2(&ag[c], g0 * hv.x, g1 * hv.y);
                    }
                }
        } else {
#pragma unroll
            for (int mt = 0; mt < 4; mt++)
#pragma unroll
                for (int half_ = 0; half_ < 2; half_++) {
                    int rl = wm * 64 + mt * 16 + g + half_ * 8;
#pragma unroll
                    for (int nt = 0; nt < 4; nt++) {
                        int c = wn * 32 + nt * 8 + tig * 2;
                        float z0 = acc[mt][nt][half_ * 2    ] + bm[c];
                        float z1 = acc[mt][nt][half_ * 2 + 1] + bm[c + 1];
                        float g0 = 1.0f / (1.0f + __expf(-z0));
                        float g1 = 1.0f / (1.0f + __expf(-z1));
                        *(__half2*)&Ms[rl * MST + c] = __floats2half2_rn(g0, g1);
                    }
                }
            __syncthreads();
            __half* gout = gate2 + (size_t)rowbase * 128;
            for (int i = tid; i < 2048; i += 256) {
                int row = i >> 4, part = i & 15;
                float4 v = *(float4*)&Ms[row * MST + part * 8];
                *(float4*)&gout[row * 128 + part * 8] = v;
            }
        }
    }
}

// ---------------- conv2 scatter ----------------
__global__ void __launch_bounds__(256) k_conv2(const int* __restrict__ src,
                                               const int* __restrict__ dst) {
    int wid = threadIdx.x >> 5, lane = threadIdx.x & 31;
    int e = blockIdx.x * 8 + wid;
    int sI = src[e], dI = dst[e];
    const __half* gp = g_g2 + (size_t)e * 128 + lane * 4;
    const __half* hp = g_h2 + (size_t)sI * 128 + lane * 4;
    float2 ga = __half22float2(*(const __half2*)&gp[0]);
    float2 gb = __half22float2(*(const __half2*)&gp[2]);
    float2 ha = __half22float2(*(const __half2*)&hp[0]);
    float2 hb = __half22float2(*(const __half2*)&hp[2]);
    float* ag = g_agg2 + (size_t)dI * 128 + lane * 4;
    red_v4(ag, ga.x * ha.x, ga.y * ha.y, gb.x * hb.x, gb.y * hb.y);
}

// ---------------- pool scatter: r = relu(PU[pi]+PV[pj]+bam) -> replica ----------------
__global__ void __launch_bounds__(256)
k_pool(const __half* __restrict__ P, const float* __restrict__ bam,
       const int* __restrict__ pi, const int* __restrict__ pj,
       const int* __restrict__ comm, float* __restrict__ pool)
{
    int wid = threadIdx.x >> 5, lane = threadIdx.x & 31;
    int e = blockIdx.x * 8 + wid;           // NP/8 blocks
    int a = pi[e], b = pj[e], cm = comm[e];
    const __half* pu = P + (size_t)a * 512 + lane * 8;
    const __half* pv = P + (size_t)b * 512 + 256 + lane * 8;
    float4 u4 = *(const float4*)pu;
    float4 v4 = *(const float4*)pv;
    const __half2* uh = (const __half2*)&u4;
    const __half2* vh = (const __half2*)&v4;
    const float* bb = bam + lane * 8;
    float r[8];
#pragma unroll
    for (int j = 0; j < 4; j++) {
        float2 ua = __half22float2(uh[j]);
        float2 va = __half22float2(vh[j]);
        r[j * 2    ] = fmaxf(ua.x + va.x + bb[j * 2    ], 0.f);
        r[j * 2 + 1] = fmaxf(ua.y + va.y + bb[j * 2 + 1], 0.f);
    }
    float* pb = pool + (size_t)(blockIdx.x & (RPL - 1)) * (NC * 256) + cm * 256 + lane * 8;
    red_v4(pb,     r[0], r[1], r[2], r[3]);
    red_v4(pb + 4, r[4], r[5], r[6], r[7]);
}

// ---------------- pool reduce ----------------
__global__ void k_poolreduce(const float* __restrict__ pool, float* __restrict__ sOut) {
    int i = blockIdx.x * 256 + threadIdx.x;
    int c = i >> 8;
    float s = 0.f;
#pragma unroll
    for (int r = 0; r < RPL; r++) s += pool[r * NC * 256 + i];
    sOut[i] = s * g_invcnt[c];
}

// ---------------- final MLP ----------------
__global__ void k_final(const float* __restrict__ Wl1, const float* __restrict__ bl1,
                        const float* __restrict__ Wl2, const float* __restrict__ bl2,
                        float* __restrict__ out) {
    __shared__ float sv[256];
    __shared__ float red[256];
    int c = blockIdx.x, j = threadIdx.x;
    sv[j] = g_s1[c * 256 + j] + g_s2[c * 256 + j];
    __syncthreads();
    float a = bl1[j];
    for (int k = 0; k < 256; k++)
        a += sv[k] * (Wl1[k * 256 + j] + Wl1[(256 + k) * 256 + j]);
    red[j] = fmaxf(a, 0.f) * Wl2[j];
    __syncthreads();
    for (int s = 128; s > 0; s >>= 1) {
        if (j < s) red[j] += red[j + s];
        __syncthreads();
    }
    if (j == 0) out[c] = red[0] + bl2[0];
}

// ---------------- host launch ----------------
extern "C" void kernel_launch(void* const* d_in, const int* in_sizes, int n_in,
                              void* d_out, int out_size) {
    (void)in_sizes; (void)n_in; (void)out_size;
    const float* x     = (const float*)d_in[0];
    const float* eattr = (const float*)d_in[1];
    const int*   ei    = (const int*)d_in[2];
    const int*   comm  = (const int*)d_in[3];
    const int*   pe    = (const int*)d_in[4];
    const float* We  = (const float*)d_in[5],  * be  = (const float*)d_in[6];
    const float* W1  = (const float*)d_in[7],  * b1  = (const float*)d_in[8];
    const float* W2  = (const float*)d_in[9],  * b2  = (const float*)d_in[10];
    const float* W3  = (const float*)d_in[11], * b3  = (const float*)d_in[12];
    const float* Wel = (const float*)d_in[13], * bel = (const float*)d_in[14];
    const float* Wm1 = (const float*)d_in[15], * bm1 = (const float*)d_in[16];
    const float* Wc1 = (const float*)d_in[17], * bc1 = (const float*)d_in[18];
    const float* Wm2 = (const float*)d_in[19], * bm2 = (const float*)d_in[20];
    const float* Wc2 = (const float*)d_in[21], * bc2 = (const float*)d_in[22];
    const float* Wam = (const float*)d_in[23], * bam = (const float*)d_in[24];
    const float* Wl1 = (const float*)d_in[25], * bl1 = (const float*)d_in[26];
    const float* Wl2 = (const float*)d_in[27], * bl2 = (const float*)d_in[28];

    const int* src = ei, * dst = ei + NEDGE;
    const int* pi  = pe, * pj  = pe + NP;

    __half *ht_, *h_, *hab_, *h2_, *h3_, *p1_, *p2_, *aggh_, *aggh2_, *g2_, *wh_;
    float *agg_, *agg2_, *pool1_, *pool2_, *s1_, *s2_;
    int *deg_, *cnt_;
    cudaGetSymbolAddress((void**)&ht_,    g_ht);
    cudaGetSymbolAddress((void**)&h_,     g_h);
    cudaGetSymbolAddress((void**)&hab_,   g_hab);
    cudaGetSymbolAddress((void**)&h2_,    g_h2);
    cudaGetSymbolAddress((void**)&h3_,    g_h3);
    cudaGetSymbolAddress((void**)&p1_,    g_p1);
    cudaGetSymbolAddress((void**)&p2_,    g_p2);
    cudaGetSymbolAddress((void**)&aggh_,  g_aggh);
    cudaGetSymbolAddress((void**)&aggh2_, g_aggh2);
    cudaGetSymbolAddress((void**)&agg_,   g_agg);
    cudaGetSymbolAddress((void**)&agg2_,  g_agg2);
    cudaGetSymbolAddress((void**)&pool1_, g_pool1);
    cudaGetSymbolAddress((void**)&pool2_, g_pool2);
    cudaGetSymbolAddress((void**)&s1_,    g_s1);
    cudaGetSymbolAddress((void**)&s2_,    g_s2);
    cudaGetSymbolAddress((void**)&wh_,    g_wh);
    cudaGetSymbolAddress((void**)&g2_,    g_g2);
    cudaGetSymbolAddress((void**)&deg_,   g_deg);
    cudaGetSymbolAddress((void**)&cnt_,   g_cnt);

    cudaFuncSetAttribute(k_elconv, cudaFuncAttributeMaxDynamicSharedMemorySize, SMEM_EL);

    cudaStream_t sB;
    cudaStreamCreateWithFlags(&sB, cudaStreamNonBlocking);
    cudaEvent_t evS, evP, evF, evJ;
    cudaEventCreateWithFlags(&evS, cudaEventDisableTiming);
    cudaEventCreateWithFlags(&evP, cudaEventDisableTiming);
    cudaEventCreateWithFlags(&evF, cudaEventDisableTiming);
    cudaEventCreateWithFlags(&evJ, cudaEventDisableTiming);

    dim3 blk(256);
    const int gN = (NN + 127) / 128;

    // fork side stream FROM origin (required for capture)
    cudaEventRecord(evS, 0);
    cudaStreamWaitEvent(sB, evS, 0);

    // side stream: deg/inv + late-needed memsets
    cudaMemsetAsync(deg_,   0, NN * sizeof(int), sB);
    cudaMemsetAsync(cnt_,   0, NC * sizeof(int), sB);
    k_deg<<<(NEDGE + 255) / 256, 256, 0, sB>>>(dst, comm);
    k_inv<<<(NN + 255) / 256, 256, 0, sB>>>();
    cudaMemsetAsync(agg2_,  0, (size_t)NN * 128 * sizeof(float), sB);
    cudaMemsetAsync(pool1_, 0, (size_t)RPL * NC * 256 * sizeof(float), sB);
    cudaMemsetAsync(pool2_, 0, (size_t)RPL * NC * 256 * sizeof(float), sB);
    cudaEventRecord(evP, sB);

    // default stream: main chain
    cudaMemsetAsync(agg_, 0, (size_t)NN * 128 * sizeof(float));
    k_transAll<<<736, 256>>>(W3, Wel, Wm1, Wc1, Wm2, Wc2, Wam);
    k_ht<<<NN, 128>>>(x, W1, b1, W2, b2);
    gemm_tc<E_RELU, 128><<<dim3(gN, 1), blk>>>(ht_, wh_ + OW3, b3, h_, NN, 128);
    gemm_tc<E_LIN, 128><<<dim3(gN, 2), blk>>>(h_, wh_ + OWAB, nullptr, hab_, NN, 256);
    k_elconv<<<NEDGE / 128, blk, SMEM_EL>>>(h_, hab_, eattr, We, be, bel,
                                            wh_ + OWC, wh_ + OWM1, bm1, wh_ + OWM2, bm2,
                                            src, dst, agg_, g2_);
    cudaStreamWaitEvent(0, evP, 0);
    k_scale<<<(NN * 32 + 255) / 256, 256>>>(agg_, aggh_);
    gemm_tc<E_RELU, 128><<<dim3(gN, 1), blk>>>(aggh_, wh_ + OWC1, bc1, h2_, NN, 128);

    // fork: pool1 chain on side stream
    cudaEventRecord(evF, 0);
    cudaStreamWaitEvent(sB, evF, 0);
    gemm_tc<E_LIN, 128><<<dim3(gN, 4), blk, 0, sB>>>(h2_, wh_ + OWUV, nullptr, p1_, NN, 512);
    k_pool<<<NP / 8, 256, 0, sB>>>(p1_, bam, pi, pj, comm, pool1_);
    k_poolreduce<<<NC, 256, 0, sB>>>(pool1_, s1_);
    cudaEventRecord(evJ, sB);

    k_conv2<<<NEDGE / 8, 256>>>(src, dst);
    k_scale<<<(NN * 32 + 255) / 256, 256>>>(agg2_, aggh2_);
    gemm_tc<E_RELU, 128><<<dim3(gN, 1), blk>>>(aggh2_, wh_ + OWC2, bc2, h3_, NN, 128);
    gemm_tc<E_LIN, 128><<<dim3(gN, 4), blk>>>(h3_, wh_ + OWUV, nullptr, p2_, NN, 512);
    k_pool<<<NP / 8, 256>>>(p2_, bam, pi, pj, comm, pool2_);
    k_poolreduce<<<NC, 256>>>(pool2_, s2_);

    cudaStreamWaitEvent(0, evJ, 0);
    k_final<<<NC, 256>>>(Wl1, bl1, Wl2, bl2, (float*)d_out);
}

// round 15
// speedup vs baseline: 4.8091x; 1.0344x over previous
#include <cuda_runtime.h>
#include <cuda_fp16.h>
#include <math.h>
#include <stdint.h>

#define NN     50000
#define NEDGE  800000
#define NP     400000
#define NC     1000
#define RPL    32

// ---------------- scratch ----------------
__device__ __half  g_ht  [NN * 128];
__device__ __half  g_h   [NN * 128];
__device__ __half  g_hab [NN * 256];    // [HA | HB] = h @ [Wa|Wb]
__device__ __half  g_h2  [NN * 128];
__device__ __half  g_h3  [NN * 128];
__device__ __half  g_p1  [NN * 512];    // [PU | PV] = h2 @ [Wu|Wv]
__device__ __half  g_p2  [NN * 512];    // from h3
__device__ float   g_agg [NN * 128];
__device__ float   g_agg2[NN * 128];
__device__ __half  g_aggh [NN * 128];
__device__ __half  g_aggh2[NN * 128];
__device__ __half  g_g2  [NEDGE * 128];
__device__ float   g_invdeg[NN];
__device__ int     g_deg [NN];
__device__ int     g_cnt [NC];
__device__ float   g_invcnt[NC];
__device__ float   g_pool1[RPL * NC * 256];
__device__ float   g_pool2[RPL * NC * 256];
__device__ float   g_s1  [NC * 256];
__device__ float   g_s2  [NC * 256];
__device__ __half  g_wh  [188416];

#define OW3   0        // 128x128
#define OWAB  16384    // 256 n x 128 k
#define OWC   49152    // 128 n x 64 k
#define OWM1  57344
#define OWC1  73728
#define OWM2  90112
#define OWC2  106496
#define OWUV  122880   // 512 n x 128 k

#define TS  40
#define MST 136

// ---------------- helpers ----------------
__device__ __forceinline__ void mma_f16(float* d, const uint32_t* a, const uint32_t* b) {
    asm volatile(
        "mma.sync.aligned.m16n8k16.row.col.f32.f16.f16.f32 "
        "{%0,%1,%2,%3}, {%4,%5,%6,%7}, {%8,%9}, {%0,%1,%2,%3};\n"
        : "+f"(d[0]), "+f"(d[1]), "+f"(d[2]), "+f"(d[3])
        : "r"(a[0]), "r"(a[1]), "r"(a[2]), "r"(a[3]), "r"(b[0]), "r"(b[1]));
}
__device__ __forceinline__ void ldsm_x4(uint32_t& r0, uint32_t& r1, uint32_t& r2,
                                        uint32_t& r3, uint32_t addr) {
    asm volatile("ldmatrix.sync.aligned.m8n8.x4.shared.b16 {%0,%1,%2,%3}, [%4];"
                 : "=r"(r0), "=r"(r1), "=r"(r2), "=r"(r3) : "r"(addr));
}
__device__ __forceinline__ void red_v4(float* p, float a, float b, float c, float d) {
    asm volatile("red.global.add.v4.f32 [%0], {%1, %2, %3, %4};"
                 :: "l"(p), "f"(a), "f"(b), "f"(c), "f"(d) : "memory");
}
__device__ __forceinline__ uint32_t s2u(const void* p) {
    return (uint32_t)__cvta_generic_to_shared(p);
}
__device__ __forceinline__ void cp16(uint32_t dst, const void* src) {
    asm volatile("cp.async.ca.shared.global [%0], [%1], 16;" :: "r"(dst), "l"(src));
}
__device__ __forceinline__ void cp_commit() { asm volatile("cp.async.commit_group;"); }
template<int N> __device__ __forceinline__ void cp_wait() {
    asm volatile("cp.async.wait_group %0;" :: "n"(N));
}

// ---------------- small kernels ----------------
__global__ void k_deg(const int* __restrict__ dst, const int* __restrict__ comm) {
    int i = blockIdx.x * blockDim.x + threadIdx.x;
    if (i < NEDGE) atomicAdd(&g_deg[dst[i]], 1);
    if (i < NP)    atomicAdd(&g_cnt[comm[i]], 1);
}
__global__ void k_inv() {
    int i = blockIdx.x * blockDim.x + threadIdx.x;
    if (i < NN) g_invdeg[i] = 1.0f / (float)max(g_deg[i], 1);
    if (i < NC) g_invcnt[i] = 1.0f / (float)max(g_cnt[i], 1);
}
__global__ void k_transAll(const float* __restrict__ W3,  const float* __restrict__ Wel,
                           const float* __restrict__ Wm1, const float* __restrict__ Wc1,
                           const float* __restrict__ Wm2, const float* __restrict__ Wc2,
                           const float* __restrict__ Wam) {
    int b = blockIdx.x, tid = threadIdx.x;
    if (b < 64) {                              // W3
        int i = b * 256 + tid; int n = i >> 7, k = i & 127;
        g_wh[OW3 + i] = __float2half(W3[k * 128 + n]);
    } else if (b < 192) {                      // WAB: [Wa|Wb] of Wel
        int i = (b - 64) * 256 + tid; int n = i >> 7, k = i & 127;
        int kk = k + ((n & 128) ? 128 : 0);
        g_wh[OWAB + i] = __float2half(Wel[kk * 128 + (n & 127)]);
    } else if (b < 224) {                      // WC: Wel rows 256..319
        int i = (b - 192) * 256 + tid; int n = i >> 6, k = i & 63;
        g_wh[OWC + i] = __float2half(Wel[(k + 256) * 128 + n]);
    } else if (b < 288) {
        int i = (b - 224) * 256 + tid; int n = i >> 7, k = i & 127;
        g_wh[OWM1 + i] = __float2half(Wm1[k * 128 + n]);
    } else if (b < 352) {
        int i = (b - 288) * 256 + tid; int n = i >> 7, k = i & 127;
        g_wh[OWC1 + i] = __float2half(Wc1[k * 128 + n]);
    } else if (b < 416) {
        int i = (b - 352) * 256 + tid; int n = i >> 7, k = i & 127;
        g_wh[OWM2 + i] = __float2half(Wm2[k * 128 + n]);
    } else if (b < 480) {
        int i = (b - 416) * 256 + tid; int n = i >> 7, k = i & 127;
        g_wh[OWC2 + i] = __float2half(Wc2[k * 128 + n]);
    } else {                                   // WUV: [Wu|Wv] of Wam
        int i = (b - 480) * 256 + tid; int n = i >> 7, k = i & 127;
        int kk = k + ((n & 256) ? 128 : 0);
        g_wh[OWUV + i] = __float2half(Wam[kk * 256 + (n & 255)]);
    }
}
__global__ void k_scale(const float* __restrict__ in, __half* __restrict__ out) {
    int i = blockIdx.x * 256 + threadIdx.x;
    if (i >= NN * 32) return;
    float4 v = *(const float4*)(in + i * 4);
    float sc = g_invdeg[i >> 5];
    *(__half2*)(out + i * 4)     = __floats2half2_rn(v.x * sc, v.y * sc);
    *(__half2*)(out + i * 4 + 2) = __floats2half2_rn(v.z * sc, v.w * sc);
}
__global__ void k_ht(const float* __restrict__ x,
                     const float* __restrict__ W1, const float* __restrict__ b1,
                     const float* __restrict__ W2, const float* __restrict__ b2) {
    int n = blockIdx.x;
    int c = threadIdx.x;
    const float* xr = x + n * 20;
    float s;
    if (c < 64) {
        s = b1[c];
#pragma unroll
        for (int k = 0; k < 8; k++) s += xr[k] * W1[k * 64 + c];
    } else {
        int cc = c - 64;
        s = b2[cc];
#pragma unroll
        for (int k = 0; k < 12; k++) s += xr[8 + k] * W2[k * 64 + cc];
    }
    g_ht[n * 128 + c] = __float2half(fmaxf(s, 0.0f));
}

// ================= plain fp16 GEMM (node-level), ldmatrix mainloop =================
enum { E_RELU = 0, E_LIN = 1 };

template<int K>
__device__ __forceinline__ void load_stage(
    __half* As, __half* Ws, int t, int st,
    const __half* __restrict__ A, const __half* __restrict__ Wt,
    const size_t* offA, int tid, int n0)
{
    const int k0 = t * 32;
    const int chunk = tid & 3;
    const int gk = k0 + chunk * 8;
#pragma unroll
    for (int l = 0; l < 2; l++) {
        int row = (tid >> 2) + l * 64;
        cp16(s2u(&As[st * 5120 + row * TS + chunk * 8]), A + offA[l] + gk);
    }
#pragma unroll
    for (int l = 0; l < 2; l++) {
        int nrow = (tid >> 2) + l * 64;
        cp16(s2u(&Ws[st * 5120 + nrow * TS + chunk * 8]),
             Wt + (size_t)(n0 + nrow) * K + gk);
    }
}

template<int EPI, int K>
__global__ void __launch_bounds__(256)
gemm_tc(const __half* __restrict__ A, const __half* __restrict__ Wt,
        const float* __restrict__ bias, __half* __restrict__ Cout,
        int rows, int ncols)
{
    __shared__ __half As[2 * 5120];
    __shared__ __half Ws[2 * 5120];

    const int tid  = threadIdx.x;
    const int wid  = tid >> 5, lane = tid & 31;
    const int wm   = wid & 1,  wn   = wid >> 1;
    const int g    = lane >> 2, tig = lane & 3;
    const int rowbase = blockIdx.x * 128;
    const int n0      = blockIdx.y * 128;

    const int laneA_row = (lane & 7) + ((lane >> 3) & 1) * 8;
    const int laneA_col = (lane >> 4) * 8;
    const int laneB_row = lane & 7;
    const int laneB_nt  = (lane >> 4);
    const int laneB_kh  = ((lane >> 3) & 1) * 8;

    size_t offA[2];
#pragma unroll
    for (int l = 0; l < 2; l++) {
        int grow = rowbase + (tid >> 2) + l * 64;
        int gc = (grow < rows) ? grow : (rows - 1);
        offA[l] = (size_t)gc * K;
    }

    float acc[4][4][4];
#pragma unroll
    for (int a = 0; a < 4; a++)
#pragma unroll
        for (int b = 0; b < 4; b++)
#pragma unroll
            for (int c = 0; c < 4; c++) acc[a][b][c] = 0.0f;

    const int NT = K / 32;
    load_stage<K>(As, Ws, 0, 0, A, Wt, offA, tid, n0);
    cp_commit();

    for (int t = 0; t < NT; t++) {
        const int s = t & 1;
        if (t + 1 < NT) {
            load_stage<K>(As, Ws, t + 1, (t + 1) & 1, A, Wt, offA, tid, n0);
            cp_commit();
            cp_wait<1>();
        } else cp_wait<0>();
        __syncthreads();

        const __half* Ab = As + s * 5120;
        const __half* Wb = Ws + s * 5120;
#pragma unroll
        for (int ks = 0; ks < 2; ks++) {
            const int kb = ks * 16;
            uint32_t af[4][4];
#pragma unroll
            for (int mt = 0; mt < 4; mt++)
                ldsm_x4(af[mt][0], af[mt][1], af[mt][2], af[mt][3],
                        s2u(&Ab[(wm * 64 + mt * 16 + laneA_row) * TS + kb + laneA_col]));
            uint32_t bf[4][2];
#pragma unroll
            for (int p = 0; p < 2; p++) {
                int nr = wn * 32 + (p * 2 + laneB_nt) * 8 + laneB_row;
                ldsm_x4(bf[p * 2][0], bf[p * 2][1], bf[p * 2 + 1][0], bf[p * 2 + 1][1],
                        s2u(&Wb[nr * TS + kb + laneB_kh]));
            }
#pragma unroll
            for (int mt = 0; mt < 4; mt++)
#pragma unroll
                for (int nt = 0; nt < 4; nt++)
                    mma_f16(acc[mt][nt], af[mt], bf[nt]);
        }
        __syncthreads();
    }

    float bc0[4], bc1[4];
    if (EPI == E_RELU) {
#pragma unroll
        for (int nt = 0; nt < 4; nt++) {
            int c = wn * 32 + nt * 8 + tig * 2;
            bc0[nt] = bias[n0 + c];
            bc1[nt] = bias[n0 + c + 1];
        }
    }

#pragma unroll
    for (int mt = 0; mt < 4; mt++) {
#pragma unroll
        for (int half_ = 0; half_ < 2; half_++) {
            int rl = wm * 64 + mt * 16 + g + half_ * 8;
            int r  = rowbase + rl;
            if (r >= rows) continue;
            __half* op = Cout + (size_t)r * ncols + n0;
#pragma unroll
            for (int nt = 0; nt < 4; nt++) {
                int c = wn * 32 + nt * 8 + tig * 2;
                float v0 = acc[mt][nt][half_ * 2    ];
                float v1 = acc[mt][nt][half_ * 2 + 1];
                if (EPI == E_RELU) {
                    v0 = fmaxf(v0 + bc0[nt], 0.f);
                    v1 = fmaxf(v1 + bc1[nt], 0.f);
                }
                *(__half2*)&op[c] = __floats2half2_rn(v0, v1);
            }
        }
    }
}

// ================= fused EL + gate1 + gate2 kernel =================
#define SM_AS 0
#define SM_WS 20480
#define SM_MS 40960                       // X = HA[src] staging, then mask
#define SM_Y  (SM_MS + 128 * MST * 2)     // Y = HB[dst], later gate1 staging
#define SM_WE (SM_Y + 128 * MST * 2)
#define SM_BE (SM_WE + 2048)
#define SMEM_EL (SM_BE + 256)

__device__ __forceinline__ void el_loadW(__half* Ws, int t, int st,
                                         const __half* __restrict__ Wt, int Kw, int tid) {
    const int k0 = t * 32;
    const int chunk = tid & 3;
#pragma unroll
    for (int l = 0; l < 2; l++) {
        int nrow = (tid >> 2) + l * 64;
        cp16(s2u(&Ws[st * 5120 + nrow * TS + chunk * 8]),
             Wt + (size_t)nrow * Kw + k0 + chunk * 8);
    }
}

__global__ void __launch_bounds__(256)
k_elconv(const __half* __restrict__ h, const __half* __restrict__ hab,
         const float* __restrict__ eattr, const float* __restrict__ We,
         const float* __restrict__ be,   const float* __restrict__ bel,
         const __half* __restrict__ Wct,
         const __half* __restrict__ Wm1t, const float* __restrict__ bm1,
         const __half* __restrict__ Wm2t, const float* __restrict__ bm2,
         const int* __restrict__ src, const int* __restrict__ dst,
         float* __restrict__ agg, __half* __restrict__ gate2)
{
    extern __shared__ char smem[];
    __half* As = (__half*)(smem + SM_AS);
    __half* Ws = (__half*)(smem + SM_WS);
    __half* Ms = (__half*)(smem + SM_MS);
    __half* Ys = (__half*)(smem + SM_Y);
    float* Wes = (float*)(smem + SM_WE);
    float* bes = (float*)(smem + SM_BE);

    const int tid  = threadIdx.x;
    const int wid  = tid >> 5, lane = tid & 31;
    const int wm   = wid & 1,  wn   = wid >> 1;
    const int g    = lane >> 2, tig = lane & 3;
    const int rowbase = blockIdx.x * 128;

    const int laneA_row = (lane & 7) + ((lane >> 3) & 1) * 8;
    const int laneA_col = (lane >> 4) * 8;
    const int laneB_row = lane & 7;
    const int laneB_nt  = (lane >> 4);
    const int laneB_kh  = ((lane >> 3) & 1) * 8;

    const int chunk = tid & 3;
    int sIdx[2], dIdx[2];
    float eat[2][8];
#pragma unroll
    for (int l = 0; l < 2; l++) {
        int grow = rowbase + (tid >> 2) + l * 64;
        sIdx[l] = src[grow];
        dIdx[l] = dst[grow];
        const float4* ap = (const float4*)(eattr + (size_t)grow * 8);
        float4 a0 = ap[0], a1 = ap[1];
        eat[l][0] = a0.x; eat[l][1] = a0.y; eat[l][2] = a0.z; eat[l][3] = a0.w;
        eat[l][4] = a1.x; eat[l][5] = a1.y; eat[l][6] = a1.z; eat[l][7] = a1.w;
    }
    if (tid < 256) { Wes[tid] = We[tid]; Wes[256 + tid] = We[256 + tid]; }
    if (tid < 64)  bes[tid] = be[tid];

    // async gathers: X = HA[src], Y = HB[dst]
#pragma unroll
    for (int l = 0; l < 2; l++) {
        int row = (tid >> 2) + l * 64;
        const __half* xa = hab + (size_t)sIdx[l] * 256;
        const __half* yb = hab + (size_t)dIdx[l] * 256 + 128;
#pragma unroll
        for (int q = 0; q < 4; q++) {
            int cc = (chunk + q * 4) * 8;
            cp16(s2u(&Ms[row * MST + cc]), xa + cc);
            cp16(s2u(&Ys[row * MST + cc]), yb + cc);
        }
    }
    el_loadW(Ws, 0, 0, Wct, 64, tid);
    el_loadW(Ws, 1, 1, Wct, 64, tid);
    cp_commit();

    __syncthreads();   // Wes/bes visible

    // compute ea tiles into As stages 0,1
#pragma unroll
    for (int t = 0; t < 2; t++) {
        const int cb = t * 32 + chunk * 8;
#pragma unroll
        for (int l = 0; l < 2; l++) {
            int row = (tid >> 2) + l * 64;
            __half* dstp = &As[t * 5120 + row * TS + chunk * 8];
#pragma unroll
            for (int j = 0; j < 8; j += 2) {
                float s0 = bes[cb + j], s1 = bes[cb + j + 1];
#pragma unroll
                for (int k = 0; k < 8; k++) {
                    s0 += eat[l][k] * Wes[k * 64 + cb + j];
                    s1 += eat[l][k] * Wes[k * 64 + cb + j + 1];
                }
                *(__half2*)&dstp[j] = __floats2half2_rn(fmaxf(s0, 0.f), fmaxf(s1, 0.f));
            }
        }
    }
    cp_wait<0>();
    __syncthreads();

    float acc[4][4][4];
#pragma unroll
    for (int a = 0; a < 4; a++)
#pragma unroll
        for (int b = 0; b < 4; b++)
#pragma unroll
            for (int c = 0; c < 4; c++) acc[a][b][c] = 0.0f;

    // phase 1 MMA: 2 k-tiles of ea@Wc
#pragma unroll
    for (int t = 0; t < 2; t++) {
        const __half* Ab = As + t * 5120;
        const __half* Wb = Ws + t * 5120;
#pragma unroll
        for (int ks = 0; ks < 2; ks++) {
            const int kb = ks * 16;
            uint32_t af[4][4];
#pragma unroll
            for (int mt = 0; mt < 4; mt++)
                ldsm_x4(af[mt][0], af[mt][1], af[mt][2], af[mt][3],
                        s2u(&Ab[(wm * 64 + mt * 16 + laneA_row) * TS + kb + laneA_col]));
            uint32_t bf[4][2];
#pragma unroll
            for (int p = 0; p < 2; p++) {
                int nr = wn * 32 + (p * 2 + laneB_nt) * 8 + laneB_row;
                ldsm_x4(bf[p * 2][0], bf[p * 2][1], bf[p * 2 + 1][0], bf[p * 2 + 1][1],
                        s2u(&Wb[nr * TS + kb + laneB_kh]));
            }
#pragma unroll
            for (int mt = 0; mt < 4; mt++)
#pragma unroll
                for (int nt = 0; nt < 4; nt++)
                    mma_f16(acc[mt][nt], af[mt], bf[nt]);
        }
    }

    // phase-1 epilogue: mask = relu(acc + X + Y + bel) -> Ms (aliases X)
#pragma unroll
    for (int mt = 0; mt < 4; mt++)
#pragma unroll
        for (int half_ = 0; half_ < 2; half_++) {
            int rl = wm * 64 + mt * 16 + g + half_ * 8;
#pragma unroll
            for (int nt = 0; nt < 4; nt++) {
                int c = wn * 32 + nt * 8 + tig * 2;
                float2 xv = __half22float2(*(__half2*)&Ms[rl * MST + c]);
                float2 yv = __half22float2(*(__half2*)&Ys[rl * MST + c]);
                float v0 = fmaxf(acc[mt][nt][half_ * 2    ] + xv.x + yv.x + bel[c    ], 0.f);
                float v1 = fmaxf(acc[mt][nt][half_ * 2 + 1] + xv.y + yv.y + bel[c + 1], 0.f);
                *(__half2*)&Ms[rl * MST + c] = __floats2half2_rn(v0, v1);
            }
        }
    __syncthreads();

    // ---- phases 2 & 3: Ms @ Wm{1,2}, K=128 ----
#pragma unroll 1
    for (int ph = 0; ph < 2; ph++) {
        const __half* Wm = (ph == 0) ? Wm1t : Wm2t;
        const float*  bm = (ph == 0) ? bm1 : bm2;

#pragma unroll
        for (int a = 0; a < 4; a++)
#pragma unroll
            for (int b = 0; b < 4; b++)
#pragma unroll
                for (int c = 0; c < 4; c++) acc[a][b][c] = 0.0f;

        el_loadW(Ws, 0, 0, Wm, 128, tid);
        cp_commit();
        for (int t = 0; t < 4; t++) {
            const int s = t & 1;
            if (t + 1 < 4) {
                el_loadW(Ws, t + 1, (t + 1) & 1, Wm, 128, tid);
                cp_commit();
                cp_wait<1>();
            } else cp_wait<0>();
            __syncthreads();

            const __half* Wb = Ws + s * 5120;
#pragma unroll
            for (int ks = 0; ks < 2; ks++) {
                const int kbM = t * 32 + ks * 16;
                const int kbW = ks * 16;
                uint32_t af[4][4];
#pragma unroll
                for (int mt = 0; mt < 4; mt++)
                    ldsm_x4(af[mt][0], af[mt][1], af[mt][2], af[mt][3],
                            s2u(&Ms[(wm * 64 + mt * 16 + laneA_row) * MST + kbM + laneA_col]));
                uint32_t bf[4][2];
#pragma unroll
                for (int p = 0; p < 2; p++) {
                    int nr = wn * 32 + (p * 2 + laneB_nt) * 8 + laneB_row;
                    ldsm_x4(bf[p * 2][0], bf[p * 2][1], bf[p * 2 + 1][0], bf[p * 2 + 1][1],
                            s2u(&Wb[nr * TS + kbW + laneB_kh]));
                }
#pragma unroll
                for (int mt = 0; mt < 4; mt++)
#pragma unroll
                    for (int nt = 0; nt < 4; nt++)
                        mma_f16(acc[mt][nt], af[mt], bf[nt]);
            }
            __syncthreads();
        }

        // stage sigmoid gates into smem (Ys for ph0, Ms for ph1)
        __half* Gs = (ph == 0) ? Ys : Ms;
#pragma unroll
        for (int mt = 0; mt < 4; mt++)
#pragma unroll
            for (int half_ = 0; half_ < 2; half_++) {
                int rl = wm * 64 + mt * 16 + g + half_ * 8;
#pragma unroll
                for (int nt = 0; nt < 4; nt++) {
                    int c = wn * 32 + nt * 8 + tig * 2;
                    float z0 = acc[mt][nt][half_ * 2    ] + bm[c];
                    float z1 = acc[mt][nt][half_ * 2 + 1] + bm[c + 1];
                    float g0 = 1.0f / (1.0f + __expf(-z0));
                    float g1 = 1.0f / (1.0f + __expf(-z1));
                    *(__half2*)&Gs[rl * MST + c] = __floats2half2_rn(g0, g1);
                }
            }
        __syncthreads();

        if (ph == 0) {
            // conv1 scatter: warp-per-edge, coalesced h[src] read + single red.v4 per lane
            for (int er = wid; er < 128; er += 8) {
                int r  = rowbase + er;
                int sI = src[r], dI = dst[r];
                const __half* gp = Ys + er * MST + lane * 4;
                const __half* hp = h + (size_t)sI * 128 + lane * 4;
                float2 ga = __half22float2(*(const __half2*)&gp[0]);
                float2 gb = __half22float2(*(const __half2*)&gp[2]);
                float2 ha = __half22float2(*(const __half2*)&hp[0]);
                float2 hb = __half22float2(*(const __half2*)&hp[2]);
                red_v4(agg + (size_t)dI * 128 + lane * 4,
                       ga.x * ha.x, ga.y * ha.y, gb.x * hb.x, gb.y * hb.y);
            }
            __syncthreads();
        } else {
            // gate2 -> gmem, coalesced
            __half* gout = gate2 + (size_t)rowbase * 128;
            for (int i = tid; i < 2048; i += 256) {
                int row = i >> 4, part = i & 15;
                float4 v = *(float4*)&Ms[row * MST + part * 8];
                *(float4*)&gout[row * 128 + part * 8] = v;
            }
        }
    }
}

// ---------------- conv2 scatter ----------------
__global__ void __launch_bounds__(256) k_conv2(const int* __restrict__ src,
                                               const int* __restrict__ dst) {
    int wid = threadIdx.x >> 5, lane = threadIdx.x & 31;
    int e = blockIdx.x * 8 + wid;
    int sI = src[e], dI = dst[e];
    const __half* gp = g_g2 + (size_t)e * 128 + lane * 4;
    const __half* hp = g_h2 + (size_t)sI * 128 + lane * 4;
    float2 ga = __half22float2(*(const __half2*)&gp[0]);
    float2 gb = __half22float2(*(const __half2*)&gp[2]);
    float2 ha = __half22float2(*(const __half2*)&hp[0]);
    float2 hb = __half22float2(*(const __half2*)&hp[2]);
    float* ag = g_agg2 + (size_t)dI * 128 + lane * 4;
    red_v4(ag, ga.x * ha.x, ga.y * ha.y, gb.x * hb.x, gb.y * hb.y);
}

// ---------------- pool scatter ----------------
__global__ void __launch_bounds__(256)
k_pool(const __half* __restrict__ P, const float* __restrict__ bam,
       const int* __restrict__ pi, const int* __restrict__ pj,
       const int* __restrict__ comm, float* __restrict__ pool)
{
    int wid = threadIdx.x >> 5, lane = threadIdx.x & 31;
    int e = blockIdx.x * 8 + wid;
    int a = pi[e], b = pj[e], cm = comm[e];
    const __half* pu = P + (size_t)a * 512 + lane * 8;
    const __half* pv = P + (size_t)b * 512 + 256 + lane * 8;
    float4 u4 = *(const float4*)pu;
    float4 v4 = *(const float4*)pv;
    const __half2* uh = (const __half2*)&u4;
    const __half2* vh = (const __half2*)&v4;
    const float* bb = bam + lane * 8;
    float r[8];
#pragma unroll
    for (int j = 0; j < 4; j++) {
        float2 ua = __half22float2(uh[j]);
        float2 va = __half22float2(vh[j]);
        r[j * 2    ] = fmaxf(ua.x + va.x + bb[j * 2    ], 0.f);
        r[j * 2 + 1] = fmaxf(ua.y + va.y + bb[j * 2 + 1], 0.f);
    }
    float* pb = pool + (size_t)(blockIdx.x & (RPL - 1)) * (NC * 256) + cm * 256 + lane * 8;
    red_v4(pb,     r[0], r[1], r[2], r[3]);
    red_v4(pb + 4, r[4], r[5], r[6], r[7]);
}

// ---------------- pool reduce ----------------
__global__ void k_poolreduce(const float* __restrict__ pool, float* __restrict__ sOut) {
    int i = blockIdx.x * 256 + threadIdx.x;
    int c = i >> 8;
    float s = 0.f;
#pragma unroll
    for (int r = 0; r < RPL; r++) s += pool[r * NC * 256 + i];
    sOut[i] = s * g_invcnt[c];
}

// ---------------- final MLP ----------------
__global__ void k_final(const float* __restrict__ Wl1, const float* __restrict__ bl1,
                        const float* __restrict__ Wl2, const float* __restrict__ bl2,
                        float* __restrict__ out) {
    __shared__ float sv[256];
    __shared__ float red[256];
    int c = blockIdx.x, j = threadIdx.x;
    sv[j] = g_s1[c * 256 + j] + g_s2[c * 256 + j];
    __syncthreads();
    float a = bl1[j];
    for (int k = 0; k < 256; k++)
        a += sv[k] * (Wl1[k * 256 + j] + Wl1[(256 + k) * 256 + j]);
    red[j] = fmaxf(a, 0.f) * Wl2[j];
    __syncthreads();
    for (int s = 128; s > 0; s >>= 1) {
        if (j < s) red[j] += red[j + s];
        __syncthreads();
    }
    if (j == 0) out[c] = red[0] + bl2[0];
}

// ---------------- host launch ----------------
extern "C" void kernel_launch(void* const* d_in, const int* in_sizes, int n_in,
                              void* d_out, int out_size) {
    (void)in_sizes; (void)n_in; (void)out_size;
    const float* x     = (const float*)d_in[0];
    const float* eattr = (const float*)d_in[1];
    const int*   ei    = (const int*)d_in[2];
    const int*   comm  = (const int*)d_in[3];
    const int*   pe    = (const int*)d_in[4];
    const float* We  = (const float*)d_in[5],  * be  = (const float*)d_in[6];
    const float* W1  = (const float*)d_in[7],  * b1  = (const float*)d_in[8];
    const float* W2  = (const float*)d_in[9],  * b2  = (const float*)d_in[10];
    const float* W3  = (const float*)d_in[11], * b3  = (const float*)d_in[12];
    const float* Wel = (const float*)d_in[13], * bel = (const float*)d_in[14];
    const float* Wm1 = (const float*)d_in[15], * bm1 = (const float*)d_in[16];
    const float* Wc1 = (const float*)d_in[17], * bc1 = (const float*)d_in[18];
    const float* Wm2 = (const float*)d_in[19], * bm2 = (const float*)d_in[20];
    const float* Wc2 = (const float*)d_in[21], * bc2 = (const float*)d_in[22];
    const float* Wam = (const float*)d_in[23], * bam = (const float*)d_in[24];
    const float* Wl1 = (const float*)d_in[25], * bl1 = (const float*)d_in[26];
    const float* Wl2 = (const float*)d_in[27], * bl2 = (const float*)d_in[28];

    const int* src = ei, * dst = ei + NEDGE;
    const int* pi  = pe, * pj  = pe + NP;

    __half *ht_, *h_, *hab_, *h2_, *h3_, *p1_, *p2_, *aggh_, *aggh2_, *g2_, *wh_;
    float *agg_, *agg2_, *pool1_, *pool2_, *s1_, *s2_;
    int *deg_, *cnt_;
    cudaGetSymbolAddress((void**)&ht_,    g_ht);
    cudaGetSymbolAddress((void**)&h_,     g_h);
    cudaGetSymbolAddress((void**)&hab_,   g_hab);
    cudaGetSymbolAddress((void**)&h2_,    g_h2);
    cudaGetSymbolAddress((void**)&h3_,    g_h3);
    cudaGetSymbolAddress((void**)&p1_,    g_p1);
    cudaGetSymbolAddress((void**)&p2_,    g_p2);
    cudaGetSymbolAddress((void**)&aggh_,  g_aggh);
    cudaGetSymbolAddress((void**)&aggh2_, g_aggh2);
    cudaGetSymbolAddress((void**)&agg_,   g_agg);
    cudaGetSymbolAddress((void**)&agg2_,  g_agg2);
    cudaGetSymbolAddress((void**)&pool1_, g_pool1);
    cudaGetSymbolAddress((void**)&pool2_, g_pool2);
    cudaGetSymbolAddress((void**)&s1_,    g_s1);
    cudaGetSymbolAddress((void**)&s2_,    g_s2);
    cudaGetSymbolAddress((void**)&wh_,    g_wh);
    cudaGetSymbolAddress((void**)&g2_,    g_g2);
    cudaGetSymbolAddress((void**)&deg_,   g_deg);
    cudaGetSymbolAddress((void**)&cnt_,   g_cnt);

    cudaFuncSetAttribute(k_elconv, cudaFuncAttributeMaxDynamicSharedMemorySize, SMEM_EL);

    cudaStream_t sB;
    cudaStreamCreateWithFlags(&sB, cudaStreamNonBlocking);
    cudaEvent_t evS, evP, evF, evJ;
    cudaEventCreateWithFlags(&evS, cudaEventDisableTiming);
    cudaEventCreateWithFlags(&evP, cudaEventDisableTiming);
    cudaEventCreateWithFlags(&evF, cudaEventDisableTiming);
    cudaEventCreateWithFlags(&evJ, cudaEventDisableTiming);

    dim3 blk(256);
    const int gN = (NN + 127) / 128;

    // fork side stream FROM origin (required for capture)
    cudaEventRecord(evS, 0);
    cudaStreamWaitEvent(sB, evS, 0);

    // side stream: deg/inv + late-needed memsets
    cudaMemsetAsync(deg_,   0, NN * sizeof(int), sB);
    cudaMemsetAsync(cnt_,   0, NC * sizeof(int), sB);
    k_deg<<<(NEDGE + 255) / 256, 256, 0, sB>>>(dst, comm);
    k_inv<<<(NN + 255) / 256, 256, 0, sB>>>();
    cudaMemsetAsync(agg2_,  0, (size_t)NN * 128 * sizeof(float), sB);
    cudaMemsetAsync(pool1_, 0, (size_t)RPL * NC * 256 * sizeof(float), sB);
    cudaMemsetAsync(pool2_, 0, (size_t)RPL * NC * 256 * sizeof(float), sB);
    cudaEventRecord(evP, sB);

    // default stream: main chain
    cudaMemsetAsync(agg_, 0, (size_t)NN * 128 * sizeof(float));
    k_transAll<<<736, 256>>>(W3, Wel, Wm1, Wc1, Wm2, Wc2, Wam);
    k_ht<<<NN, 128>>>(x, W1, b1, W2, b2);
    gemm_tc<E_RELU, 128><<<dim3(gN, 1), blk>>>(ht_, wh_ + OW3, b3, h_, NN, 128);
    gemm_tc<E_LIN, 128><<<dim3(gN, 2), blk>>>(h_, wh_ + OWAB, nullptr, hab_, NN, 256);
    k_elconv<<<NEDGE / 128, blk, SMEM_EL>>>(h_, hab_, eattr, We, be, bel,
                                            wh_ + OWC, wh_ + OWM1, bm1, wh_ + OWM2, bm2,
                                            src, dst, agg_, g2_);
    cudaStreamWaitEvent(0, evP, 0);
    k_scale<<<(NN * 32 + 255) / 256, 256>>>(agg_, aggh_);
    gemm_tc<E_RELU, 128><<<dim3(gN, 1), blk>>>(aggh_, wh_ + OWC1, bc1, h2_, NN, 128);

    // fork: pool1 chain on side stream
    cudaEventRecord(evF, 0);
    cudaStreamWaitEvent(sB, evF, 0);
    gemm_tc<E_LIN, 128><<<dim3(gN, 4), blk, 0, sB>>>(h2_, wh_ + OWUV, nullptr, p1_, NN, 512);
    k_pool<<<NP / 8, 256, 0, sB>>>(p1_, bam, pi, pj, comm, pool1_);
    k_poolreduce<<<NC, 256, 0, sB>>>(pool1_, s1_);
    cudaEventRecord(evJ, sB);

    k_conv2<<<NEDGE / 8, 256>>>(src, dst);
    k_scale<<<(NN * 32 + 255) / 256, 256>>>(agg2_, aggh2_);
    gemm_tc<E_RELU, 128><<<dim3(gN, 1), blk>>>(aggh2_, wh_ + OWC2, bc2, h3_, NN, 128);
    gemm_tc<E_LIN, 128><<<dim3(gN, 4), blk>>>(h3_, wh_ + OWUV, nullptr, p2_, NN, 512);
    k_pool<<<NP / 8, 256>>>(p2_, bam, pi, pj, comm, pool2_);
    k_poolreduce<<<NC, 256>>>(pool2_, s2_);

    cudaStreamWaitEvent(0, evJ, 0);
    k_final<<<NC, 256>>>(Wl1, bl1, Wl2, bl2, (float*)d_out);
}

// round 17
// speedup vs baseline: 4.8543x; 1.0094x over previous
#include <cuda_runtime.h>
#include <cuda_fp16.h>
#include <math.h>
#include <stdint.h>

#define NN     50000
#define NEDGE  800000
#define NP     400000
#define NC     1000
#define RPL    16

// ---------------- scratch ----------------
__device__ __half  g_ht  [NN * 128];
__device__ __half  g_h   [NN * 128];
__device__ __half  g_hab [NN * 256];    // [HA | HB] = h @ [Wa|Wb]
__device__ __half  g_h2  [NN * 128];
__device__ __half  g_p1  [NN * 512];    // [PU | PV] = h2 @ [Wu|Wv]
__device__ __half  g_p2  [NN * 512];    // from h3 (h3 itself never materialized)
__device__ float   g_agg [NN * 128];
__device__ float   g_agg2[NN * 128];
__device__ __half  g_aggh [NN * 128];
__device__ __half  g_aggh2[NN * 128];
__device__ __half  g_g2  [NEDGE * 128];
__device__ float   g_invdeg[NN];
__device__ int     g_deg [NN];
__device__ int     g_cnt [NC];
__device__ float   g_invcnt[NC];
__device__ float   g_pool1[RPL * NC * 256];
__device__ float   g_pool2[RPL * NC * 256];
__device__ float   g_s1  [NC * 256];
__device__ float   g_s2  [NC * 256];
__device__ __half  g_wh  [188416];

#define OW3   0        // 128x128
#define OWAB  16384    // 256 n x 128 k
#define OWC   49152    // 128 n x 64 k
#define OWM1  57344
#define OWC1  73728
#define OWM2  90112
#define OWC2  106496
#define OWUV  122880   // 512 n x 128 k

#define TS  40
#define MST 136

// ---------------- helpers ----------------
__device__ __forceinline__ void mma_f16(float* d, const uint32_t* a, const uint32_t* b) {
    asm volatile(
        "mma.sync.aligned.m16n8k16.row.col.f32.f16.f16.f32 "
        "{%0,%1,%2,%3}, {%4,%5,%6,%7}, {%8,%9}, {%0,%1,%2,%3};\n"
        : "+f"(d[0]), "+f"(d[1]), "+f"(d[2]), "+f"(d[3])
        : "r"(a[0]), "r"(a[1]), "r"(a[2]), "r"(a[3]), "r"(b[0]), "r"(b[1]));
}
__device__ __forceinline__ void ldsm_x4(uint32_t& r0, uint32_t& r1, uint32_t& r2,
                                        uint32_t& r3, uint32_t addr) {
    asm volatile("ldmatrix.sync.aligned.m8n8.x4.shared.b16 {%0,%1,%2,%3}, [%4];"
                 : "=r"(r0), "=r"(r1), "=r"(r2), "=r"(r3) : "r"(addr));
}
__device__ __forceinline__ void red_v4(float* p, float a, float b, float c, float d) {
    asm volatile("red.global.add.v4.f32 [%0], {%1, %2, %3, %4};"
                 :: "l"(p), "f"(a), "f"(b), "f"(c), "f"(d) : "memory");
}
__device__ __forceinline__ uint32_t s2u(const void* p) {
    return (uint32_t)__cvta_generic_to_shared(p);
}
__device__ __forceinline__ void cp16(uint32_t dst, const void* src) {
    asm volatile("cp.async.ca.shared.global [%0], [%1], 16;" :: "r"(dst), "l"(src));
}
__device__ __forceinline__ void cp_commit() { asm volatile("cp.async.commit_group;"); }
template<int N> __device__ __forceinline__ void cp_wait() {
    asm volatile("cp.async.wait_group %0;" :: "n"(N));
}

// ---------------- small kernels ----------------
__global__ void k_deg(const int* __restrict__ dst, const int* __restrict__ comm) {
    int i = blockIdx.x * blockDim.x + threadIdx.x;
    if (i < NEDGE) atomicAdd(&g_deg[dst[i]], 1);
    if (i < NP)    atomicAdd(&g_cnt[comm[i]], 1);
}
__global__ void k_inv() {
    int i = blockIdx.x * blockDim.x + threadIdx.x;
    if (i < NN) g_invdeg[i] = 1.0f / (float)max(g_deg[i], 1);
    if (i < NC) g_invcnt[i] = 1.0f / (float)max(g_cnt[i], 1);
}
__global__ void k_transAll(const float* __restrict__ W3,  const float* __restrict__ Wel,
                           const float* __restrict__ Wm1, const float* __restrict__ Wc1,
                           const float* __restrict__ Wm2, const float* __restrict__ Wc2,
                           const float* __restrict__ Wam) {
    int b = blockIdx.x, tid = threadIdx.x;
    if (b < 64) {
        int i = b * 256 + tid; int n = i >> 7, k = i & 127;
        g_wh[OW3 + i] = __float2half(W3[k * 128 + n]);
    } else if (b < 192) {
        int i = (b - 64) * 256 + tid; int n = i >> 7, k = i & 127;
        int kk = k + ((n & 128) ? 128 : 0);
        g_wh[OWAB + i] = __float2half(Wel[kk * 128 + (n & 127)]);
    } else if (b < 224) {
        int i = (b - 192) * 256 + tid; int n = i >> 6, k = i & 63;
        g_wh[OWC + i] = __float2half(Wel[(k + 256) * 128 + n]);
    } else if (b < 288) {
        int i = (b - 224) * 256 + tid; int n = i >> 7, k = i & 127;
        g_wh[OWM1 + i] = __float2half(Wm1[k * 128 + n]);
    } else if (b < 352) {
        int i = (b - 288) * 256 + tid; int n = i >> 7, k = i & 127;
        g_wh[OWC1 + i] = __float2half(Wc1[k * 128 + n]);
    } else if (b < 416) {
        int i = (b - 352) * 256 + tid; int n = i >> 7, k = i & 127;
        g_wh[OWM2 + i] = __float2half(Wm2[k * 128 + n]);
    } else if (b < 480) {
        int i = (b - 416) * 256 + tid; int n = i >> 7, k = i & 127;
        g_wh[OWC2 + i] = __float2half(Wc2[k * 128 + n]);
    } else {
        int i = (b - 480) * 256 + tid; int n = i >> 7, k = i & 127;
        int kk = k + ((n & 256) ? 128 : 0);
        g_wh[OWUV + i] = __float2half(Wam[kk * 256 + (n & 255)]);
    }
}
__global__ void k_scale(const float* __restrict__ in, __half* __restrict__ out) {
    int i = blockIdx.x * 256 + threadIdx.x;
    if (i >= NN * 32) return;
    float4 v = *(const float4*)(in + i * 4);
    float sc = g_invdeg[i >> 5];
    *(__half2*)(out + i * 4)     = __floats2half2_rn(v.x * sc, v.y * sc);
    *(__half2*)(out + i * 4 + 2) = __floats2half2_rn(v.z * sc, v.w * sc);
}
__global__ void k_ht(const float* __restrict__ x,
                     const float* __restrict__ W1, const float* __restrict__ b1,
                     const float* __restrict__ W2, const float* __restrict__ b2) {
    int n = blockIdx.x;
    int c = threadIdx.x;
    const float* xr = x + n * 20;
    float s;
    if (c < 64) {
        s = b1[c];
#pragma unroll
        for (int k = 0; k < 8; k++) s += xr[k] * W1[k * 64 + c];
    } else {
        int cc = c - 64;
        s = b2[cc];
#pragma unroll
        for (int k = 0; k < 12; k++) s += xr[8 + k] * W2[k * 64 + cc];
    }
    g_ht[n * 128 + c] = __float2half(fmaxf(s, 0.0f));
}

// ================= plain fp16 GEMM (node-level), ldmatrix mainloop =================
enum { E_RELU = 0, E_LIN = 1 };

template<int K>
__device__ __forceinline__ void load_stage(
    __half* As, __half* Ws, int t, int st,
    const __half* __restrict__ A, const __half* __restrict__ Wt,
    const size_t* offA, int tid, int n0)
{
    const int k0 = t * 32;
    const int chunk = tid & 3;
    const int gk = k0 + chunk * 8;
#pragma unroll
    for (int l = 0; l < 2; l++) {
        int row = (tid >> 2) + l * 64;
        cp16(s2u(&As[st * 5120 + row * TS + chunk * 8]), A + offA[l] + gk);
    }
#pragma unroll
    for (int l = 0; l < 2; l++) {
        int nrow = (tid >> 2) + l * 64;
        cp16(s2u(&Ws[st * 5120 + nrow * TS + chunk * 8]),
             Wt + (size_t)(n0 + nrow) * K + gk);
    }
}

template<int EPI, int K>
__global__ void __launch_bounds__(256)
gemm_tc(const __half* __restrict__ A, const __half* __restrict__ Wt,
        const float* __restrict__ bias, __half* __restrict__ Cout,
        int rows, int ncols)
{
    __shared__ __half As[2 * 5120];
    __shared__ __half Ws[2 * 5120];

    const int tid  = threadIdx.x;
    const int wid  = tid >> 5, lane = tid & 31;
    const int wm   = wid & 1,  wn   = wid >> 1;
    const int g    = lane >> 2, tig = lane & 3;
    const int rowbase = blockIdx.x * 128;
    const int n0      = blockIdx.y * 128;

    const int laneA_row = (lane & 7) + ((lane >> 3) & 1) * 8;
    const int laneA_col = (lane >> 4) * 8;
    const int laneB_row = lane & 7;
    const int laneB_nt  = (lane >> 4);
    const int laneB_kh  = ((lane >> 3) & 1) * 8;

    size_t offA[2];
#pragma unroll
    for (int l = 0; l < 2; l++) {
        int grow = rowbase + (tid >> 2) + l * 64;
        int gc = (grow < rows) ? grow : (rows - 1);
        offA[l] = (size_t)gc * K;
    }

    float acc[4][4][4];
#pragma unroll
    for (int a = 0; a < 4; a++)
#pragma unroll
        for (int b = 0; b < 4; b++)
#pragma unroll
            for (int c = 0; c < 4; c++) acc[a][b][c] = 0.0f;

    const int NT = K / 32;
    load_stage<K>(As, Ws, 0, 0, A, Wt, offA, tid, n0);
    cp_commit();

    for (int t = 0; t < NT; t++) {
        const int s = t & 1;
        if (t + 1 < NT) {
            load_stage<K>(As, Ws, t + 1, (t + 1) & 1, A, Wt, offA, tid, n0);
            cp_commit();
            cp_wait<1>();
        } else cp_wait<0>();
        __syncthreads();

        const __half* Ab = As + s * 5120;
        const __half* Wb = Ws + s * 5120;
#pragma unroll
        for (int ks = 0; ks < 2; ks++) {
            const int kb = ks * 16;
            uint32_t af[4][4];
#pragma unroll
            for (int mt = 0; mt < 4; mt++)
                ldsm_x4(af[mt][0], af[mt][1], af[mt][2], af[mt][3],
                        s2u(&Ab[(wm * 64 + mt * 16 + laneA_row) * TS + kb + laneA_col]));
            uint32_t bf[4][2];
#pragma unroll
            for (int p = 0; p < 2; p++) {
                int nr = wn * 32 + (p * 2 + laneB_nt) * 8 + laneB_row;
                ldsm_x4(bf[p * 2][0], bf[p * 2][1], bf[p * 2 + 1][0], bf[p * 2 + 1][1],
                        s2u(&Wb[nr * TS + kb + laneB_kh]));
            }
#pragma unroll
            for (int mt = 0; mt < 4; mt++)
#pragma unroll
                for (int nt = 0; nt < 4; nt++)
                    mma_f16(acc[mt][nt], af[mt], bf[nt]);
        }
        __syncthreads();
    }

    float bc0[4], bc1[4];
    if (EPI == E_RELU) {
#pragma unroll
        for (int nt = 0; nt < 4; nt++) {
            int c = wn * 32 + nt * 8 + tig * 2;
            bc0[nt] = bias[n0 + c];
            bc1[nt] = bias[n0 + c + 1];
        }
    }

#pragma unroll
    for (int mt = 0; mt < 4; mt++) {
#pragma unroll
        for (int half_ = 0; half_ < 2; half_++) {
            int rl = wm * 64 + mt * 16 + g + half_ * 8;
            int r  = rowbase + rl;
            if (r >= rows) continue;
            __half* op = Cout + (size_t)r * ncols + n0;
#pragma unroll
            for (int nt = 0; nt < 4; nt++) {
                int c = wn * 32 + nt * 8 + tig * 2;
                float v0 = acc[mt][nt][half_ * 2    ];
                float v1 = acc[mt][nt][half_ * 2 + 1];
                if (EPI == E_RELU) {
                    v0 = fmaxf(v0 + bc0[nt], 0.f);
                    v1 = fmaxf(v1 + bc1[nt], 0.f);
                }
                *(__half2*)&op[c] = __floats2half2_rn(v0, v1);
            }
        }
    }
}

// ================= fused chain GEMM: T = relu(A@W1+b1); out2 = T@W2 =================
#define CH_AS 0
#define CH_WS 20480
#define CH_TS 40960
#define SMEM_CH (CH_TS + 128 * MST * 2)    // 75,776 bytes

template<int NY, bool WRITE1>
__global__ void __launch_bounds__(256)
gemm_chain(const __half* __restrict__ A, const __half* __restrict__ W1t,
           const float* __restrict__ bias1, __half* __restrict__ Out1,
           const __half* __restrict__ W2t, __half* __restrict__ Out2,
           int rows)
{
    extern __shared__ char smem[];
    __half* As = (__half*)(smem + CH_AS);
    __half* Ws = (__half*)(smem + CH_WS);
    __half* Ts = (__half*)(smem + CH_TS);

    const int tid  = threadIdx.x;
    const int wid  = tid >> 5, lane = tid & 31;
    const int wm   = wid & 1,  wn   = wid >> 1;
    const int g    = lane >> 2, tig = lane & 3;
    const int rowbase = blockIdx.x * 128;

    const int laneA_row = (lane & 7) + ((lane >> 3) & 1) * 8;
    const int laneA_col = (lane >> 4) * 8;
    const int laneB_row = lane & 7;
    const int laneB_nt  = (lane >> 4);
    const int laneB_kh  = ((lane >> 3) & 1) * 8;
    const int chunk = tid & 3;

    size_t offA[2];
#pragma unroll
    for (int l = 0; l < 2; l++) {
        int grow = rowbase + (tid >> 2) + l * 64;
        int gc = (grow < rows) ? grow : (rows - 1);
        offA[l] = (size_t)gc * 128;
    }

    float acc[4][4][4];
#pragma unroll
    for (int a = 0; a < 4; a++)
#pragma unroll
        for (int b = 0; b < 4; b++)
#pragma unroll
            for (int c = 0; c < 4; c++) acc[a][b][c] = 0.0f;

    // ---- phase 1: T = relu(A@W1 + b1), K=128 ----
    load_stage<128>(As, Ws, 0, 0, A, W1t, offA, tid, 0);
    cp_commit();
    for (int t = 0; t < 4; t++) {
        const int s = t & 1;
        if (t + 1 < 4) {
            load_stage<128>(As, Ws, t + 1, (t + 1) & 1, A, W1t, offA, tid, 0);
            cp_commit();
            cp_wait<1>();
        } else cp_wait<0>();
        __syncthreads();

        const __half* Ab = As + s * 5120;
        const __half* Wb = Ws + s * 5120;
#pragma unroll
        for (int ks = 0; ks < 2; ks++) {
            const int kb = ks * 16;
            uint32_t af[4][4];
#pragma unroll
            for (int mt = 0; mt < 4; mt++)
                ldsm_x4(af[mt][0], af[mt][1], af[mt][2], af[mt][3],
                        s2u(&Ab[(wm * 64 + mt * 16 + laneA_row) * TS + kb + laneA_col]));
            uint32_t bf[4][2];
#pragma unroll
            for (int p = 0; p < 2; p++) {
                int nr = wn * 32 + (p * 2 + laneB_nt) * 8 + laneB_row;
                ldsm_x4(bf[p * 2][0], bf[p * 2][1], bf[p * 2 + 1][0], bf[p * 2 + 1][1],
                        s2u(&Wb[nr * TS + kb + laneB_kh]));
            }
#pragma unroll
            for (int mt = 0; mt < 4; mt++)
#pragma unroll
                for (int nt = 0; nt < 4; nt++)
                    mma_f16(acc[mt][nt], af[mt], bf[nt]);
        }
        __syncthreads();
    }

    // phase-1 epilogue -> Ts (+ optional gmem)
#pragma unroll
    for (int mt = 0; mt < 4; mt++)
#pragma unroll
        for (int half_ = 0; half_ < 2; half_++) {
            int rl = wm * 64 + mt * 16 + g + half_ * 8;
            int r  = rowbase + rl;
#pragma unroll
            for (int nt = 0; nt < 4; nt++) {
                int c = wn * 32 + nt * 8 + tig * 2;
                float v0 = fmaxf(acc[mt][nt][half_ * 2    ] + bias1[c    ], 0.f);
                float v1 = fmaxf(acc[mt][nt][half_ * 2 + 1] + bias1[c + 1], 0.f);
                __half2 hv = __floats2half2_rn(v0, v1);
                *(__half2*)&Ts[rl * MST + c] = hv;
                if (WRITE1 && r < rows)
                    *(__half2*)&Out1[(size_t)r * 128 + c] = hv;
            }
        }
    __syncthreads();

    // ---- phase 2: Out2[:, ny*128 ..] = T @ W2[ny], K=128 ----
    const int ncols2 = NY * 128;
#pragma unroll 1
    for (int ny = 0; ny < NY; ny++) {
        const __half* Wn = W2t + (size_t)ny * 128 * 128;

#pragma unroll
        for (int a = 0; a < 4; a++)
#pragma unroll
            for (int b = 0; b < 4; b++)
#pragma unroll
                for (int c = 0; c < 4; c++) acc[a][b][c] = 0.0f;

        {
            const int gk0 = chunk * 8;
#pragma unroll
            for (int l = 0; l < 2; l++) {
                int nrow = (tid >> 2) + l * 64;
                cp16(s2u(&Ws[nrow * TS + chunk * 8]), Wn + (size_t)nrow * 128 + gk0);
            }
            cp_commit();
        }
        for (int t = 0; t < 4; t++) {
            const int s = t & 1;
            if (t + 1 < 4) {
                const int sn = (t + 1) & 1;
                const int gk = (t + 1) * 32 + chunk * 8;
#pragma unroll
                for (int l = 0; l < 2; l++) {
                    int nrow = (tid >> 2) + l * 64;
                    cp16(s2u(&Ws[sn * 5120 + nrow * TS + chunk * 8]),
                         Wn + (size_t)nrow * 128 + gk);
                }
                cp_commit();
                cp_wait<1>();
            } else cp_wait<0>();
            __syncthreads();

            const __half* Wb = Ws + s * 5120;
#pragma unroll
            for (int ks = 0; ks < 2; ks++) {
                const int kbM = t * 32 + ks * 16;
                const int kbW = ks * 16;
                uint32_t af[4][4];
#pragma unroll
                for (int mt = 0; mt < 4; mt++)
                    ldsm_x4(af[mt][0], af[mt][1], af[mt][2], af[mt][3],
                            s2u(&Ts[(wm * 64 + mt * 16 + laneA_row) * MST + kbM + laneA_col]));
                uint32_t bf[4][2];
#pragma unroll
                for (int p = 0; p < 2; p++) {
                    int nr = wn * 32 + (p * 2 + laneB_nt) * 8 + laneB_row;
                    ldsm_x4(bf[p * 2][0], bf[p * 2][1], bf[p * 2 + 1][0], bf[p * 2 + 1][1],
                            s2u(&Wb[nr * TS + kbW + laneB_kh]));
                }
#pragma unroll
                for (int mt = 0; mt < 4; mt++)
#pragma unroll
                    for (int nt = 0; nt < 4; nt++)
                        mma_f16(acc[mt][nt], af[mt], bf[nt]);
            }
            __syncthreads();
        }

#pragma unroll
        for (int mt = 0; mt < 4; mt++)
#pragma unroll
            for (int half_ = 0; half_ < 2; half_++) {
                int rl = wm * 64 + mt * 16 + g + half_ * 8;
                int r  = rowbase + rl;
                if (r >= rows) continue;
                __half* op = Out2 + (size_t)r * ncols2 + ny * 128;
#pragma unroll
                for (int nt = 0; nt < 4; nt++) {
                    int c = wn * 32 + nt * 8 + tig * 2;
                    *(__half2*)&op[c] = __floats2half2_rn(acc[mt][nt][half_ * 2],
                                                          acc[mt][nt][half_ * 2 + 1]);
                }
            }
    }
}

// ================= fused EL + gate1 + gate2 kernel =================
#define SM_AS 0
#define SM_WS 20480
#define SM_MS 40960
#define SM_Y  (SM_MS + 128 * MST * 2)
#define SM_WE (SM_Y + 128 * MST * 2)
#define SM_BE (SM_WE + 2048)
#define SMEM_EL (SM_BE + 256)

__device__ __forceinline__ void el_loadW(__half* Ws, int t, int st,
                                         const __half* __restrict__ Wt, int Kw, int tid) {
    const int k0 = t * 32;
    const int chunk = tid & 3;
#pragma unroll
    for (int l = 0; l < 2; l++) {
        int nrow = (tid >> 2) + l * 64;
        cp16(s2u(&Ws[st * 5120 + nrow * TS + chunk * 8]),
             Wt + (size_t)nrow * Kw + k0 + chunk * 8);
    }
}

__global__ void __launch_bounds__(256)
k_elconv(const __half* __restrict__ h, const __half* __restrict__ hab,
         const float* __restrict__ eattr, const float* __restrict__ We,
         const float* __restrict__ be,   const float* __restrict__ bel,
         const __half* __restrict__ Wct,
         const __half* __restrict__ Wm1t, const float* __restrict__ bm1,
         const __half* __restrict__ Wm2t, const float* __restrict__ bm2,
         const int* __restrict__ src, const int* __restrict__ dst,
         float* __restrict__ agg, __half* __restrict__ gate2)
{
    extern __shared__ char smem[];
    __half* As = (__half*)(smem + SM_AS);
    __half* Ws = (__half*)(smem + SM_WS);
    __half* Ms = (__half*)(smem + SM_MS);
    __half* Ys = (__half*)(smem + SM_Y);
    float* Wes = (float*)(smem + SM_WE);
    float* bes = (float*)(smem + SM_BE);

    const int tid  = threadIdx.x;
    const int wid  = tid >> 5, lane = tid & 31;
    const int wm   = wid & 1,  wn   = wid >> 1;
    const int g    = lane >> 2, tig = lane & 3;
    const int rowbase = blockIdx.x * 128;

    const int laneA_row = (lane & 7) + ((lane >> 3) & 1) * 8;
    const int laneA_col = (lane >> 4) * 8;
    const int laneB_row = lane & 7;
    const int laneB_nt  = (lane >> 4);
    const int laneB_kh  = ((lane >> 3) & 1) * 8;

    const int chunk = tid & 3;
    int sIdx[2], dIdx[2];
    float eat[2][8];
#pragma unroll
    for (int l = 0; l < 2; l++) {
        int grow = rowbase + (tid >> 2) + l * 64;
        sIdx[l] = src[grow];
        dIdx[l] = dst[grow];
        const float4* ap = (const float4*)(eattr + (size_t)grow * 8);
        float4 a0 = ap[0], a1 = ap[1];
        eat[l][0] = a0.x; eat[l][1] = a0.y; eat[l][2] = a0.z; eat[l][3] = a0.w;
        eat[l][4] = a1.x; eat[l][5] = a1.y; eat[l][6] = a1.z; eat[l][7] = a1.w;
    }
    if (tid < 256) { Wes[tid] = We[tid]; Wes[256 + tid] = We[256 + tid]; }
    if (tid < 64)  bes[tid] = be[tid];

    // async gathers: X = HA[src], Y = HB[dst]
#pragma unroll
    for (int l = 0; l < 2; l++) {
        int row = (tid >> 2) + l * 64;
        const __half* xa = hab + (size_t)sIdx[l] * 256;
        const __half* yb = hab + (size_t)dIdx[l] * 256 + 128;
#pragma unroll
        for (int q = 0; q < 4; q++) {
            int cc = (chunk + q * 4) * 8;
            cp16(s2u(&Ms[row * MST + cc]), xa + cc);
            cp16(s2u(&Ys[row * MST + cc]), yb + cc);
        }
    }
    el_loadW(Ws, 0, 0, Wct, 64, tid);
    el_loadW(Ws, 1, 1, Wct, 64, tid);
    cp_commit();

    __syncthreads();

    // compute ea tiles into As stages 0,1
#pragma unroll
    for (int t = 0; t < 2; t++) {
        const int cb = t * 32 + chunk * 8;
#pragma unroll
        for (int l = 0; l < 2; l++) {
            int row = (tid >> 2) + l * 64;
            __half* dstp = &As[t * 5120 + row * TS + chunk * 8];
#pragma unroll
            for (int j = 0; j < 8; j += 2) {
                float s0 = bes[cb + j], s1 = bes[cb + j + 1];
#pragma unroll
                for (int k = 0; k < 8; k++) {
                    s0 += eat[l][k] * Wes[k * 64 + cb + j];
                    s1 += eat[l][k] * Wes[k * 64 + cb + j + 1];
                }
                *(__half2*)&dstp[j] = __floats2half2_rn(fmaxf(s0, 0.f), fmaxf(s1, 0.f));
            }
        }
    }
    cp_wait<0>();
    __syncthreads();

    float acc[4][4][4];
#pragma unroll
    for (int a = 0; a < 4; a++)
#pragma unroll
        for (int b = 0; b < 4; b++)
#pragma unroll
            for (int c = 0; c < 4; c++) acc[a][b][c] = 0.0f;

    // phase 1 MMA: 2 k-tiles of ea@Wc
#pragma unroll
    for (int t = 0; t < 2; t++) {
        const __half* Ab = As + t * 5120;
        const __half* Wb = Ws + t * 5120;
#pragma unroll
        for (int ks = 0; ks < 2; ks++) {
            const int kb = ks * 16;
            uint32_t af[4][4];
#pragma unroll
            for (int mt = 0; mt < 4; mt++)
                ldsm_x4(af[mt][0], af[mt][1], af[mt][2], af[mt][3],
                        s2u(&Ab[(wm * 64 + mt * 16 + laneA_row) * TS + kb + laneA_col]));
            uint32_t bf[4][2];
#pragma unroll
            for (int p = 0; p < 2; p++) {
                int nr = wn * 32 + (p * 2 + laneB_nt) * 8 + laneB_row;
                ldsm_x4(bf[p * 2][0], bf[p * 2][1], bf[p * 2 + 1][0], bf[p * 2 + 1][1],
                        s2u(&Wb[nr * TS + kb + laneB_kh]));
            }
#pragma unroll
            for (int mt = 0; mt < 4; mt++)
#pragma unroll
                for (int nt = 0; nt < 4; nt++)
                    mma_f16(acc[mt][nt], af[mt], bf[nt]);
        }
    }

    // phase-1 epilogue: mask = relu(acc + X + Y + bel) -> Ms
#pragma unroll
    for (int mt = 0; mt < 4; mt++)
#pragma unroll
        for (int half_ = 0; half_ < 2; half_++) {
            int rl = wm * 64 + mt * 16 + g + half_ * 8;
#pragma unroll
            for (int nt = 0; nt < 4; nt++) {
                int c = wn * 32 + nt * 8 + tig * 2;
                float2 xv = __half22float2(*(__half2*)&Ms[rl * MST + c]);
                float2 yv = __half22float2(*(__half2*)&Ys[rl * MST + c]);
                float v0 = fmaxf(acc[mt][nt][half_ * 2    ] + xv.x + yv.x + bel[c    ], 0.f);
                float v1 = fmaxf(acc[mt][nt][half_ * 2 + 1] + xv.y + yv.y + bel[c + 1], 0.f);
                *(__half2*)&Ms[rl * MST + c] = __floats2half2_rn(v0, v1);
            }
        }
    __syncthreads();

    // ---- phases 2 & 3: Ms @ Wm{1,2}, K=128 ----
#pragma unroll 1
    for (int ph = 0; ph < 2; ph++) {
        const __half* Wm = (ph == 0) ? Wm1t : Wm2t;
        const float*  bm = (ph == 0) ? bm1 : bm2;

#pragma unroll
        for (int a = 0; a < 4; a++)
#pragma unroll
            for (int b = 0; b < 4; b++)
#pragma unroll
                for (int c = 0; c < 4; c++) acc[a][b][c] = 0.0f;

        el_loadW(Ws, 0, 0, Wm, 128, tid);
        cp_commit();
        for (int t = 0; t < 4; t++) {
            const int s = t & 1;
            if (t + 1 < 4) {
                el_loadW(Ws, t + 1, (t + 1) & 1, Wm, 128, tid);
                cp_commit();
                cp_wait<1>();
            } else cp_wait<0>();
            __syncthreads();

            const __half* Wb = Ws + s * 5120;
#pragma unroll
            for (int ks = 0; ks < 2; ks++) {
                const int kbM = t * 32 + ks * 16;
                const int kbW = ks * 16;
                uint32_t af[4][4];
#pragma unroll
                for (int mt = 0; mt < 4; mt++)
                    ldsm_x4(af[mt][0], af[mt][1], af[mt][2], af[mt][3],
                            s2u(&Ms[(wm * 64 + mt * 16 + laneA_row) * MST + kbM + laneA_col]));
                uint32_t bf[4][2];
#pragma unroll
                for (int p = 0; p < 2; p++) {
                    int nr = wn * 32 + (p * 2 + laneB_nt) * 8 + laneB_row;
                    ldsm_x4(bf[p * 2][0], bf[p * 2][1], bf[p * 2 + 1][0], bf[p * 2 + 1][1],
                            s2u(&Wb[nr * TS + kbW + laneB_kh]));
                }
#pragma unroll
                for (int mt = 0; mt < 4; mt++)
#pragma unroll
                    for (int nt = 0; nt < 4; nt++)
                        mma_f16(acc[mt][nt], af[mt], bf[nt]);
            }
            __syncthreads();
        }

        __half* Gs = (ph == 0) ? Ys : Ms;
#pragma unroll
        for (int mt = 0; mt < 4; mt++)
#pragma unroll
            for (int half_ = 0; half_ < 2; half_++) {
                int rl = wm * 64 + mt * 16 + g + half_ * 8;
#pragma unroll
                for (int nt = 0; nt < 4; nt++) {
                    int c = wn * 32 + nt * 8 + tig * 2;
                    float z0 = acc[mt][nt][half_ * 2    ] + bm[c];
                    float z1 = acc[mt][nt][half_ * 2 + 1] + bm[c + 1];
                    float g0 = 1.0f / (1.0f + __expf(-z0));
                    float g1 = 1.0f / (1.0f + __expf(-z1));
                    *(__half2*)&Gs[rl * MST + c] = __floats2half2_rn(g0, g1);
                }
            }
        __syncthreads();

        if (ph == 0) {
            for (int er = wid; er < 128; er += 8) {
                int r  = rowbase + er;
                int sI = src[r], dI = dst[r];
                const __half* gp = Ys + er * MST + lane * 4;
                const __half* hp = h + (size_t)sI * 128 + lane * 4;
                float2 ga = __half22float2(*(const __half2*)&gp[0]);
                float2 gb = __half22float2(*(const __half2*)&gp[2]);
                float2 ha = __half22float2(*(const __half2*)&hp[0]);
                float2 hb = __half22float2(*(const __half2*)&hp[2]);
                red_v4(agg + (size_t)dI * 128 + lane * 4,
                       ga.x * ha.x, ga.y * ha.y, gb.x * hb.x, gb.y * hb.y);
            }
            __syncthreads();
        } else {
            __half* gout = gate2 + (size_t)rowbase * 128;
            for (int i = tid; i < 2048; i += 256) {
                int row = i >> 4, part = i & 15;
                float4 v = *(float4*)&Ms[row * MST + part * 8];
                *(float4*)&gout[row * 128 + part * 8] = v;
            }
        }
    }
}

// ---------------- conv2 scatter ----------------
__global__ void __launch_bounds__(256) k_conv2(const int* __restrict__ src,
                                               const int* __restrict__ dst) {
    int wid = threadIdx.x >> 5, lane = threadIdx.x & 31;
    int e = blockIdx.x * 8 + wid;
    int sI = src[e], dI = dst[e];
    const __half* gp = g_g2 + (size_t)e * 128 + lane * 4;
    const __half* hp = g_h2 + (size_t)sI * 128 + lane * 4;
    float2 ga = __half22float2(*(const __half2*)&gp[0]);
    float2 gb = __half22float2(*(const __half2*)&gp[2]);
    float2 ha = __half22float2(*(const __half2*)&hp[0]);
    float2 hb = __half22float2(*(const __half2*)&hp[2]);
    float* ag = g_agg2 + (size_t)dI * 128 + lane * 4;
    red_v4(ag, ga.x * ha.x, ga.y * ha.y, gb.x * hb.x, gb.y * hb.y);
}

// ---------------- pool scatter ----------------
__global__ void __launch_bounds__(256)
k_pool(const __half* __restrict__ P, const float* __restrict__ bam,
       const int* __restrict__ pi, const int* __restrict__ pj,
       const int* __restrict__ comm, float* __restrict__ pool)
{
    int wid = threadIdx.x >> 5, lane = threadIdx.x & 31;
    int e = blockIdx.x * 8 + wid;
    int a = pi[e], b = pj[e], cm = comm[e];
    const __half* pu = P + (size_t)a * 512 + lane * 8;
    const __half* pv = P + (size_t)b * 512 + 256 + lane * 8;
    float4 u4 = *(const float4*)pu;
    float4 v4 = *(const float4*)pv;
    const __half2* uh = (const __half2*)&u4;
    const __half2* vh = (const __half2*)&v4;
    const float* bb = bam + lane * 8;
    float r[8];
#pragma unroll
    for (int j = 0; j < 4; j++) {
        float2 ua = __half22float2(uh[j]);
        float2 va = __half22float2(vh[j]);
        r[j * 2    ] = fmaxf(ua.x + va.x + bb[j * 2    ], 0.f);
        r[j * 2 + 1] = fmaxf(ua.y + va.y + bb[j * 2 + 1], 0.f);
    }
    float* pb = pool + (size_t)(blockIdx.x & (RPL - 1)) * (NC * 256) + cm * 256 + lane * 8;
    red_v4(pb,     r[0], r[1], r[2], r[3]);
    red_v4(pb + 4, r[4], r[5], r[6], r[7]);
}

// ---------------- pool reduce ----------------
__global__ void k_poolreduce(const float* __restrict__ pool, float* __restrict__ sOut) {
    int i = blockIdx.x * 256 + threadIdx.x;
    int c = i >> 8;
    float s = 0.f;
#pragma unroll
    for (int r = 0; r < RPL; r++) s += pool[r * NC * 256 + i];
    sOut[i] = s * g_invcnt[c];
}

// ---------------- final MLP ----------------
__global__ void k_final(const float* __restrict__ Wl1, const float* __restrict__ bl1,
                        const float* __restrict__ Wl2, const float* __restrict__ bl2,
                        float* __restrict__ out) {
    __shared__ float sv[256];
    __shared__ float red[256];
    int c = blockIdx.x, j = threadIdx.x;
    sv[j] = g_s1[c * 256 + j] + g_s2[c * 256 + j];
    __syncthreads();
    float a = bl1[j];
    for (int k = 0; k < 256; k++)
        a += sv[k] * (Wl1[k * 256 + j] + Wl1[(256 + k) * 256 + j]);
    red[j] = fmaxf(a, 0.f) * Wl2[j];
    __syncthreads();
    for (int s = 128; s > 0; s >>= 1) {
        if (j < s) red[j] += red[j + s];
        __syncthreads();
    }
    if (j == 0) out[c] = red[0] + bl2[0];
}

// ---------------- host launch ----------------
extern "C" void kernel_launch(void* const* d_in, const int* in_sizes, int n_in,
                              void* d_out, int out_size) {
    (void)in_sizes; (void)n_in; (void)out_size;
    const float* x     = (const float*)d_in[0];
    const float* eattr = (const float*)d_in[1];
    const int*   ei    = (const int*)d_in[2];
    const int*   comm  = (const int*)d_in[3];
    const int*   pe    = (const int*)d_in[4];
    const float* We  = (const float*)d_in[5],  * be  = (const float*)d_in[6];
    const float* W1  = (const float*)d_in[7],  * b1  = (const float*)d_in[8];
    const float* W2  = (const float*)d_in[9],  * b2  = (const float*)d_in[10];
    const float* W3  = (const float*)d_in[11], * b3  = (const float*)d_in[12];
    const float* Wel = (const float*)d_in[13], * bel = (const float*)d_in[14];
    const float* Wm1 = (const float*)d_in[15], * bm1 = (const float*)d_in[16];
    const float* Wc1 = (const float*)d_in[17], * bc1 = (const float*)d_in[18];
    const float* Wm2 = (const float*)d_in[19], * bm2 = (const float*)d_in[20];
    const float* Wc2 = (const float*)d_in[21], * bc2 = (const float*)d_in[22];
    const float* Wam = (const float*)d_in[23], * bam = (const float*)d_in[24];
    const float* Wl1 = (const float*)d_in[25], * bl1 = (const float*)d_in[26];
    const float* Wl2 = (const float*)d_in[27], * bl2 = (const float*)d_in[28];

    const int* src = ei, * dst = ei + NEDGE;
    const int* pi  = pe, * pj  = pe + NP;

    __half *ht_, *h_, *hab_, *h2_, *p1_, *p2_, *aggh_, *aggh2_, *g2_, *wh_;
    float *agg_, *agg2_, *pool1_, *pool2_, *s1_, *s2_;
    int *deg_, *cnt_;
    cudaGetSymbolAddress((void**)&ht_,    g_ht);
    cudaGetSymbolAddress((void**)&h_,     g_h);
    cudaGetSymbolAddress((void**)&hab_,   g_hab);
    cudaGetSymbolAddress((void**)&h2_,    g_h2);
    cudaGetSymbolAddress((void**)&p1_,    g_p1);
    cudaGetSymbolAddress((void**)&p2_,    g_p2);
    cudaGetSymbolAddress((void**)&aggh_,  g_aggh);
    cudaGetSymbolAddress((void**)&aggh2_, g_aggh2);
    cudaGetSymbolAddress((void**)&agg_,   g_agg);
    cudaGetSymbolAddress((void**)&agg2_,  g_agg2);
    cudaGetSymbolAddress((void**)&pool1_, g_pool1);
    cudaGetSymbolAddress((void**)&pool2_, g_pool2);
    cudaGetSymbolAddress((void**)&s1_,    g_s1);
    cudaGetSymbolAddress((void**)&s2_,    g_s2);
    cudaGetSymbolAddress((void**)&wh_,    g_wh);
    cudaGetSymbolAddress((void**)&g2_,    g_g2);
    cudaGetSymbolAddress((void**)&deg_,   g_deg);
    cudaGetSymbolAddress((void**)&cnt_,   g_cnt);

    cudaFuncSetAttribute(k_elconv, cudaFuncAttributeMaxDynamicSharedMemorySize, SMEM_EL);
    cudaFuncSetAttribute(gemm_chain<2, true>,
                         cudaFuncAttributeMaxDynamicSharedMemorySize, SMEM_CH);
    cudaFuncSetAttribute(gemm_chain<4, false>,
                         cudaFuncAttributeMaxDynamicSharedMemorySize, SMEM_CH);

    cudaStream_t sB;
    cudaStreamCreateWithFlags(&sB, cudaStreamNonBlocking);
    cudaEvent_t evS, evP, evF, evJ;
    cudaEventCreateWithFlags(&evS, cudaEventDisableTiming);
    cudaEventCreateWithFlags(&evP, cudaEventDisableTiming);
    cudaEventCreateWithFlags(&evF, cudaEventDisableTiming);
    cudaEventCreateWithFlags(&evJ, cudaEventDisableTiming);

    dim3 blk(256);
    const int gN = (NN + 127) / 128;

    // fork side stream FROM origin (required for capture)
    cudaEventRecord(evS, 0);
    cudaStreamWaitEvent(sB, evS, 0);

    // side stream: deg/inv + late-needed memsets
    cudaMemsetAsync(deg_,   0, NN * sizeof(int), sB);
    cudaMemsetAsync(cnt_,   0, NC * sizeof(int), sB);
    k_deg<<<(NEDGE + 255) / 256, 256, 0, sB>>>(dst, comm);
    k_inv<<<(NN + 255) / 256, 256, 0, sB>>>();
    cudaMemsetAsync(agg2_,  0, (size_t)NN * 128 * sizeof(float), sB);
    cudaMemsetAsync(pool1_, 0, (size_t)RPL * NC * 256 * sizeof(float), sB);
    cudaMemsetAsync(pool2_, 0, (size_t)RPL * NC * 256 * sizeof(float), sB);
    cudaEventRecord(evP, sB);

    // default stream: main chain
    cudaMemsetAsync(agg_, 0, (size_t)NN * 128 * sizeof(float));
    k_transAll<<<736, 256>>>(W3, Wel, Wm1, Wc1, Wm2, Wc2, Wam);
    k_ht<<<NN, 128>>>(x, W1, b1, W2, b2);
    // fused: h = relu(ht@W3+b3); hab = h@WAB
    gemm_chain<2, true><<<gN, blk, SMEM_CH>>>(ht_, wh_ + OW3, b3, h_,
                                              wh_ + OWAB, hab_, NN);
    k_elconv<<<NEDGE / 128, blk, SMEM_EL>>>(h_, hab_, eattr, We, be, bel,
                                            wh_ + OWC, wh_ + OWM1, bm1, wh_ + OWM2, bm2,
                                            src, dst, agg_, g2_);
    cudaStreamWaitEvent(0, evP, 0);
    k_scale<<<(NN * 32 + 255) / 256, 256>>>(agg_, aggh_);
    gemm_tc<E_RELU, 128><<<dim3(gN, 1), blk>>>(aggh_, wh_ + OWC1, bc1, h2_, NN, 128);

    // fork: pool1 chain on side stream
    cudaEventRecord(evF, 0);
    cudaStreamWaitEvent(sB, evF, 0);
    gemm_tc<E_LIN, 128><<<dim3(gN, 4), blk, 0, sB>>>(h2_, wh_ + OWUV, nullptr, p1_, NN, 512);
    k_pool<<<NP / 8, 256, 0, sB>>>(p1_, bam, pi, pj, comm, pool1_);
    k_poolreduce<<<NC, 256, 0, sB>>>(pool1_, s1_);
    cudaEventRecord(evJ, sB);

    k_conv2<<<NEDGE / 8, 256>>>(src, dst);
    k_scale<<<(NN * 32 + 255) / 256, 256>>>(agg2_, aggh2_);
    // fused: h3 = relu(aggh2@WC2+bc2) (smem only); P2 = h3@WUV
    gemm_chain<4, false><<<gN, blk, SMEM_CH>>>(aggh2_, wh_ + OWC2, bc2, nullptr,
                                               wh_ + OWUV, p2_, NN);
    k_pool<<<NP / 8, 256>>>(p2_, bam, pi, pj, comm, pool2_);
    k_poolreduce<<<NC, 256>>>(pool2_, s2_);

    cudaStreamWaitEvent(0, evJ, 0);
    k_final<<<NC, 256>>>(Wl1, bl1, Wl2, bl2, (float*)d_out);
}